// round 1
// baseline (speedup 1.0000x reference)
#include <cuda_runtime.h>
#include <math.h>

#define BB  8
#define CC  256
#define HH  64
#define WW  64
#define HWP 4096
#define NHH 4
#define HDD 64
#define C3  768

// ---- scratch (static device globals; no allocation at runtime) ----
__device__ float g_xf  [2ULL*BB*CC*HWP];     //  67 MB  multiscale conv out
__device__ float g_qkv [2ULL*BB*C3*HWP];     // 201 MB  gelu(bn(qkv))
__device__ float g_rnorm[2*BB*2*CC];         //  reciprocal L2 norms (q:0-255,k:256-511)
__device__ float g_attn[2*BB*NHH*HDD*HDD];   //  softmaxed attention
__device__ float g_xout[2ULL*BB*CC*HWP];     //  67 MB  attn @ v
__device__ float g_pool[2*BB*CC];
__device__ float g_gate[2*BB*CC];

// ---------------------------------------------------------------------------
// K0: zero the pooling accumulator (graph replays must be deterministic)
// ---------------------------------------------------------------------------
__global__ void zero_pool_kernel() {
    int i = blockIdx.x * 256 + threadIdx.x;
    if (i < 2*BB*CC) g_pool[i] = 0.0f;
}

// ---------------------------------------------------------------------------
// K1: fused multiscale depthwise conv (k=3,5,7 averaged) for both streams
// One block per (c, b, s). Combined 7x7 weight built once per block.
// ---------------------------------------------------------------------------
__global__ void msconv_kernel(const float* __restrict__ x1, const float* __restrict__ x2,
                              const float* __restrict__ w3, const float* __restrict__ b3,
                              const float* __restrict__ w5, const float* __restrict__ b5,
                              const float* __restrict__ w7, const float* __restrict__ b7)
{
    int c = blockIdx.x, b = blockIdx.y, s = blockIdx.z;
    const float* xin = (s ? x2 : x1) + ((size_t)b*CC + c)*HWP;

    __shared__ float tile[70*70];
    __shared__ float wc[49];
    int t = threadIdx.x;

    if (t < 49) {
        int ky = t / 7, kx = t % 7;
        float w = w7[c*49 + t];
        if (ky >= 1 && ky <= 5 && kx >= 1 && kx <= 5) w += w5[c*25 + (ky-1)*5 + (kx-1)];
        if (ky >= 2 && ky <= 4 && kx >= 2 && kx <= 4) w += w3[c*9  + (ky-2)*3 + (kx-2)];
        wc[t] = w * (1.0f/3.0f);
    }
    for (int i = t; i < 70*70; i += 256) {
        int ty = i / 70, tx = i % 70;
        int gy = ty - 3, gx = tx - 3;
        tile[i] = (gy >= 0 && gy < HH && gx >= 0 && gx < WW) ? xin[gy*WW + gx] : 0.0f;
    }
    __syncthreads();

    float bias = (b3[c] + b5[c] + b7[c]) * (1.0f/3.0f);
    float* outp = g_xf + ((size_t)(s*BB+b)*CC + c)*HWP;
    #pragma unroll
    for (int i = 0; i < 16; i++) {
        int p = t + i*256;
        int py = p >> 6, px = p & 63;
        float acc = bias;
        #pragma unroll
        for (int ky = 0; ky < 7; ky++)
            #pragma unroll
            for (int kx = 0; kx < 7; kx++)
                acc += wc[ky*7+kx] * tile[(py+ky)*70 + px+kx];
        outp[p] = acc;
    }
}

// ---------------------------------------------------------------------------
// K2: qkv 1x1 conv GEMM (768x256 @ 256x4096 per (s,b)) + BN + exact GELU
// 64x64 tile, BK=16, 256 threads, 4x4 per thread.
// ---------------------------------------------------------------------------
__global__ void qkv_gemm_kernel(
    const float* __restrict__ w1, const float* __restrict__ bq1,
    const float* __restrict__ g1, const float* __restrict__ be1,
    const float* __restrict__ m1, const float* __restrict__ v1,
    const float* __restrict__ w2, const float* __restrict__ bq2,
    const float* __restrict__ g2, const float* __restrict__ be2,
    const float* __restrict__ m2, const float* __restrict__ v2)
{
    int pTile = blockIdx.x, oTile = blockIdx.y;
    int s = blockIdx.z >> 3, b = blockIdx.z & 7;
    const float* W  = s ? w2  : w1;
    const float* bq = s ? bq2 : bq1;
    const float* bg = s ? g2  : g1;
    const float* bb = s ? be2 : be1;
    const float* bm = s ? m2  : m1;
    const float* bv = s ? v2  : v1;
    const float* X  = g_xf  + (size_t)(s*BB+b)*CC*HWP;
    float*       Y  = g_qkv + (size_t)(s*BB+b)*C3*HWP;

    __shared__ float As[16][64];
    __shared__ float Bs[16][68];
    int t  = threadIdx.x;
    int tx = t & 15, ty = t >> 4;
    int oBase = oTile*64, pBase = pTile*64;
    float acc[4][4] = {};

    for (int k0 = 0; k0 < CC; k0 += 16) {
        #pragma unroll
        for (int e = 0; e < 4; e++) {
            int idx = t + e*256;
            int i  = idx >> 4, kk  = idx & 15;
            As[kk][i] = W[(size_t)(oBase+i)*CC + k0 + kk];
            int kk2 = idx >> 6, j = idx & 63;
            Bs[kk2][j] = X[(size_t)(k0+kk2)*HWP + pBase + j];
        }
        __syncthreads();
        #pragma unroll
        for (int kk = 0; kk < 16; kk++) {
            float ra[4], rb[4];
            #pragma unroll
            for (int ii = 0; ii < 4; ii++) ra[ii] = As[kk][ty*4+ii];
            #pragma unroll
            for (int jj = 0; jj < 4; jj++) rb[jj] = Bs[kk][tx*4+jj];
            #pragma unroll
            for (int ii = 0; ii < 4; ii++)
                #pragma unroll
                for (int jj = 0; jj < 4; jj++)
                    acc[ii][jj] += ra[ii]*rb[jj];
        }
        __syncthreads();
    }

    #pragma unroll
    for (int ii = 0; ii < 4; ii++) {
        int o = oBase + ty*4 + ii;
        float scl = bg[o] * rsqrtf(bv[o] + 1e-5f);
        float sft = bb[o] - bm[o]*scl;
        float bqo = bq[o];
        #pragma unroll
        for (int jj = 0; jj < 4; jj++) {
            int p = pBase + tx*4 + jj;
            float v = (acc[ii][jj] + bqo)*scl + sft;
            v = 0.5f*v*(1.0f + erff(v*0.70710678118654752f));
            Y[(size_t)o*HWP + p] = v;
        }
    }
}

// ---------------------------------------------------------------------------
// K3: reciprocal L2 norms over n=4096 for q (ch 0-255) and k (ch 256-511)
// ---------------------------------------------------------------------------
__global__ void norm_kernel() {
    int ch = blockIdx.x, b = blockIdx.y, s = blockIdx.z;
    const float* row = g_qkv + ((size_t)(s*BB+b)*C3 + ch)*HWP;
    float ss = 0.0f;
    for (int i = threadIdx.x; i < HWP; i += 256) { float v = row[i]; ss += v*v; }
    __shared__ float red[256];
    red[threadIdx.x] = ss; __syncthreads();
    for (int st = 128; st > 0; st >>= 1) {
        if (threadIdx.x < st) red[threadIdx.x] += red[threadIdx.x + st];
        __syncthreads();
    }
    if (threadIdx.x == 0) {
        float n = sqrtf(red[0]);
        g_rnorm[(s*BB+b)*512 + ch] = 1.0f / fmaxf(n, 1e-12f);
    }
}

// ---------------------------------------------------------------------------
// K4: cross-attention logits (64x64 GEMM, K=4096) + scale + softmax
// which=0: q1.k2 -> attn for stream1; which=1: q2.k1 -> attn for stream2.
// ---------------------------------------------------------------------------
__global__ void attn_kernel() {
    int h = blockIdx.x, b = blockIdx.y, which = blockIdx.z;
    int qs = which, ks = 1 - which;
    const float* Q = g_qkv + ((size_t)(qs*BB+b)*C3 +       h*HDD)*HWP;
    const float* K = g_qkv + ((size_t)(ks*BB+b)*C3 + CC +  h*HDD)*HWP;

    __shared__ float Qs[64][33];
    __shared__ float Ks[64][33];
    __shared__ float Ss[64][65];
    __shared__ float rq[64], rk[64];

    int t = threadIdx.x;
    int tx = t & 15, ty = t >> 4;

    if (t < 64) {
        rq[t] = g_rnorm[(qs*BB+b)*512 +       h*64 + t];
        rk[t] = g_rnorm[(ks*BB+b)*512 + 256 + h*64 + t];
    }

    float acc[4][4] = {};
    for (int n0 = 0; n0 < HWP; n0 += 32) {
        #pragma unroll
        for (int e = 0; e < 8; e++) {
            int idx = t + e*256;
            int cc = idx >> 5, nn = idx & 31;
            Qs[cc][nn] = Q[(size_t)cc*HWP + n0 + nn];
            Ks[cc][nn] = K[(size_t)cc*HWP + n0 + nn];
        }
        __syncthreads();
        #pragma unroll
        for (int nn = 0; nn < 32; nn++) {
            float ra[4], rb[4];
            #pragma unroll
            for (int ii = 0; ii < 4; ii++) ra[ii] = Qs[ty*4+ii][nn];
            #pragma unroll
            for (int jj = 0; jj < 4; jj++) rb[jj] = Ks[tx*4+jj][nn];
            #pragma unroll
            for (int ii = 0; ii < 4; ii++)
                #pragma unroll
                for (int jj = 0; jj < 4; jj++)
                    acc[ii][jj] += ra[ii]*rb[jj];
        }
        __syncthreads();
    }

    const float temp = 0.125f;   // HD^-0.5
    #pragma unroll
    for (int ii = 0; ii < 4; ii++)
        #pragma unroll
        for (int jj = 0; jj < 4; jj++)
            Ss[ty*4+ii][tx*4+jj] = acc[ii][jj] * temp * rq[ty*4+ii] * rk[tx*4+jj];
    __syncthreads();

    if (t < 64) {
        float m = -1e30f;
        #pragma unroll
        for (int d = 0; d < 64; d++) m = fmaxf(m, Ss[t][d]);
        float sum = 0.0f;
        #pragma unroll
        for (int d = 0; d < 64; d++) { float ev = expf(Ss[t][d] - m); Ss[t][d] = ev; sum += ev; }
        float inv = 1.0f / sum;
        float* ap = g_attn + ((size_t)((which*BB+b)*NHH + h)*HDD + t)*HDD;
        #pragma unroll
        for (int d = 0; d < 64; d++) ap[d] = Ss[t][d]*inv;
    }
}

// ---------------------------------------------------------------------------
// K5: x_out = attn @ v  (64 x 4096 per (which,b,h)); also accumulates SE pool
// ---------------------------------------------------------------------------
__global__ void av_kernel() {
    int nTile = blockIdx.x;
    int hb = blockIdx.y;              // NH*B
    int which = blockIdx.z;
    int h = hb & 3, b = hb >> 2;
    const float* V = g_qkv  + ((size_t)(which*BB+b)*C3 + 2*CC + h*HDD)*HWP;
    const float* A = g_attn + (size_t)((which*BB+b)*NHH + h)*HDD*HDD;

    __shared__ float As[64][65];
    __shared__ float Vs[64][65];
    __shared__ float psum[64];

    int t = threadIdx.x;
    for (int i = t; i < 4096; i += 256) As[i >> 6][i & 63] = A[i];
    int n0 = nTile*64;
    #pragma unroll
    for (int e = 0; e < 16; e++) {
        int idx = t + e*256;
        int d = idx >> 6, nn = idx & 63;
        Vs[d][nn] = V[(size_t)d*HWP + n0 + nn];
    }
    if (t < 64) psum[t] = 0.0f;
    __syncthreads();

    int tx = t & 15, ty = t >> 4;
    float acc[4][4] = {};
    #pragma unroll 8
    for (int d = 0; d < 64; d++) {
        float rb[4];
        #pragma unroll
        for (int jj = 0; jj < 4; jj++) rb[jj] = Vs[d][tx*4+jj];
        #pragma unroll
        for (int ii = 0; ii < 4; ii++) {
            float ra = As[ty*4+ii][d];
            #pragma unroll
            for (int jj = 0; jj < 4; jj++) acc[ii][jj] += ra*rb[jj];
        }
    }

    float* O = g_xout + ((size_t)(which*BB+b)*CC + h*HDD)*HWP;
    #pragma unroll
    for (int ii = 0; ii < 4; ii++) {
        int cidx = ty*4 + ii;
        float rs = 0.0f;
        #pragma unroll
        for (int jj = 0; jj < 4; jj++) {
            O[(size_t)cidx*HWP + n0 + tx*4 + jj] = acc[ii][jj];
            rs += acc[ii][jj];
        }
        atomicAdd(&psum[cidx], rs);
    }
    __syncthreads();
    if (t < 64) atomicAdd(&g_pool[(which*BB+b)*CC + h*HDD + t], psum[t]);
}

// ---------------------------------------------------------------------------
// K6: SE gate (per (s,b)): relu(W1 . mean) -> sigmoid(W2 . y)
// ---------------------------------------------------------------------------
__global__ void se_kernel(const float* __restrict__ w1, const float* __restrict__ b1_,
                          const float* __restrict__ w2, const float* __restrict__ b2_)
{
    int b = blockIdx.x, s = blockIdx.y;
    __shared__ float pm[256], ys[32];
    int t = threadIdx.x;
    pm[t] = g_pool[(s*BB+b)*CC + t] * (1.0f/HWP);
    __syncthreads();
    if (t < 32) {
        float a = b1_[t];
        #pragma unroll 8
        for (int c = 0; c < 256; c++) a += w1[t*256 + c]*pm[c];
        ys[t] = fmaxf(a, 0.0f);
    }
    __syncthreads();
    float a = b2_[t];
    #pragma unroll
    for (int r = 0; r < 32; r++) a += w2[t*32 + r]*ys[r];
    g_gate[(s*BB+b)*CC + t] = 1.0f/(1.0f + expf(-a));
}

// ---------------------------------------------------------------------------
// K7: output projection GEMM (256x256 @ 256x4096) with gate on input, + bias
//     + residual, writes final output.
// ---------------------------------------------------------------------------
__global__ void out_gemm_kernel(const float* __restrict__ x1, const float* __restrict__ x2,
                                const float* __restrict__ pw1, const float* __restrict__ pb1,
                                const float* __restrict__ pw2, const float* __restrict__ pb2,
                                float* __restrict__ out)
{
    int pTile = blockIdx.x, oTile = blockIdx.y;
    int s = blockIdx.z >> 3, b = blockIdx.z & 7;
    const float* W    = s ? pw2 : pw1;
    const float* pb   = s ? pb2 : pb1;
    const float* X    = g_xout + (size_t)(s*BB+b)*CC*HWP;
    const float* gate = g_gate + (s*BB+b)*CC;
    const float* res  = (s ? x2 : x1) + (size_t)b*CC*HWP;
    float*       Y    = out + (size_t)s*BB*CC*HWP + (size_t)b*CC*HWP;

    __shared__ float As[16][64];
    __shared__ float Bs[16][68];
    int t = threadIdx.x;
    int tx = t & 15, ty = t >> 4;
    int oBase = oTile*64, pBase = pTile*64;
    float acc[4][4] = {};

    for (int k0 = 0; k0 < CC; k0 += 16) {
        #pragma unroll
        for (int e = 0; e < 4; e++) {
            int idx = t + e*256;
            int i = idx >> 4, kk = idx & 15;
            As[kk][i] = W[(size_t)(oBase+i)*CC + k0 + kk];
            int kk2 = idx >> 6, j = idx & 63;
            Bs[kk2][j] = X[(size_t)(k0+kk2)*HWP + pBase + j] * gate[k0+kk2];
        }
        __syncthreads();
        #pragma unroll
        for (int kk = 0; kk < 16; kk++) {
            float ra[4], rb[4];
            #pragma unroll
            for (int ii = 0; ii < 4; ii++) ra[ii] = As[kk][ty*4+ii];
            #pragma unroll
            for (int jj = 0; jj < 4; jj++) rb[jj] = Bs[kk][tx*4+jj];
            #pragma unroll
            for (int ii = 0; ii < 4; ii++)
                #pragma unroll
                for (int jj = 0; jj < 4; jj++)
                    acc[ii][jj] += ra[ii]*rb[jj];
        }
        __syncthreads();
    }

    #pragma unroll
    for (int ii = 0; ii < 4; ii++) {
        int o = oBase + ty*4 + ii;
        float bo = pb[o];
        #pragma unroll
        for (int jj = 0; jj < 4; jj++) {
            int p = pBase + tx*4 + jj;
            Y[(size_t)o*HWP + p] = acc[ii][jj] + bo + res[(size_t)o*HWP + p];
        }
    }
}

// ---------------------------------------------------------------------------
extern "C" void kernel_launch(void* const* d_in, const int* in_sizes, int n_in,
                              void* d_out, int out_size)
{
    const float* x1     = (const float*)d_in[0];
    const float* x2     = (const float*)d_in[1];
    const float* ms_w3  = (const float*)d_in[2];
    const float* ms_b3  = (const float*)d_in[3];
    const float* ms_w5  = (const float*)d_in[4];
    const float* ms_b5  = (const float*)d_in[5];
    const float* ms_w7  = (const float*)d_in[6];
    const float* ms_b7  = (const float*)d_in[7];
    const float* qkv1_w = (const float*)d_in[8];
    const float* qkv1_b = (const float*)d_in[9];
    const float* bn1_g  = (const float*)d_in[10];
    const float* bn1_b  = (const float*)d_in[11];
    const float* bn1_m  = (const float*)d_in[12];
    const float* bn1_v  = (const float*)d_in[13];
    const float* qkv2_w = (const float*)d_in[14];
    const float* qkv2_b = (const float*)d_in[15];
    const float* bn2_g  = (const float*)d_in[16];
    const float* bn2_b  = (const float*)d_in[17];
    const float* bn2_m  = (const float*)d_in[18];
    const float* bn2_v  = (const float*)d_in[19];
    const float* ca_w1  = (const float*)d_in[20];
    const float* ca_b1  = (const float*)d_in[21];
    const float* ca_w2  = (const float*)d_in[22];
    const float* ca_b2  = (const float*)d_in[23];
    const float* po1_w  = (const float*)d_in[24];
    const float* po1_b  = (const float*)d_in[25];
    const float* po2_w  = (const float*)d_in[26];
    const float* po2_b  = (const float*)d_in[27];
    float* out = (float*)d_out;

    zero_pool_kernel<<<16, 256>>>();
    msconv_kernel<<<dim3(CC, BB, 2), 256>>>(x1, x2, ms_w3, ms_b3, ms_w5, ms_b5, ms_w7, ms_b7);
    qkv_gemm_kernel<<<dim3(HWP/64, C3/64, 16), 256>>>(
        qkv1_w, qkv1_b, bn1_g, bn1_b, bn1_m, bn1_v,
        qkv2_w, qkv2_b, bn2_g, bn2_b, bn2_m, bn2_v);
    norm_kernel<<<dim3(512, BB, 2), 256>>>();
    attn_kernel<<<dim3(NHH, BB, 2), 256>>>();
    av_kernel<<<dim3(HWP/64, NHH*BB, 2), 256>>>();
    se_kernel<<<dim3(BB, 2), 256>>>(ca_w1, ca_b1, ca_w2, ca_b2);
    out_gemm_kernel<<<dim3(HWP/64, CC/64, 16), 256>>>(x1, x2, po1_w, po1_b, po2_w, po2_b, out);
}

// round 3
// speedup vs baseline: 2.1943x; 2.1943x over previous
#include <cuda_runtime.h>
#include <math.h>
#include <cstdint>

#define BB  8
#define CC  256
#define HH  64
#define WW  64
#define HWP 4096
#define NHH 4
#define HDD 64
#define C3  768

// ---- scratch (static device globals; no allocation at runtime) ----
__device__ float g_xf  [2ULL*BB*CC*HWP];     //  67 MB  multiscale conv out
__device__ float g_qkv [2ULL*BB*C3*HWP];     // 201 MB  gelu(bn(qkv))
__device__ float g_rnorm[2*BB*2*CC];         //  reciprocal L2 norms
__device__ float g_attn[2*BB*NHH*HDD*HDD];   //  softmaxed attention
__device__ float g_xout[2ULL*BB*CC*HWP];     //  67 MB  attn @ v
__device__ float g_pool[2*BB*CC];
__device__ float g_gate[2*BB*CC];

// ======================= helpers =======================
__device__ __forceinline__ uint32_t smem_u32(const void* p) {
    uint32_t a;
    asm("{ .reg .u64 t; cvta.to.shared.u64 t, %1; cvt.u32.u64 %0, t; }" : "=r"(a) : "l"(p));
    return a;
}
__device__ __forceinline__ uint32_t tf32r(float x) {
    uint32_t y; asm("cvt.rna.tf32.f32 %0, %1;" : "=r"(y) : "f"(x)); return y;
}
__device__ __forceinline__ void cpa16(uint32_t dst, const void* src) {
    asm volatile("cp.async.cg.shared.global [%0], [%1], 16;" :: "r"(dst), "l"(src));
}
#define CPA_COMMIT() asm volatile("cp.async.commit_group;" ::: "memory")
#define CPA_WAIT1()  asm volatile("cp.async.wait_group 1;" ::: "memory")
#define CPA_WAIT0()  asm volatile("cp.async.wait_group 0;" ::: "memory")

__device__ __forceinline__ void mma_tf32(float* d, const uint32_t* a, uint32_t b0, uint32_t b1) {
    asm volatile(
        "mma.sync.aligned.m16n8k8.row.col.f32.tf32.tf32.f32 "
        "{%0,%1,%2,%3}, {%4,%5,%6,%7}, {%8,%9}, {%0,%1,%2,%3};"
        : "+f"(d[0]), "+f"(d[1]), "+f"(d[2]), "+f"(d[3])
        : "r"(a[0]), "r"(a[1]), "r"(a[2]), "r"(a[3]), "r"(b0), "r"(b1));
}

// smem strides (floats), padded for conflict-free fragment loads
#define ASTRIDE 20    // A tile: 128 rows (m) x 16 (k), row stride 20 (80B, 16B-mult)
#define BSTRIDE 136   // B tile: 16 rows (k) x 128 (n), row stride 136 (544B, 16B-mult)

// ---------------------------------------------------------------------------
// K0: zero the pooling accumulator
// ---------------------------------------------------------------------------
__global__ void zero_pool_kernel() {
    int i = blockIdx.x * 256 + threadIdx.x;
    if (i < 2*BB*CC) g_pool[i] = 0.0f;
}

// ---------------------------------------------------------------------------
// K1: fused multiscale depthwise conv (k=3,5,7 averaged)
// ---------------------------------------------------------------------------
__global__ void msconv_kernel(const float* __restrict__ x1, const float* __restrict__ x2,
                              const float* __restrict__ w3, const float* __restrict__ b3,
                              const float* __restrict__ w5, const float* __restrict__ b5,
                              const float* __restrict__ w7, const float* __restrict__ b7)
{
    int c = blockIdx.x, b = blockIdx.y, s = blockIdx.z;
    const float* xin = (s ? x2 : x1) + ((size_t)b*CC + c)*HWP;

    __shared__ float tile[70*70];
    __shared__ float wc[49];
    int t = threadIdx.x;

    if (t < 49) {
        int ky = t / 7, kx = t % 7;
        float w = w7[c*49 + t];
        if (ky >= 1 && ky <= 5 && kx >= 1 && kx <= 5) w += w5[c*25 + (ky-1)*5 + (kx-1)];
        if (ky >= 2 && ky <= 4 && kx >= 2 && kx <= 4) w += w3[c*9  + (ky-2)*3 + (kx-2)];
        wc[t] = w * (1.0f/3.0f);
    }
    for (int i = t; i < 70*70; i += 256) {
        int ty = i / 70, tx = i % 70;
        int gy = ty - 3, gx = tx - 3;
        tile[i] = (gy >= 0 && gy < HH && gx >= 0 && gx < WW) ? xin[gy*WW + gx] : 0.0f;
    }
    __syncthreads();

    float bias = (b3[c] + b5[c] + b7[c]) * (1.0f/3.0f);
    float* outp = g_xf + ((size_t)(s*BB+b)*CC + c)*HWP;
    #pragma unroll
    for (int i = 0; i < 16; i++) {
        int p = t + i*256;
        int py = p >> 6, px = p & 63;
        float acc = bias;
        #pragma unroll
        for (int ky = 0; ky < 7; ky++)
            #pragma unroll
            for (int kx = 0; kx < 7; kx++)
                acc += wc[ky*7+kx] * tile[(py+ky)*70 + px+kx];
        outp[p] = acc;
    }
}

// ---------------------------------------------------------------------------
// K2: qkv GEMM on mma.sync tf32.  Block: M=128, N=128, K=256, BK=16, 8 warps,
// cp.async double buffer.  Epilogue: +bias, BN, exact GELU.
// ---------------------------------------------------------------------------
__global__ void __launch_bounds__(256, 2) qkv_tc_kernel(
    const float* __restrict__ w1, const float* __restrict__ bq1,
    const float* __restrict__ g1, const float* __restrict__ be1,
    const float* __restrict__ m1, const float* __restrict__ v1,
    const float* __restrict__ w2, const float* __restrict__ bq2,
    const float* __restrict__ g2, const float* __restrict__ be2,
    const float* __restrict__ m2, const float* __restrict__ v2)
{
    __shared__ __align__(16) float sA[2][128*ASTRIDE];
    __shared__ __align__(16) float sB[2][16*BSTRIDE];

    int pBase = blockIdx.x * 128;
    int oBase = blockIdx.y * 128;
    int s = blockIdx.z >> 3, b = blockIdx.z & 7;

    const float* W   = s ? w2  : w1;
    const float* bq  = s ? bq2 : bq1;
    const float* bg  = s ? g2  : g1;
    const float* bbv = s ? be2 : be1;
    const float* bm  = s ? m2  : m1;
    const float* bv  = s ? v2  : v1;
    const float* X   = g_xf  + (size_t)(s*BB+b)*CC*HWP;
    float*       Y   = g_qkv + (size_t)(s*BB+b)*C3*HWP;

    int t = threadIdx.x;
    int wid = t >> 5, lane = t & 31;
    int warpM = wid >> 1, warpN = wid & 1;
    int mbw = warpM*32, nbw = warpN*64;
    int g = lane >> 2, q = lane & 3;

    uint32_t sAb[2] = { smem_u32(sA[0]), smem_u32(sA[1]) };
    uint32_t sBb[2] = { smem_u32(sB[0]), smem_u32(sB[1]) };

    // staging indices: A chunks (row = m, q4 = 16B quarter of 16-float row)
    int aRow0 = t >> 1,        aQ0 = (t & 1) * 2;      // chunks t*2
    // actually map: 512 chunks, thread handles chunk t and t+256
    // chunk c: row = c>>2, q4 = c&3
    int ac0_r = t >> 2, ac0_q = t & 3;
    int ac1_r = (t + 256) >> 2, ac1_q = (t + 256) & 3;
    int bc0_r = t >> 5, bc0_q = t & 31;
    int bc1_r = (t + 256) >> 5, bc1_q = (t + 256) & 31;
    (void)aRow0; (void)aQ0;

    float acc[2][8][4] = {};

    auto stage = [&](int k0, int buf) {
        cpa16(sAb[buf] + (uint32_t)(ac0_r*ASTRIDE + ac0_q*4)*4,
              W + (size_t)(oBase + ac0_r)*CC + k0 + ac0_q*4);
        cpa16(sAb[buf] + (uint32_t)(ac1_r*ASTRIDE + ac1_q*4)*4,
              W + (size_t)(oBase + ac1_r)*CC + k0 + ac1_q*4);
        cpa16(sBb[buf] + (uint32_t)(bc0_r*BSTRIDE + bc0_q*4)*4,
              X + (size_t)(k0 + bc0_r)*HWP + pBase + bc0_q*4);
        cpa16(sBb[buf] + (uint32_t)(bc1_r*BSTRIDE + bc1_q*4)*4,
              X + (size_t)(k0 + bc1_r)*HWP + pBase + bc1_q*4);
    };

    stage(0, 0);
    CPA_COMMIT();

    const int NIT = CC / 16;
    for (int it = 0; it < NIT; it++) {
        int buf = it & 1;
        if (it + 1 < NIT) { stage((it+1)*16, buf ^ 1); CPA_COMMIT(); CPA_WAIT1(); }
        else CPA_WAIT0();
        __syncthreads();

        const float* A = sA[buf];
        const float* Bm = sB[buf];
        #pragma unroll
        for (int kk = 0; kk < 2; kk++) {
            uint32_t af[2][4];
            #pragma unroll
            for (int mt = 0; mt < 2; mt++) {
                int m = mbw + mt*16 + g;
                int k = kk*8 + q;
                af[mt][0] = tf32r(A[m*ASTRIDE + k]);
                af[mt][1] = tf32r(A[(m+8)*ASTRIDE + k]);
                af[mt][2] = tf32r(A[m*ASTRIDE + k + 4]);
                af[mt][3] = tf32r(A[(m+8)*ASTRIDE + k + 4]);
            }
            #pragma unroll
            for (int nt = 0; nt < 8; nt++) {
                int n = nbw + nt*8 + g;
                int k = kk*8 + q;
                uint32_t b0 = tf32r(Bm[k*BSTRIDE + n]);
                uint32_t b1 = tf32r(Bm[(k+4)*BSTRIDE + n]);
                mma_tf32(acc[0][nt], af[0], b0, b1);
                mma_tf32(acc[1][nt], af[1], b0, b1);
            }
        }
        __syncthreads();
    }

    // epilogue: BN + exact GELU
    #pragma unroll
    for (int mt = 0; mt < 2; mt++) {
        int o0 = oBase + mbw + mt*16 + g;
        int o1 = o0 + 8;
        float scl0 = bg[o0] * rsqrtf(bv[o0] + 1e-5f);
        float sft0 = bbv[o0] - bm[o0]*scl0 + bq[o0]*scl0;
        float scl1 = bg[o1] * rsqrtf(bv[o1] + 1e-5f);
        float sft1 = bbv[o1] - bm[o1]*scl1 + bq[o1]*scl1;
        float* y0 = Y + (size_t)o0*HWP + pBase + nbw + q*2;
        float* y1 = Y + (size_t)o1*HWP + pBase + nbw + q*2;
        #pragma unroll
        for (int nt = 0; nt < 8; nt++) {
            float2 v0, v1;
            v0.x = acc[mt][nt][0]*scl0 + sft0;
            v0.y = acc[mt][nt][1]*scl0 + sft0;
            v1.x = acc[mt][nt][2]*scl1 + sft1;
            v1.y = acc[mt][nt][3]*scl1 + sft1;
            v0.x = 0.5f*v0.x*(1.0f + erff(v0.x*0.70710678118654752f));
            v0.y = 0.5f*v0.y*(1.0f + erff(v0.y*0.70710678118654752f));
            v1.x = 0.5f*v1.x*(1.0f + erff(v1.x*0.70710678118654752f));
            v1.y = 0.5f*v1.y*(1.0f + erff(v1.y*0.70710678118654752f));
            *(float2*)(y0 + nt*8) = v0;
            *(float2*)(y1 + nt*8) = v1;
        }
    }
}

// ---------------------------------------------------------------------------
// K3: reciprocal L2 norms
// ---------------------------------------------------------------------------
__global__ void norm_kernel() {
    int ch = blockIdx.x, b = blockIdx.y, s = blockIdx.z;
    const float* row = g_qkv + ((size_t)(s*BB+b)*C3 + ch)*HWP;
    float ss = 0.0f;
    for (int i = threadIdx.x; i < HWP; i += 256) { float v = row[i]; ss += v*v; }
    __shared__ float red[256];
    red[threadIdx.x] = ss; __syncthreads();
    for (int st = 128; st > 0; st >>= 1) {
        if (threadIdx.x < st) red[threadIdx.x] += red[threadIdx.x + st];
        __syncthreads();
    }
    if (threadIdx.x == 0) {
        float n = sqrtf(red[0]);
        g_rnorm[(s*BB+b)*512 + ch] = 1.0f / fmaxf(n, 1e-12f);
    }
}

// ---------------------------------------------------------------------------
// K4: cross-attention logits + softmax
// ---------------------------------------------------------------------------
__global__ void attn_kernel() {
    int h = blockIdx.x, b = blockIdx.y, which = blockIdx.z;
    int qs = which, ks = 1 - which;
    const float* Q = g_qkv + ((size_t)(qs*BB+b)*C3 +       h*HDD)*HWP;
    const float* K = g_qkv + ((size_t)(ks*BB+b)*C3 + CC +  h*HDD)*HWP;

    __shared__ float Qs[64][33];
    __shared__ float Ks[64][33];
    __shared__ float Ss[64][65];
    __shared__ float rq[64], rk[64];

    int t = threadIdx.x;
    int tx = t & 15, ty = t >> 4;

    if (t < 64) {
        rq[t] = g_rnorm[(qs*BB+b)*512 +       h*64 + t];
        rk[t] = g_rnorm[(ks*BB+b)*512 + 256 + h*64 + t];
    }

    float acc[4][4] = {};
    for (int n0 = 0; n0 < HWP; n0 += 32) {
        #pragma unroll
        for (int e = 0; e < 8; e++) {
            int idx = t + e*256;
            int cc = idx >> 5, nn = idx & 31;
            Qs[cc][nn] = Q[(size_t)cc*HWP + n0 + nn];
            Ks[cc][nn] = K[(size_t)cc*HWP + n0 + nn];
        }
        __syncthreads();
        #pragma unroll
        for (int nn = 0; nn < 32; nn++) {
            float ra[4], rb[4];
            #pragma unroll
            for (int ii = 0; ii < 4; ii++) ra[ii] = Qs[ty*4+ii][nn];
            #pragma unroll
            for (int jj = 0; jj < 4; jj++) rb[jj] = Ks[tx*4+jj][nn];
            #pragma unroll
            for (int ii = 0; ii < 4; ii++)
                #pragma unroll
                for (int jj = 0; jj < 4; jj++)
                    acc[ii][jj] += ra[ii]*rb[jj];
        }
        __syncthreads();
    }

    const float temp = 0.125f;
    #pragma unroll
    for (int ii = 0; ii < 4; ii++)
        #pragma unroll
        for (int jj = 0; jj < 4; jj++)
            Ss[ty*4+ii][tx*4+jj] = acc[ii][jj] * temp * rq[ty*4+ii] * rk[tx*4+jj];
    __syncthreads();

    if (t < 64) {
        float m = -1e30f;
        #pragma unroll
        for (int d = 0; d < 64; d++) m = fmaxf(m, Ss[t][d]);
        float sum = 0.0f;
        #pragma unroll
        for (int d = 0; d < 64; d++) { float ev = expf(Ss[t][d] - m); Ss[t][d] = ev; sum += ev; }
        float inv = 1.0f / sum;
        float* ap = g_attn + ((size_t)((which*BB+b)*NHH + h)*HDD + t)*HDD;
        #pragma unroll
        for (int d = 0; d < 64; d++) ap[d] = Ss[t][d]*inv;
    }
}

// ---------------------------------------------------------------------------
// K5: x_out = attn @ v; accumulates SE pool
// ---------------------------------------------------------------------------
__global__ void av_kernel() {
    int nTile = blockIdx.x;
    int hb = blockIdx.y;
    int which = blockIdx.z;
    int h = hb & 3, b = hb >> 2;
    const float* V = g_qkv  + ((size_t)(which*BB+b)*C3 + 2*CC + h*HDD)*HWP;
    const float* A = g_attn + (size_t)((which*BB+b)*NHH + h)*HDD*HDD;

    __shared__ float As[64][65];
    __shared__ float Vs[64][65];
    __shared__ float psum[64];

    int t = threadIdx.x;
    for (int i = t; i < 4096; i += 256) As[i >> 6][i & 63] = A[i];
    int n0 = nTile*64;
    #pragma unroll
    for (int e = 0; e < 16; e++) {
        int idx = t + e*256;
        int d = idx >> 6, nn = idx & 63;
        Vs[d][nn] = V[(size_t)d*HWP + n0 + nn];
    }
    if (t < 64) psum[t] = 0.0f;
    __syncthreads();

    int tx = t & 15, ty = t >> 4;
    float acc[4][4] = {};
    #pragma unroll 8
    for (int d = 0; d < 64; d++) {
        float rb[4];
        #pragma unroll
        for (int jj = 0; jj < 4; jj++) rb[jj] = Vs[d][tx*4+jj];
        #pragma unroll
        for (int ii = 0; ii < 4; ii++) {
            float ra = As[ty*4+ii][d];
            #pragma unroll
            for (int jj = 0; jj < 4; jj++) acc[ii][jj] += ra*rb[jj];
        }
    }

    float* O = g_xout + ((size_t)(which*BB+b)*CC + h*HDD)*HWP;
    #pragma unroll
    for (int ii = 0; ii < 4; ii++) {
        int cidx = ty*4 + ii;
        float rs = 0.0f;
        #pragma unroll
        for (int jj = 0; jj < 4; jj++) {
            O[(size_t)cidx*HWP + n0 + tx*4 + jj] = acc[ii][jj];
            rs += acc[ii][jj];
        }
        atomicAdd(&psum[cidx], rs);
    }
    __syncthreads();
    if (t < 64) atomicAdd(&g_pool[(which*BB+b)*CC + h*HDD + t], psum[t]);
}

// ---------------------------------------------------------------------------
// K6: SE gate
// ---------------------------------------------------------------------------
__global__ void se_kernel(const float* __restrict__ w1, const float* __restrict__ b1_,
                          const float* __restrict__ w2, const float* __restrict__ b2_)
{
    int b = blockIdx.x, s = blockIdx.y;
    __shared__ float pm[256], ys[32];
    int t = threadIdx.x;
    pm[t] = g_pool[(s*BB+b)*CC + t] * (1.0f/HWP);
    __syncthreads();
    if (t < 32) {
        float a = b1_[t];
        #pragma unroll 8
        for (int c = 0; c < 256; c++) a += w1[t*256 + c]*pm[c];
        ys[t] = fmaxf(a, 0.0f);
    }
    __syncthreads();
    float a = b2_[t];
    #pragma unroll
    for (int r = 0; r < 32; r++) a += w2[t*32 + r]*ys[r];
    g_gate[(s*BB+b)*CC + t] = 1.0f/(1.0f + expf(-a));
}

// ---------------------------------------------------------------------------
// K7: output projection on mma.sync tf32; gate applied at B-fragment load;
//     epilogue bias + residual.
// ---------------------------------------------------------------------------
__global__ void __launch_bounds__(256, 2) out_tc_kernel(
    const float* __restrict__ x1, const float* __restrict__ x2,
    const float* __restrict__ pw1, const float* __restrict__ pb1,
    const float* __restrict__ pw2, const float* __restrict__ pb2,
    float* __restrict__ out)
{
    __shared__ __align__(16) float sA[2][128*ASTRIDE];
    __shared__ __align__(16) float sB[2][16*BSTRIDE];
    __shared__ float gs[256];

    int pBase = blockIdx.x * 128;
    int oBase = blockIdx.y * 128;
    int s = blockIdx.z >> 3, b = blockIdx.z & 7;

    const float* W    = s ? pw2 : pw1;
    const float* pb   = s ? pb2 : pb1;
    const float* X    = g_xout + (size_t)(s*BB+b)*CC*HWP;
    const float* gate = g_gate + (s*BB+b)*CC;
    const float* res  = (s ? x2 : x1) + (size_t)b*CC*HWP;
    float*       Y    = out + ((size_t)s*BB + b)*CC*HWP;

    int t = threadIdx.x;
    int wid = t >> 5, lane = t & 31;
    int warpM = wid >> 1, warpN = wid & 1;
    int mbw = warpM*32, nbw = warpN*64;
    int g = lane >> 2, q = lane & 3;

    gs[t] = gate[t];

    uint32_t sAb[2] = { smem_u32(sA[0]), smem_u32(sA[1]) };
    uint32_t sBb[2] = { smem_u32(sB[0]), smem_u32(sB[1]) };

    int ac0_r = t >> 2, ac0_q = t & 3;
    int ac1_r = (t + 256) >> 2, ac1_q = (t + 256) & 3;
    int bc0_r = t >> 5, bc0_q = t & 31;
    int bc1_r = (t + 256) >> 5, bc1_q = (t + 256) & 31;

    float acc[2][8][4] = {};

    auto stage = [&](int k0, int buf) {
        cpa16(sAb[buf] + (uint32_t)(ac0_r*ASTRIDE + ac0_q*4)*4,
              W + (size_t)(oBase + ac0_r)*CC + k0 + ac0_q*4);
        cpa16(sAb[buf] + (uint32_t)(ac1_r*ASTRIDE + ac1_q*4)*4,
              W + (size_t)(oBase + ac1_r)*CC + k0 + ac1_q*4);
        cpa16(sBb[buf] + (uint32_t)(bc0_r*BSTRIDE + bc0_q*4)*4,
              X + (size_t)(k0 + bc0_r)*HWP + pBase + bc0_q*4);
        cpa16(sBb[buf] + (uint32_t)(bc1_r*BSTRIDE + bc1_q*4)*4,
              X + (size_t)(k0 + bc1_r)*HWP + pBase + bc1_q*4);
    };

    stage(0, 0);
    CPA_COMMIT();

    const int NIT = CC / 16;
    for (int it = 0; it < NIT; it++) {
        int buf = it & 1;
        if (it + 1 < NIT) { stage((it+1)*16, buf ^ 1); CPA_COMMIT(); CPA_WAIT1(); }
        else CPA_WAIT0();
        __syncthreads();

        const float* A = sA[buf];
        const float* Bm = sB[buf];
        int k0 = it*16;
        #pragma unroll
        for (int kk = 0; kk < 2; kk++) {
            uint32_t af[2][4];
            #pragma unroll
            for (int mt = 0; mt < 2; mt++) {
                int m = mbw + mt*16 + g;
                int k = kk*8 + q;
                af[mt][0] = tf32r(A[m*ASTRIDE + k]);
                af[mt][1] = tf32r(A[(m+8)*ASTRIDE + k]);
                af[mt][2] = tf32r(A[m*ASTRIDE + k + 4]);
                af[mt][3] = tf32r(A[(m+8)*ASTRIDE + k + 4]);
            }
            float g0 = gs[k0 + kk*8 + q];
            float g1 = gs[k0 + kk*8 + q + 4];
            #pragma unroll
            for (int nt = 0; nt < 8; nt++) {
                int n = nbw + nt*8 + g;
                int k = kk*8 + q;
                uint32_t b0 = tf32r(Bm[k*BSTRIDE + n] * g0);
                uint32_t b1 = tf32r(Bm[(k+4)*BSTRIDE + n] * g1);
                mma_tf32(acc[0][nt], af[0], b0, b1);
                mma_tf32(acc[1][nt], af[1], b0, b1);
            }
        }
        __syncthreads();
    }

    #pragma unroll
    for (int mt = 0; mt < 2; mt++) {
        int o0 = oBase + mbw + mt*16 + g;
        int o1 = o0 + 8;
        float bo0 = pb[o0], bo1 = pb[o1];
        float* y0 = Y + (size_t)o0*HWP + pBase + nbw + q*2;
        float* y1 = Y + (size_t)o1*HWP + pBase + nbw + q*2;
        const float* r0 = res + (size_t)o0*HWP + pBase + nbw + q*2;
        const float* r1 = res + (size_t)o1*HWP + pBase + nbw + q*2;
        #pragma unroll
        for (int nt = 0; nt < 8; nt++) {
            float2 rv0 = *(const float2*)(r0 + nt*8);
            float2 rv1 = *(const float2*)(r1 + nt*8);
            float2 v0, v1;
            v0.x = acc[mt][nt][0] + bo0 + rv0.x;
            v0.y = acc[mt][nt][1] + bo0 + rv0.y;
            v1.x = acc[mt][nt][2] + bo1 + rv1.x;
            v1.y = acc[mt][nt][3] + bo1 + rv1.y;
            *(float2*)(y0 + nt*8) = v0;
            *(float2*)(y1 + nt*8) = v1;
        }
    }
}

// ---------------------------------------------------------------------------
extern "C" void kernel_launch(void* const* d_in, const int* in_sizes, int n_in,
                              void* d_out, int out_size)
{
    const float* x1     = (const float*)d_in[0];
    const float* x2     = (const float*)d_in[1];
    const float* ms_w3  = (const float*)d_in[2];
    const float* ms_b3  = (const float*)d_in[3];
    const float* ms_w5  = (const float*)d_in[4];
    const float* ms_b5  = (const float*)d_in[5];
    const float* ms_w7  = (const float*)d_in[6];
    const float* ms_b7  = (const float*)d_in[7];
    const float* qkv1_w = (const float*)d_in[8];
    const float* qkv1_b = (const float*)d_in[9];
    const float* bn1_g  = (const float*)d_in[10];
    const float* bn1_b  = (const float*)d_in[11];
    const float* bn1_m  = (const float*)d_in[12];
    const float* bn1_v  = (const float*)d_in[13];
    const float* qkv2_w = (const float*)d_in[14];
    const float* qkv2_b = (const float*)d_in[15];
    const float* bn2_g  = (const float*)d_in[16];
    const float* bn2_b  = (const float*)d_in[17];
    const float* bn2_m  = (const float*)d_in[18];
    const float* bn2_v  = (const float*)d_in[19];
    const float* ca_w1  = (const float*)d_in[20];
    const float* ca_b1  = (const float*)d_in[21];
    const float* ca_w2  = (const float*)d_in[22];
    const float* ca_b2  = (const float*)d_in[23];
    const float* po1_w  = (const float*)d_in[24];
    const float* po1_b  = (const float*)d_in[25];
    const float* po2_w  = (const float*)d_in[26];
    const float* po2_b  = (const float*)d_in[27];
    float* out = (float*)d_out;

    zero_pool_kernel<<<16, 256>>>();
    msconv_kernel<<<dim3(CC, BB, 2), 256>>>(x1, x2, ms_w3, ms_b3, ms_w5, ms_b5, ms_w7, ms_b7);
    qkv_tc_kernel<<<dim3(HWP/128, C3/128, 16), 256>>>(
        qkv1_w, qkv1_b, bn1_g, bn1_b, bn1_m, bn1_v,
        qkv2_w, qkv2_b, bn2_g, bn2_b, bn2_m, bn2_v);
    norm_kernel<<<dim3(512, BB, 2), 256>>>();
    attn_kernel<<<dim3(NHH, BB, 2), 256>>>();
    av_kernel<<<dim3(HWP/64, NHH*BB, 2), 256>>>();
    se_kernel<<<dim3(BB, 2), 256>>>(ca_w1, ca_b1, ca_w2, ca_b2);
    out_tc_kernel<<<dim3(HWP/128, CC/128, 16), 256>>>(x1, x2, po1_w, po1_b, po2_w, po2_b, out);
}

// round 4
// speedup vs baseline: 3.2730x; 1.4916x over previous
#include <cuda_runtime.h>
#include <math.h>
#include <cstdint>

#define BB  8
#define CC  256
#define HH  64
#define WW  64
#define HWP 4096
#define NHH 4
#define HDD 64
#define C3  768
#define NPT 32            // qkv pTile count (4096/128)

// ---- scratch (static device globals; no allocation at runtime) ----
__device__ float g_xf   [2ULL*BB*CC*HWP];       //  67 MB  multiscale conv out
__device__ float g_qkv  [2ULL*BB*C3*HWP];       // 201 MB  gelu(bn(qkv))
__device__ float g_ss_part[NPT*16*512];         //  per-pTile sum-of-squares partials (q,k)
__device__ float g_vs_part[NPT*16*256];         //  per-pTile V row-sum partials
__device__ float g_rnorm[16*512];               //  reciprocal L2 norms
__device__ float g_vmean[16*256];               //  row-means of V
__device__ float g_lpart[4ULL*2*BB*NHH*HDD*HDD];// attn logit partials (4 chunks)
__device__ float g_attn [2*BB*NHH*HDD*HDD];     //  softmaxed attention
__device__ float g_pool [2*BB*CC];              //  = mean_n(A@V)
__device__ float g_gate [2*BB*CC];
__device__ float g_M    [16ULL*CC*CC];          //  M = PO*diag(gate)*A_blk

// ======================= helpers =======================
__device__ __forceinline__ uint32_t smem_u32(const void* p) {
    uint32_t a;
    asm("{ .reg .u64 t; cvta.to.shared.u64 t, %1; cvt.u32.u64 %0, t; }" : "=r"(a) : "l"(p));
    return a;
}
__device__ __forceinline__ uint32_t tf32r(float x) {
    uint32_t y; asm("cvt.rna.tf32.f32 %0, %1;" : "=r"(y) : "f"(x)); return y;
}
__device__ __forceinline__ void cpa16(uint32_t dst, const void* src) {
    asm volatile("cp.async.cg.shared.global [%0], [%1], 16;" :: "r"(dst), "l"(src));
}
#define CPA_COMMIT() asm volatile("cp.async.commit_group;" ::: "memory")
#define CPA_WAIT1()  asm volatile("cp.async.wait_group 1;" ::: "memory")
#define CPA_WAIT0()  asm volatile("cp.async.wait_group 0;" ::: "memory")

__device__ __forceinline__ void mma_tf32(float* d, const uint32_t* a, uint32_t b0, uint32_t b1) {
    asm volatile(
        "mma.sync.aligned.m16n8k8.row.col.f32.tf32.tf32.f32 "
        "{%0,%1,%2,%3}, {%4,%5,%6,%7}, {%8,%9}, {%0,%1,%2,%3};"
        : "+f"(d[0]), "+f"(d[1]), "+f"(d[2]), "+f"(d[3])
        : "r"(a[0]), "r"(a[1]), "r"(a[2]), "r"(a[3]), "r"(b0), "r"(b1));
}

#define ASTRIDE 20
#define BSTRIDE 136

// ---------------------------------------------------------------------------
// K1: fused multiscale depthwise conv; vertical register strips (16 rows/thr)
// ---------------------------------------------------------------------------
__global__ void msconv_kernel(const float* __restrict__ x1, const float* __restrict__ x2,
                              const float* __restrict__ w3, const float* __restrict__ b3,
                              const float* __restrict__ w5, const float* __restrict__ b5,
                              const float* __restrict__ w7, const float* __restrict__ b7)
{
    int c = blockIdx.x, b = blockIdx.y, s = blockIdx.z;
    const float* xin = (s ? x2 : x1) + ((size_t)b*CC + c)*HWP;

    __shared__ float tile[70*70];
    __shared__ float wc[49];
    int t = threadIdx.x;

    if (t < 49) {
        int ky = t / 7, kx = t % 7;
        float w = w7[c*49 + t];
        if (ky >= 1 && ky <= 5 && kx >= 1 && kx <= 5) w += w5[c*25 + (ky-1)*5 + (kx-1)];
        if (ky >= 2 && ky <= 4 && kx >= 2 && kx <= 4) w += w3[c*9  + (ky-2)*3 + (kx-2)];
        wc[t] = w * (1.0f/3.0f);
    }
    for (int i = t; i < 70*70; i += 256) {
        int ty = i / 70, tx = i % 70;
        int gy = ty - 3, gx = tx - 3;
        tile[i] = (gy >= 0 && gy < HH && gx >= 0 && gx < WW) ? xin[gy*WW + gx] : 0.0f;
    }
    __syncthreads();

    int tx = t & 63;
    int ty0 = (t >> 6) * 16;
    float bias = (b3[c] + b5[c] + b7[c]) * (1.0f/3.0f);

    float acc[16];
    #pragma unroll
    for (int i = 0; i < 16; i++) acc[i] = bias;

    #pragma unroll
    for (int r = 0; r < 22; r++) {
        float v[7];
        #pragma unroll
        for (int kx = 0; kx < 7; kx++) v[kx] = tile[(ty0 + r)*70 + tx + kx];
        #pragma unroll
        for (int ky = 0; ky < 7; ky++) {
            int ro = r - ky;
            if (ro >= 0 && ro < 16) {
                #pragma unroll
                for (int kx = 0; kx < 7; kx++)
                    acc[ro] += wc[ky*7+kx] * v[kx];
            }
        }
    }

    float* outp = g_xf + ((size_t)(s*BB+b)*CC + c)*HWP;
    #pragma unroll
    for (int i = 0; i < 16; i++)
        outp[(ty0 + i)*WW + tx] = acc[i];
}

// ---------------------------------------------------------------------------
// K2: qkv GEMM (mma.sync tf32) + BN + GELU epilogue; also emits per-pTile
//     sum-of-squares (q,k channels) and row-sum (v channels) partials.
// ---------------------------------------------------------------------------
__global__ void __launch_bounds__(256, 2) qkv_tc_kernel(
    const float* __restrict__ w1, const float* __restrict__ bq1,
    const float* __restrict__ g1, const float* __restrict__ be1,
    const float* __restrict__ m1, const float* __restrict__ v1,
    const float* __restrict__ w2, const float* __restrict__ bq2,
    const float* __restrict__ g2, const float* __restrict__ be2,
    const float* __restrict__ m2, const float* __restrict__ v2)
{
    __shared__ __align__(16) float sA[2][128*ASTRIDE];
    __shared__ __align__(16) float sB[2][16*BSTRIDE];
    __shared__ float sred[128][2];

    int pTile = blockIdx.x;
    int pBase = pTile * 128;
    int oBase = blockIdx.y * 128;
    int s = blockIdx.z >> 3, b = blockIdx.z & 7;
    int sb = s*BB + b;

    const float* W   = s ? w2  : w1;
    const float* bq  = s ? bq2 : bq1;
    const float* bg  = s ? g2  : g1;
    const float* bbv = s ? be2 : be1;
    const float* bm  = s ? m2  : m1;
    const float* bv  = s ? v2  : v1;
    const float* X   = g_xf  + (size_t)sb*CC*HWP;
    float*       Y   = g_qkv + (size_t)sb*C3*HWP;

    int t = threadIdx.x;
    int wid = t >> 5, lane = t & 31;
    int warpM = wid >> 1, warpN = wid & 1;
    int mbw = warpM*32, nbw = warpN*64;
    int g = lane >> 2, q = lane & 3;

    uint32_t sAb[2] = { smem_u32(sA[0]), smem_u32(sA[1]) };
    uint32_t sBb[2] = { smem_u32(sB[0]), smem_u32(sB[1]) };

    int ac0_r = t >> 2, ac0_q = t & 3;
    int ac1_r = (t + 256) >> 2, ac1_q = (t + 256) & 3;
    int bc0_r = t >> 5, bc0_q = t & 31;
    int bc1_r = (t + 256) >> 5, bc1_q = (t + 256) & 31;

    float acc[2][8][4] = {};

    auto stage = [&](int k0, int buf) {
        cpa16(sAb[buf] + (uint32_t)(ac0_r*ASTRIDE + ac0_q*4)*4,
              W + (size_t)(oBase + ac0_r)*CC + k0 + ac0_q*4);
        cpa16(sAb[buf] + (uint32_t)(ac1_r*ASTRIDE + ac1_q*4)*4,
              W + (size_t)(oBase + ac1_r)*CC + k0 + ac1_q*4);
        cpa16(sBb[buf] + (uint32_t)(bc0_r*BSTRIDE + bc0_q*4)*4,
              X + (size_t)(k0 + bc0_r)*HWP + pBase + bc0_q*4);
        cpa16(sBb[buf] + (uint32_t)(bc1_r*BSTRIDE + bc1_q*4)*4,
              X + (size_t)(k0 + bc1_r)*HWP + pBase + bc1_q*4);
    };

    stage(0, 0);
    CPA_COMMIT();

    const int NIT = CC / 16;
    for (int it = 0; it < NIT; it++) {
        int buf = it & 1;
        if (it + 1 < NIT) { stage((it+1)*16, buf ^ 1); CPA_COMMIT(); CPA_WAIT1(); }
        else CPA_WAIT0();
        __syncthreads();

        const float* A = sA[buf];
        const float* Bm = sB[buf];
        #pragma unroll
        for (int kk = 0; kk < 2; kk++) {
            uint32_t af[2][4];
            #pragma unroll
            for (int mt = 0; mt < 2; mt++) {
                int m = mbw + mt*16 + g;
                int k = kk*8 + q;
                af[mt][0] = tf32r(A[m*ASTRIDE + k]);
                af[mt][1] = tf32r(A[(m+8)*ASTRIDE + k]);
                af[mt][2] = tf32r(A[m*ASTRIDE + k + 4]);
                af[mt][3] = tf32r(A[(m+8)*ASTRIDE + k + 4]);
            }
            #pragma unroll
            for (int nt = 0; nt < 8; nt++) {
                int n = nbw + nt*8 + g;
                int k = kk*8 + q;
                uint32_t b0 = tf32r(Bm[k*BSTRIDE + n]);
                uint32_t b1 = tf32r(Bm[(k+4)*BSTRIDE + n]);
                mma_tf32(acc[0][nt], af[0], b0, b1);
                mma_tf32(acc[1][nt], af[1], b0, b1);
            }
        }
        __syncthreads();
    }

    bool isV = (oBase >= 512);
    float rs[2][2] = {};

    // epilogue: BN + exact GELU; accumulate row statistics
    #pragma unroll
    for (int mt = 0; mt < 2; mt++) {
        int o0 = oBase + mbw + mt*16 + g;
        int o1 = o0 + 8;
        float scl0 = bg[o0] * rsqrtf(bv[o0] + 1e-5f);
        float sft0 = bbv[o0] - bm[o0]*scl0 + bq[o0]*scl0;
        float scl1 = bg[o1] * rsqrtf(bv[o1] + 1e-5f);
        float sft1 = bbv[o1] - bm[o1]*scl1 + bq[o1]*scl1;
        float* y0 = Y + (size_t)o0*HWP + pBase + nbw + q*2;
        float* y1 = Y + (size_t)o1*HWP + pBase + nbw + q*2;
        #pragma unroll
        for (int nt = 0; nt < 8; nt++) {
            float2 v0, v1;
            v0.x = acc[mt][nt][0]*scl0 + sft0;
            v0.y = acc[mt][nt][1]*scl0 + sft0;
            v1.x = acc[mt][nt][2]*scl1 + sft1;
            v1.y = acc[mt][nt][3]*scl1 + sft1;
            v0.x = 0.5f*v0.x*(1.0f + erff(v0.x*0.70710678118654752f));
            v0.y = 0.5f*v0.y*(1.0f + erff(v0.y*0.70710678118654752f));
            v1.x = 0.5f*v1.x*(1.0f + erff(v1.x*0.70710678118654752f));
            v1.y = 0.5f*v1.y*(1.0f + erff(v1.y*0.70710678118654752f));
            *(float2*)(y0 + nt*8) = v0;
            *(float2*)(y1 + nt*8) = v1;
            if (isV) {
                rs[mt][0] += v0.x + v0.y;
                rs[mt][1] += v1.x + v1.y;
            } else {
                rs[mt][0] += v0.x*v0.x + v0.y*v0.y;
                rs[mt][1] += v1.x*v1.x + v1.y*v1.y;
            }
        }
    }

    // reduce across the 4 q-lanes of each quad, combine warpN halves in smem
    #pragma unroll
    for (int mt = 0; mt < 2; mt++)
        #pragma unroll
        for (int rr = 0; rr < 2; rr++) {
            float v = rs[mt][rr];
            v += __shfl_xor_sync(0xffffffffu, v, 1);
            v += __shfl_xor_sync(0xffffffffu, v, 2);
            if (q == 0) sred[mbw + mt*16 + g + rr*8][warpN] = v;
        }
    __syncthreads();
    if (t < 128) {
        float tot = sred[t][0] + sred[t][1];
        if (isV) g_vs_part[((size_t)pTile*16 + sb)*256 + (oBase - 512 + t)] = tot;
        else     g_ss_part[((size_t)pTile*16 + sb)*512 + (oBase + t)] = tot;
    }
}

// ---------------------------------------------------------------------------
// K3: finalize rnorm and vmean from partials (deterministic)
// ---------------------------------------------------------------------------
__global__ void finalize_kernel() {
    int sb = blockIdx.x;
    int t = threadIdx.x;
    // t in [0,512): rnorm
    float ss = 0.0f;
    for (int p = 0; p < NPT; p++) ss += g_ss_part[((size_t)p*16 + sb)*512 + t];
    g_rnorm[sb*512 + t] = 1.0f / fmaxf(sqrtf(ss), 1e-12f);
    if (t < 256) {
        float vs = 0.0f;
        for (int p = 0; p < NPT; p++) vs += g_vs_part[((size_t)p*16 + sb)*256 + t];
        g_vmean[sb*256 + t] = vs * (1.0f/HWP);
    }
}

// ---------------------------------------------------------------------------
// K4: attention logit partials: raw QK^T over a 1024-wide n-chunk
// ---------------------------------------------------------------------------
__global__ void attn_part_kernel() {
    int cx = blockIdx.x;               // chunk 0..3
    int hb = blockIdx.y;               // h + 4*b
    int which = blockIdx.z;
    int h = hb & 3, b = hb >> 2;
    int qs = which, ks = 1 - which;
    const float* Q = g_qkv + ((size_t)(qs*BB+b)*C3 +       h*HDD)*HWP;
    const float* K = g_qkv + ((size_t)(ks*BB+b)*C3 + CC +  h*HDD)*HWP;

    __shared__ float Qs[64][33];
    __shared__ float Ks[64][33];

    int t = threadIdx.x;
    int tx = t & 15, ty = t >> 4;

    float acc[4][4] = {};
    int nEnd = (cx+1)*1024;
    for (int n0 = cx*1024; n0 < nEnd; n0 += 32) {
        #pragma unroll
        for (int e = 0; e < 8; e++) {
            int idx = t + e*256;
            int cc = idx >> 5, nn = idx & 31;
            Qs[cc][nn] = Q[(size_t)cc*HWP + n0 + nn];
            Ks[cc][nn] = K[(size_t)cc*HWP + n0 + nn];
        }
        __syncthreads();
        #pragma unroll
        for (int nn = 0; nn < 32; nn++) {
            float ra[4], rb[4];
            #pragma unroll
            for (int ii = 0; ii < 4; ii++) ra[ii] = Qs[ty*4+ii][nn];
            #pragma unroll
            for (int jj = 0; jj < 4; jj++) rb[jj] = Ks[tx*4+jj][nn];
            #pragma unroll
            for (int ii = 0; ii < 4; ii++)
                #pragma unroll
                for (int jj = 0; jj < 4; jj++)
                    acc[ii][jj] += ra[ii]*rb[jj];
        }
        __syncthreads();
    }

    float* P = g_lpart + (size_t)(((cx*2 + which)*BB + b)*NHH + h)*HDD*HDD;
    #pragma unroll
    for (int ii = 0; ii < 4; ii++)
        #pragma unroll
        for (int jj = 0; jj < 4; jj++)
            P[(ty*4+ii)*64 + tx*4+jj] = acc[ii][jj];
}

// ---------------------------------------------------------------------------
// K5: softmax over summed partials + SE-pool via A @ vmean
// ---------------------------------------------------------------------------
__global__ void attn_soft_kernel() {
    int hb = blockIdx.x;
    int which = blockIdx.y;
    int h = hb & 3, b = hb >> 2;
    int t = threadIdx.x;   // 64 threads, thread = attention row c

    __shared__ float S[64][65];
    __shared__ float rq[64], rk[64], vm[64];

    rq[t] = g_rnorm[(which*BB+b)*512 +       h*64 + t];
    rk[t] = g_rnorm[((1-which)*BB+b)*512 + 256 + h*64 + t];
    vm[t] = g_vmean[(which*BB+b)*256 + h*64 + t];

    // sum 4 chunk partials, coalesced
    #pragma unroll
    for (int cx = 0; cx < 4; cx++) {
        const float* P = g_lpart + (size_t)(((cx*2 + which)*BB + b)*NHH + h)*HDD*HDD;
        for (int idx = t; idx < 4096; idx += 64) {
            float v = P[idx];
            if (cx == 0) S[idx >> 6][idx & 63] = v;
            else         S[idx >> 6][idx & 63] += v;
        }
        __syncthreads();
    }

    float sc = 0.125f * rq[t];
    float m = -1e30f;
    #pragma unroll
    for (int d = 0; d < 64; d++) {
        float v = S[t][d] * sc * rk[d];
        S[t][d] = v;
        m = fmaxf(m, v);
    }
    float sum = 0.0f;
    #pragma unroll
    for (int d = 0; d < 64; d++) { float ev = expf(S[t][d] - m); S[t][d] = ev; sum += ev; }
    float inv = 1.0f / sum;

    float* ap = g_attn + (size_t)(((which*BB+b)*NHH + h)*HDD + t)*HDD;
    float pool = 0.0f;
    #pragma unroll
    for (int d = 0; d < 64; d++) {
        float a = S[t][d] * inv;
        ap[d] = a;
        pool += a * vm[d];
    }
    g_pool[(which*BB+b)*CC + h*64 + t] = pool;
}

// ---------------------------------------------------------------------------
// K6: SE gate (pool already holds the spatial mean)
// ---------------------------------------------------------------------------
__global__ void se_kernel(const float* __restrict__ w1, const float* __restrict__ b1_,
                          const float* __restrict__ w2, const float* __restrict__ b2_)
{
    int b = blockIdx.x, s = blockIdx.y;
    __shared__ float pm[256], ys[32];
    int t = threadIdx.x;
    pm[t] = g_pool[(s*BB+b)*CC + t];
    __syncthreads();
    if (t < 32) {
        float a = b1_[t];
        #pragma unroll 8
        for (int c = 0; c < 256; c++) a += w1[t*256 + c]*pm[c];
        ys[t] = fmaxf(a, 0.0f);
    }
    __syncthreads();
    float a = b2_[t];
    #pragma unroll
    for (int r = 0; r < 32; r++) a += w2[t*32 + r]*ys[r];
    g_gate[(s*BB+b)*CC + t] = 1.0f/(1.0f + expf(-a));
}

// ---------------------------------------------------------------------------
// K7: M = PO * diag(gate) * A_blk   (per (s,b,h): 256x64 = PO_blk @ A_h)
// ---------------------------------------------------------------------------
__global__ void __launch_bounds__(256) mproj_kernel(
    const float* __restrict__ pw1, const float* __restrict__ pw2)
{
    int h = blockIdx.x, b = blockIdx.y, s = blockIdx.z;
    int sb = s*BB + b;
    const float* PO = s ? pw2 : pw1;
    const float* A  = g_attn + (size_t)((sb)*NHH + h)*HDD*HDD;
    int t = threadIdx.x;

    __shared__ float Ag[64][65];
    __shared__ float gsl[64];

    if (t < 64) gsl[t] = g_gate[sb*CC + h*64 + t];
    for (int idx = t; idx < 4096; idx += 256)
        Ag[idx >> 6][idx & 63] = A[idx];
    __syncthreads();

    float m[64];
    #pragma unroll
    for (int d = 0; d < 64; d++) m[d] = 0.0f;

    const float* po = PO + (size_t)t*CC + h*64;
    for (int c = 0; c < 64; c++) {
        float poc = po[c] * gsl[c];
        #pragma unroll
        for (int d = 0; d < 64; d++) m[d] += poc * Ag[c][d];
    }

    float* Mp = g_M + (size_t)sb*CC*CC + (size_t)t*CC + h*64;
    #pragma unroll
    for (int d = 0; d < 64; d++) Mp[d] = m[d];
}

// ---------------------------------------------------------------------------
// K8: out = M @ V + bias + residual  (mma.sync tf32)
// ---------------------------------------------------------------------------
__global__ void __launch_bounds__(256, 2) mv_tc_kernel(
    const float* __restrict__ x1, const float* __restrict__ x2,
    const float* __restrict__ pb1, const float* __restrict__ pb2,
    float* __restrict__ out)
{
    __shared__ __align__(16) float sA[2][128*ASTRIDE];
    __shared__ __align__(16) float sB[2][16*BSTRIDE];

    int pBase = blockIdx.x * 128;
    int oBase = blockIdx.y * 128;
    int s = blockIdx.z >> 3, b = blockIdx.z & 7;
    int sb = s*BB + b;

    const float* Msb  = g_M + (size_t)sb*CC*CC;
    const float* pb   = s ? pb2 : pb1;
    const float* V    = g_qkv + (size_t)sb*C3*HWP + (size_t)512*HWP;
    const float* res  = (s ? x2 : x1) + (size_t)b*CC*HWP;
    float*       Y    = out + ((size_t)sb)*CC*HWP;

    int t = threadIdx.x;
    int wid = t >> 5, lane = t & 31;
    int warpM = wid >> 1, warpN = wid & 1;
    int mbw = warpM*32, nbw = warpN*64;
    int g = lane >> 2, q = lane & 3;

    uint32_t sAb[2] = { smem_u32(sA[0]), smem_u32(sA[1]) };
    uint32_t sBb[2] = { smem_u32(sB[0]), smem_u32(sB[1]) };

    int ac0_r = t >> 2, ac0_q = t & 3;
    int ac1_r = (t + 256) >> 2, ac1_q = (t + 256) & 3;
    int bc0_r = t >> 5, bc0_q = t & 31;
    int bc1_r = (t + 256) >> 5, bc1_q = (t + 256) & 31;

    float acc[2][8][4] = {};

    auto stage = [&](int k0, int buf) {
        cpa16(sAb[buf] + (uint32_t)(ac0_r*ASTRIDE + ac0_q*4)*4,
              Msb + (size_t)(oBase + ac0_r)*CC + k0 + ac0_q*4);
        cpa16(sAb[buf] + (uint32_t)(ac1_r*ASTRIDE + ac1_q*4)*4,
              Msb + (size_t)(oBase + ac1_r)*CC + k0 + ac1_q*4);
        cpa16(sBb[buf] + (uint32_t)(bc0_r*BSTRIDE + bc0_q*4)*4,
              V + (size_t)(k0 + bc0_r)*HWP + pBase + bc0_q*4);
        cpa16(sBb[buf] + (uint32_t)(bc1_r*BSTRIDE + bc1_q*4)*4,
              V + (size_t)(k0 + bc1_r)*HWP + pBase + bc1_q*4);
    };

    stage(0, 0);
    CPA_COMMIT();

    const int NIT = CC / 16;
    for (int it = 0; it < NIT; it++) {
        int buf = it & 1;
        if (it + 1 < NIT) { stage((it+1)*16, buf ^ 1); CPA_COMMIT(); CPA_WAIT1(); }
        else CPA_WAIT0();
        __syncthreads();

        const float* A = sA[buf];
        const float* Bm = sB[buf];
        #pragma unroll
        for (int kk = 0; kk < 2; kk++) {
            uint32_t af[2][4];
            #pragma unroll
            for (int mt = 0; mt < 2; mt++) {
                int m = mbw + mt*16 + g;
                int k = kk*8 + q;
                af[mt][0] = tf32r(A[m*ASTRIDE + k]);
                af[mt][1] = tf32r(A[(m+8)*ASTRIDE + k]);
                af[mt][2] = tf32r(A[m*ASTRIDE + k + 4]);
                af[mt][3] = tf32r(A[(m+8)*ASTRIDE + k + 4]);
            }
            #pragma unroll
            for (int nt = 0; nt < 8; nt++) {
                int n = nbw + nt*8 + g;
                int k = kk*8 + q;
                uint32_t b0 = tf32r(Bm[k*BSTRIDE + n]);
                uint32_t b1 = tf32r(Bm[(k+4)*BSTRIDE + n]);
                mma_tf32(acc[0][nt], af[0], b0, b1);
                mma_tf32(acc[1][nt], af[1], b0, b1);
            }
        }
        __syncthreads();
    }

    #pragma unroll
    for (int mt = 0; mt < 2; mt++) {
        int o0 = oBase + mbw + mt*16 + g;
        int o1 = o0 + 8;
        float bo0 = pb[o0], bo1 = pb[o1];
        float* y0 = Y + (size_t)o0*HWP + pBase + nbw + q*2;
        float* y1 = Y + (size_t)o1*HWP + pBase + nbw + q*2;
        const float* r0 = res + (size_t)o0*HWP + pBase + nbw + q*2;
        const float* r1 = res + (size_t)o1*HWP + pBase + nbw + q*2;
        #pragma unroll
        for (int nt = 0; nt < 8; nt++) {
            float2 rv0 = *(const float2*)(r0 + nt*8);
            float2 rv1 = *(const float2*)(r1 + nt*8);
            float2 v0, v1;
            v0.x = acc[mt][nt][0] + bo0 + rv0.x;
            v0.y = acc[mt][nt][1] + bo0 + rv0.y;
            v1.x = acc[mt][nt][2] + bo1 + rv1.x;
            v1.y = acc[mt][nt][3] + bo1 + rv1.y;
            *(float2*)(y0 + nt*8) = v0;
            *(float2*)(y1 + nt*8) = v1;
        }
    }
}

// ---------------------------------------------------------------------------
extern "C" void kernel_launch(void* const* d_in, const int* in_sizes, int n_in,
                              void* d_out, int out_size)
{
    const float* x1     = (const float*)d_in[0];
    const float* x2     = (const float*)d_in[1];
    const float* ms_w3  = (const float*)d_in[2];
    const float* ms_b3  = (const float*)d_in[3];
    const float* ms_w5  = (const float*)d_in[4];
    const float* ms_b5  = (const float*)d_in[5];
    const float* ms_w7  = (const float*)d_in[6];
    const float* ms_b7  = (const float*)d_in[7];
    const float* qkv1_w = (const float*)d_in[8];
    const float* qkv1_b = (const float*)d_in[9];
    const float* bn1_g  = (const float*)d_in[10];
    const float* bn1_b  = (const float*)d_in[11];
    const float* bn1_m  = (const float*)d_in[12];
    const float* bn1_v  = (const float*)d_in[13];
    const float* qkv2_w = (const float*)d_in[14];
    const float* qkv2_b = (const float*)d_in[15];
    const float* bn2_g  = (const float*)d_in[16];
    const float* bn2_b  = (const float*)d_in[17];
    const float* bn2_m  = (const float*)d_in[18];
    const float* bn2_v  = (const float*)d_in[19];
    const float* ca_w1  = (const float*)d_in[20];
    const float* ca_b1  = (const float*)d_in[21];
    const float* ca_w2  = (const float*)d_in[22];
    const float* ca_b2  = (const float*)d_in[23];
    const float* po1_w  = (const float*)d_in[24];
    const float* po1_b  = (const float*)d_in[25];
    const float* po2_w  = (const float*)d_in[26];
    const float* po2_b  = (const float*)d_in[27];
    float* out = (float*)d_out;

    msconv_kernel<<<dim3(CC, BB, 2), 256>>>(x1, x2, ms_w3, ms_b3, ms_w5, ms_b5, ms_w7, ms_b7);
    qkv_tc_kernel<<<dim3(NPT, C3/128, 16), 256>>>(
        qkv1_w, qkv1_b, bn1_g, bn1_b, bn1_m, bn1_v,
        qkv2_w, qkv2_b, bn2_g, bn2_b, bn2_m, bn2_v);
    finalize_kernel<<<16, 512>>>();
    attn_part_kernel<<<dim3(4, NHH*BB, 2), 256>>>();
    attn_soft_kernel<<<dim3(NHH*BB, 2), 64>>>();
    se_kernel<<<dim3(BB, 2), 256>>>(ca_w1, ca_b1, ca_w2, ca_b2);
    mproj_kernel<<<dim3(NHH, BB, 2), 256>>>(po1_w, po2_w);
    mv_tc_kernel<<<dim3(HWP/128, CC/128, 16), 256>>>(x1, x2, po1_b, po2_b, out);
}

// round 5
// speedup vs baseline: 3.8657x; 1.1811x over previous
#include <cuda_runtime.h>
#include <cuda_bf16.h>
#include <math.h>
#include <cstdint>

#define BB  8
#define CC  256
#define HH  64
#define WW  64
#define HWP 4096
#define NHH 4
#define HDD 64
#define C3  768
#define NPT 32            // qkv pTile count (4096/128)

// ---- scratch (static device globals; no allocation at runtime) ----
__device__ float          g_xf [2ULL*BB*CC*HWP];   //  67 MB  multiscale conv out
__device__ __nv_bfloat16  g_qk [2ULL*BB*512*HWP];  //  67 MB  gelu(bn(q,k)) in bf16
__device__ float          g_v  [2ULL*BB*CC*HWP];   //  67 MB  gelu(bn(v)) fp32
__device__ float g_ss_part[NPT*16*512];            //  per-pTile sum-of-squares partials (q,k)
__device__ float g_vs_part[NPT*16*256];            //  per-pTile V row-sum partials
__device__ float g_rnorm[16*512];                  //  reciprocal L2 norms
__device__ float g_vmean[16*256];                  //  row-means of V
__device__ float g_lpart[4ULL*2*BB*NHH*HDD*HDD];   //  attn logit partials (4 chunks)
__device__ float g_attn [2*BB*NHH*HDD*HDD];        //  softmaxed attention
__device__ float g_pool [2*BB*CC];                 //  = mean_n(A@V)
__device__ float g_gate [2*BB*CC];
__device__ float g_M    [16ULL*CC*CC];             //  M = PO*diag(gate)*A_blk

// ======================= helpers =======================
__device__ __forceinline__ uint32_t smem_u32(const void* p) {
    uint32_t a;
    asm("{ .reg .u64 t; cvta.to.shared.u64 t, %1; cvt.u32.u64 %0, t; }" : "=r"(a) : "l"(p));
    return a;
}
__device__ __forceinline__ uint32_t tf32r(float x) {
    uint32_t y; asm("cvt.rna.tf32.f32 %0, %1;" : "=r"(y) : "f"(x)); return y;
}
__device__ __forceinline__ void cpa16(uint32_t dst, const void* src) {
    asm volatile("cp.async.cg.shared.global [%0], [%1], 16;" :: "r"(dst), "l"(src));
}
#define CPA_COMMIT() asm volatile("cp.async.commit_group;" ::: "memory")
#define CPA_WAIT1()  asm volatile("cp.async.wait_group 1;" ::: "memory")
#define CPA_WAIT0()  asm volatile("cp.async.wait_group 0;" ::: "memory")

__device__ __forceinline__ void mma_tf32(float* d, const uint32_t* a, uint32_t b0, uint32_t b1) {
    asm volatile(
        "mma.sync.aligned.m16n8k8.row.col.f32.tf32.tf32.f32 "
        "{%0,%1,%2,%3}, {%4,%5,%6,%7}, {%8,%9}, {%0,%1,%2,%3};"
        : "+f"(d[0]), "+f"(d[1]), "+f"(d[2]), "+f"(d[3])
        : "r"(a[0]), "r"(a[1]), "r"(a[2]), "r"(a[3]), "r"(b0), "r"(b1));
}
__device__ __forceinline__ void mma_bf16(float* d, const uint32_t* a, uint32_t b0, uint32_t b1) {
    asm volatile(
        "mma.sync.aligned.m16n8k16.row.col.f32.bf16.bf16.f32 "
        "{%0,%1,%2,%3}, {%4,%5,%6,%7}, {%8,%9}, {%0,%1,%2,%3};"
        : "+f"(d[0]), "+f"(d[1]), "+f"(d[2]), "+f"(d[3])
        : "r"(a[0]), "r"(a[1]), "r"(a[2]), "r"(a[3]), "r"(b0), "r"(b1));
}

#define ASTRIDE 20
#define BSTRIDE 136

// ---------------------------------------------------------------------------
// K1: fused multiscale depthwise conv; vertical register strips (16 rows/thr)
// ---------------------------------------------------------------------------
__global__ void msconv_kernel(const float* __restrict__ x1, const float* __restrict__ x2,
                              const float* __restrict__ w3, const float* __restrict__ b3,
                              const float* __restrict__ w5, const float* __restrict__ b5,
                              const float* __restrict__ w7, const float* __restrict__ b7)
{
    int c = blockIdx.x, b = blockIdx.y, s = blockIdx.z;
    const float* xin = (s ? x2 : x1) + ((size_t)b*CC + c)*HWP;

    __shared__ float tile[70*70];
    __shared__ float wc[49];
    int t = threadIdx.x;

    if (t < 49) {
        int ky = t / 7, kx = t % 7;
        float w = w7[c*49 + t];
        if (ky >= 1 && ky <= 5 && kx >= 1 && kx <= 5) w += w5[c*25 + (ky-1)*5 + (kx-1)];
        if (ky >= 2 && ky <= 4 && kx >= 2 && kx <= 4) w += w3[c*9  + (ky-2)*3 + (kx-2)];
        wc[t] = w * (1.0f/3.0f);
    }
    for (int i = t; i < 70*70; i += 256) {
        int ty = i / 70, tx = i % 70;
        int gy = ty - 3, gx = tx - 3;
        tile[i] = (gy >= 0 && gy < HH && gx >= 0 && gx < WW) ? xin[gy*WW + gx] : 0.0f;
    }
    __syncthreads();

    int tx = t & 63;
    int ty0 = (t >> 6) * 16;
    float bias = (b3[c] + b5[c] + b7[c]) * (1.0f/3.0f);

    float acc[16];
    #pragma unroll
    for (int i = 0; i < 16; i++) acc[i] = bias;

    #pragma unroll
    for (int r = 0; r < 22; r++) {
        float v[7];
        #pragma unroll
        for (int kx = 0; kx < 7; kx++) v[kx] = tile[(ty0 + r)*70 + tx + kx];
        #pragma unroll
        for (int ky = 0; ky < 7; ky++) {
            int ro = r - ky;
            if (ro >= 0 && ro < 16) {
                #pragma unroll
                for (int kx = 0; kx < 7; kx++)
                    acc[ro] += wc[ky*7+kx] * v[kx];
            }
        }
    }

    float* outp = g_xf + ((size_t)(s*BB+b)*CC + c)*HWP;
    #pragma unroll
    for (int i = 0; i < 16; i++)
        outp[(ty0 + i)*WW + tx] = acc[i];
}

// ---------------------------------------------------------------------------
// K2: qkv GEMM (mma.sync tf32) + BN + GELU; q,k written bf16, v fp32.
//     Emits per-pTile sum-of-squares (q,k) and row-sum (v) partials.
// ---------------------------------------------------------------------------
__global__ void __launch_bounds__(256, 2) qkv_tc_kernel(
    const float* __restrict__ w1, const float* __restrict__ bq1,
    const float* __restrict__ g1, const float* __restrict__ be1,
    const float* __restrict__ m1, const float* __restrict__ v1,
    const float* __restrict__ w2, const float* __restrict__ bq2,
    const float* __restrict__ g2, const float* __restrict__ be2,
    const float* __restrict__ m2, const float* __restrict__ v2)
{
    __shared__ __align__(16) float sA[2][128*ASTRIDE];
    __shared__ __align__(16) float sB[2][16*BSTRIDE];
    __shared__ float sred[128][2];

    int pTile = blockIdx.x;
    int pBase = pTile * 128;
    int oBase = blockIdx.y * 128;
    int s = blockIdx.z >> 3, b = blockIdx.z & 7;
    int sb = s*BB + b;

    const float* W   = s ? w2  : w1;
    const float* bq  = s ? bq2 : bq1;
    const float* bg  = s ? g2  : g1;
    const float* bbv = s ? be2 : be1;
    const float* bm  = s ? m2  : m1;
    const float* bv  = s ? v2  : v1;
    const float* X   = g_xf + (size_t)sb*CC*HWP;

    int t = threadIdx.x;
    int wid = t >> 5, lane = t & 31;
    int warpM = wid >> 1, warpN = wid & 1;
    int mbw = warpM*32, nbw = warpN*64;
    int g = lane >> 2, q = lane & 3;

    uint32_t sAb[2] = { smem_u32(sA[0]), smem_u32(sA[1]) };
    uint32_t sBb[2] = { smem_u32(sB[0]), smem_u32(sB[1]) };

    int ac0_r = t >> 2, ac0_q = t & 3;
    int ac1_r = (t + 256) >> 2, ac1_q = (t + 256) & 3;
    int bc0_r = t >> 5, bc0_q = t & 31;
    int bc1_r = (t + 256) >> 5, bc1_q = (t + 256) & 31;

    float acc[2][8][4] = {};

    auto stage = [&](int k0, int buf) {
        cpa16(sAb[buf] + (uint32_t)(ac0_r*ASTRIDE + ac0_q*4)*4,
              W + (size_t)(oBase + ac0_r)*CC + k0 + ac0_q*4);
        cpa16(sAb[buf] + (uint32_t)(ac1_r*ASTRIDE + ac1_q*4)*4,
              W + (size_t)(oBase + ac1_r)*CC + k0 + ac1_q*4);
        cpa16(sBb[buf] + (uint32_t)(bc0_r*BSTRIDE + bc0_q*4)*4,
              X + (size_t)(k0 + bc0_r)*HWP + pBase + bc0_q*4);
        cpa16(sBb[buf] + (uint32_t)(bc1_r*BSTRIDE + bc1_q*4)*4,
              X + (size_t)(k0 + bc1_r)*HWP + pBase + bc1_q*4);
    };

    stage(0, 0);
    CPA_COMMIT();

    const int NIT = CC / 16;
    for (int it = 0; it < NIT; it++) {
        int buf = it & 1;
        if (it + 1 < NIT) { stage((it+1)*16, buf ^ 1); CPA_COMMIT(); CPA_WAIT1(); }
        else CPA_WAIT0();
        __syncthreads();

        const float* A = sA[buf];
        const float* Bm = sB[buf];
        #pragma unroll
        for (int kk = 0; kk < 2; kk++) {
            uint32_t af[2][4];
            #pragma unroll
            for (int mt = 0; mt < 2; mt++) {
                int m = mbw + mt*16 + g;
                int k = kk*8 + q;
                af[mt][0] = tf32r(A[m*ASTRIDE + k]);
                af[mt][1] = tf32r(A[(m+8)*ASTRIDE + k]);
                af[mt][2] = tf32r(A[m*ASTRIDE + k + 4]);
                af[mt][3] = tf32r(A[(m+8)*ASTRIDE + k + 4]);
            }
            #pragma unroll
            for (int nt = 0; nt < 8; nt++) {
                int n = nbw + nt*8 + g;
                int k = kk*8 + q;
                uint32_t b0 = tf32r(Bm[k*BSTRIDE + n]);
                uint32_t b1 = tf32r(Bm[(k+4)*BSTRIDE + n]);
                mma_tf32(acc[0][nt], af[0], b0, b1);
                mma_tf32(acc[1][nt], af[1], b0, b1);
            }
        }
        __syncthreads();
    }

    bool isV = (oBase >= 512);
    float rs[2][2] = {};

    // epilogue: BN + exact GELU; accumulate row statistics
    #pragma unroll
    for (int mt = 0; mt < 2; mt++) {
        int o0 = oBase + mbw + mt*16 + g;
        int o1 = o0 + 8;
        float scl0 = bg[o0] * rsqrtf(bv[o0] + 1e-5f);
        float sft0 = bbv[o0] - bm[o0]*scl0 + bq[o0]*scl0;
        float scl1 = bg[o1] * rsqrtf(bv[o1] + 1e-5f);
        float sft1 = bbv[o1] - bm[o1]*scl1 + bq[o1]*scl1;

        float* yv0 = g_v + ((size_t)sb*CC + (o0 - 512))*HWP + pBase + nbw + q*2;
        float* yv1 = g_v + ((size_t)sb*CC + (o1 - 512))*HWP + pBase + nbw + q*2;
        __nv_bfloat16* yq0 = g_qk + ((size_t)sb*512 + o0)*HWP + pBase + nbw + q*2;
        __nv_bfloat16* yq1 = g_qk + ((size_t)sb*512 + o1)*HWP + pBase + nbw + q*2;

        #pragma unroll
        for (int nt = 0; nt < 8; nt++) {
            float2 v0, v1;
            v0.x = acc[mt][nt][0]*scl0 + sft0;
            v0.y = acc[mt][nt][1]*scl0 + sft0;
            v1.x = acc[mt][nt][2]*scl1 + sft1;
            v1.y = acc[mt][nt][3]*scl1 + sft1;
            v0.x = 0.5f*v0.x*(1.0f + erff(v0.x*0.70710678118654752f));
            v0.y = 0.5f*v0.y*(1.0f + erff(v0.y*0.70710678118654752f));
            v1.x = 0.5f*v1.x*(1.0f + erff(v1.x*0.70710678118654752f));
            v1.y = 0.5f*v1.y*(1.0f + erff(v1.y*0.70710678118654752f));
            if (isV) {
                *(float2*)(yv0 + nt*8) = v0;
                *(float2*)(yv1 + nt*8) = v1;
                rs[mt][0] += v0.x + v0.y;
                rs[mt][1] += v1.x + v1.y;
            } else {
                *(__nv_bfloat162*)(yq0 + nt*8) = __float22bfloat162_rn(v0);
                *(__nv_bfloat162*)(yq1 + nt*8) = __float22bfloat162_rn(v1);
                rs[mt][0] += v0.x*v0.x + v0.y*v0.y;
                rs[mt][1] += v1.x*v1.x + v1.y*v1.y;
            }
        }
    }

    #pragma unroll
    for (int mt = 0; mt < 2; mt++)
        #pragma unroll
        for (int rr = 0; rr < 2; rr++) {
            float v = rs[mt][rr];
            v += __shfl_xor_sync(0xffffffffu, v, 1);
            v += __shfl_xor_sync(0xffffffffu, v, 2);
            if (q == 0) sred[mbw + mt*16 + g + rr*8][warpN] = v;
        }
    __syncthreads();
    if (t < 128) {
        float tot = sred[t][0] + sred[t][1];
        if (isV) g_vs_part[((size_t)pTile*16 + sb)*256 + (oBase - 512 + t)] = tot;
        else     g_ss_part[((size_t)pTile*16 + sb)*512 + (oBase + t)] = tot;
    }
}

// ---------------------------------------------------------------------------
// K3: finalize rnorm and vmean from partials (deterministic)
// ---------------------------------------------------------------------------
__global__ void finalize_kernel() {
    int sb = blockIdx.x;
    int t = threadIdx.x;
    float ss = 0.0f;
    for (int p = 0; p < NPT; p++) ss += g_ss_part[((size_t)p*16 + sb)*512 + t];
    g_rnorm[sb*512 + t] = 1.0f / fmaxf(sqrtf(ss), 1e-12f);
    if (t < 256) {
        float vs = 0.0f;
        for (int p = 0; p < NPT; p++) vs += g_vs_part[((size_t)p*16 + sb)*256 + t];
        g_vmean[sb*256 + t] = vs * (1.0f/HWP);
    }
}

// ---------------------------------------------------------------------------
// K4: attention logit partials via bf16 mma: raw QK^T over a 1024-wide n-chunk
//     8 warps; warp w owns d-columns [w*8, w*8+8), all 64 rows.
// ---------------------------------------------------------------------------
#define ANC 128
#define AST (ANC + 8)   // bf16 row stride (136 elems = 272B, 16B multiple)

__global__ void __launch_bounds__(256) attn_part_kernel() {
    int cx = blockIdx.x;               // chunk 0..3 (1024 cols each)
    int hb = blockIdx.y;               // h + 4*b
    int which = blockIdx.z;
    int h = hb & 3, b = hb >> 2;
    const __nv_bfloat16* Q = g_qk + ((size_t)(which*BB+b)*512 +       h*HDD)*HWP;
    const __nv_bfloat16* K = g_qk + ((size_t)((1-which)*BB+b)*512 + 256 + h*HDD)*HWP;

    __shared__ __align__(16) __nv_bfloat16 sQ[2][64*AST];
    __shared__ __align__(16) __nv_bfloat16 sK[2][64*AST];

    int t = threadIdx.x;
    int wid = t >> 5, lane = t & 31;
    int g = lane >> 2, q = lane & 3;
    int dBase = wid * 8;

    uint32_t sQb[2] = { smem_u32(sQ[0]), smem_u32(sQ[1]) };
    uint32_t sKb[2] = { smem_u32(sK[0]), smem_u32(sK[1]) };

    // staging: 64 rows x 128 bf16 per tile = 1024 16B-chunks; 4 per thread
    auto stage = [&](int n0, int buf) {
        #pragma unroll
        for (int e = 0; e < 4; e++) {
            int c = t + e*256;
            int row = c >> 4, grp = c & 15;
            cpa16(sQb[buf] + (uint32_t)(row*AST + grp*8)*2, Q + (size_t)row*HWP + n0 + grp*8);
            cpa16(sKb[buf] + (uint32_t)(row*AST + grp*8)*2, K + (size_t)row*HWP + n0 + grp*8);
        }
    };

    float acc[4][4] = {};
    int n0base = cx * 1024;

    stage(n0base, 0);
    CPA_COMMIT();

    for (int st = 0; st < 8; st++) {
        int buf = st & 1;
        if (st + 1 < 8) { stage(n0base + (st+1)*ANC, buf ^ 1); CPA_COMMIT(); CPA_WAIT1(); }
        else CPA_WAIT0();
        __syncthreads();

        const __nv_bfloat16* Qs = sQ[buf];
        const __nv_bfloat16* Ks = sK[buf];
        #pragma unroll
        for (int ks = 0; ks < 8; ks++) {
            uint32_t b0 = *(const uint32_t*)(Ks + (dBase + g)*AST + ks*16 + 2*q);
            uint32_t b1 = *(const uint32_t*)(Ks + (dBase + g)*AST + ks*16 + 2*q + 8);
            #pragma unroll
            for (int mt = 0; mt < 4; mt++) {
                uint32_t a[4];
                const __nv_bfloat16* r0 = Qs + (mt*16 + g)*AST + ks*16 + 2*q;
                const __nv_bfloat16* r1 = r0 + 8*AST;
                a[0] = *(const uint32_t*)(r0);
                a[1] = *(const uint32_t*)(r1);
                a[2] = *(const uint32_t*)(r0 + 8);
                a[3] = *(const uint32_t*)(r1 + 8);
                mma_bf16(acc[mt], a, b0, b1);
            }
        }
        __syncthreads();
    }

    // write partials: thread (g,q) holds C[g][2q],C[g][2q+1],C[g+8][2q],C[g+8][2q+1]
    float* P = g_lpart + (size_t)(((cx*2 + which)*BB + b)*NHH + h)*HDD*HDD;
    #pragma unroll
    for (int mt = 0; mt < 4; mt++) {
        float2 lo = { acc[mt][0], acc[mt][1] };
        float2 hi = { acc[mt][2], acc[mt][3] };
        *(float2*)(P + (mt*16 + g)*64 + dBase + 2*q) = lo;
        *(float2*)(P + (mt*16 + g + 8)*64 + dBase + 2*q) = hi;
    }
}

// ---------------------------------------------------------------------------
// K5: softmax over summed partials + SE-pool via A @ vmean
// ---------------------------------------------------------------------------
__global__ void attn_soft_kernel() {
    int hb = blockIdx.x;
    int which = blockIdx.y;
    int h = hb & 3, b = hb >> 2;
    int t = threadIdx.x;   // 64 threads, thread = attention row c

    __shared__ float S[64][65];
    __shared__ float rq[64], rk[64], vm[64];

    rq[t] = g_rnorm[(which*BB+b)*512 +       h*64 + t];
    rk[t] = g_rnorm[((1-which)*BB+b)*512 + 256 + h*64 + t];
    vm[t] = g_vmean[(which*BB+b)*256 + h*64 + t];

    #pragma unroll
    for (int cx = 0; cx < 4; cx++) {
        const float* P = g_lpart + (size_t)(((cx*2 + which)*BB + b)*NHH + h)*HDD*HDD;
        for (int idx = t; idx < 4096; idx += 64) {
            float v = P[idx];
            if (cx == 0) S[idx >> 6][idx & 63] = v;
            else         S[idx >> 6][idx & 63] += v;
        }
        __syncthreads();
    }

    float sc = 0.125f * rq[t];
    float m = -1e30f;
    #pragma unroll
    for (int d = 0; d < 64; d++) {
        float v = S[t][d] * sc * rk[d];
        S[t][d] = v;
        m = fmaxf(m, v);
    }
    float sum = 0.0f;
    #pragma unroll
    for (int d = 0; d < 64; d++) { float ev = expf(S[t][d] - m); S[t][d] = ev; sum += ev; }
    float inv = 1.0f / sum;

    float* ap = g_attn + (size_t)(((which*BB+b)*NHH + h)*HDD + t)*HDD;
    float pool = 0.0f;
    #pragma unroll
    for (int d = 0; d < 64; d++) {
        float a = S[t][d] * inv;
        ap[d] = a;
        pool += a * vm[d];
    }
    g_pool[(which*BB+b)*CC + h*64 + t] = pool;
}

// ---------------------------------------------------------------------------
// K6: SE gate
// ---------------------------------------------------------------------------
__global__ void se_kernel(const float* __restrict__ w1, const float* __restrict__ b1_,
                          const float* __restrict__ w2, const float* __restrict__ b2_)
{
    int b = blockIdx.x, s = blockIdx.y;
    __shared__ float pm[256], ys[32];
    int t = threadIdx.x;
    pm[t] = g_pool[(s*BB+b)*CC + t];
    __syncthreads();
    if (t < 32) {
        float a = b1_[t];
        #pragma unroll 8
        for (int c = 0; c < 256; c++) a += w1[t*256 + c]*pm[c];
        ys[t] = fmaxf(a, 0.0f);
    }
    __syncthreads();
    float a = b2_[t];
    #pragma unroll
    for (int r = 0; r < 32; r++) a += w2[t*32 + r]*ys[r];
    g_gate[(s*BB+b)*CC + t] = 1.0f/(1.0f + expf(-a));
}

// ---------------------------------------------------------------------------
// K7: M = PO * diag(gate) * A_blk
// ---------------------------------------------------------------------------
__global__ void __launch_bounds__(256) mproj_kernel(
    const float* __restrict__ pw1, const float* __restrict__ pw2)
{
    int h = blockIdx.x, b = blockIdx.y, s = blockIdx.z;
    int sb = s*BB + b;
    const float* PO = s ? pw2 : pw1;
    const float* A  = g_attn + (size_t)((sb)*NHH + h)*HDD*HDD;
    int t = threadIdx.x;

    __shared__ float Ag[64][65];
    __shared__ float gsl[64];

    if (t < 64) gsl[t] = g_gate[sb*CC + h*64 + t];
    for (int idx = t; idx < 4096; idx += 256)
        Ag[idx >> 6][idx & 63] = A[idx];
    __syncthreads();

    float m[64];
    #pragma unroll
    for (int d = 0; d < 64; d++) m[d] = 0.0f;

    const float* po = PO + (size_t)t*CC + h*64;
    for (int c = 0; c < 64; c++) {
        float poc = po[c] * gsl[c];
        #pragma unroll
        for (int d = 0; d < 64; d++) m[d] += poc * Ag[c][d];
    }

    float* Mp = g_M + (size_t)sb*CC*CC + (size_t)t*CC + h*64;
    #pragma unroll
    for (int d = 0; d < 64; d++) Mp[d] = m[d];
}

// ---------------------------------------------------------------------------
// K8: out = M @ V + bias + residual  (mma.sync tf32)
// ---------------------------------------------------------------------------
__global__ void __launch_bounds__(256, 2) mv_tc_kernel(
    const float* __restrict__ x1, const float* __restrict__ x2,
    const float* __restrict__ pb1, const float* __restrict__ pb2,
    float* __restrict__ out)
{
    __shared__ __align__(16) float sA[2][128*ASTRIDE];
    __shared__ __align__(16) float sB[2][16*BSTRIDE];

    int pBase = blockIdx.x * 128;
    int oBase = blockIdx.y * 128;
    int s = blockIdx.z >> 3, b = blockIdx.z & 7;
    int sb = s*BB + b;

    const float* Msb  = g_M + (size_t)sb*CC*CC;
    const float* pb   = s ? pb2 : pb1;
    const float* V    = g_v + (size_t)sb*CC*HWP;
    const float* res  = (s ? x2 : x1) + (size_t)b*CC*HWP;
    float*       Y    = out + ((size_t)sb)*CC*HWP;

    int t = threadIdx.x;
    int wid = t >> 5, lane = t & 31;
    int warpM = wid >> 1, warpN = wid & 1;
    int mbw = warpM*32, nbw = warpN*64;
    int g = lane >> 2, q = lane & 3;

    uint32_t sAb[2] = { smem_u32(sA[0]), smem_u32(sA[1]) };
    uint32_t sBb[2] = { smem_u32(sB[0]), smem_u32(sB[1]) };

    int ac0_r = t >> 2, ac0_q = t & 3;
    int ac1_r = (t + 256) >> 2, ac1_q = (t + 256) & 3;
    int bc0_r = t >> 5, bc0_q = t & 31;
    int bc1_r = (t + 256) >> 5, bc1_q = (t + 256) & 31;

    float acc[2][8][4] = {};

    auto stage = [&](int k0, int buf) {
        cpa16(sAb[buf] + (uint32_t)(ac0_r*ASTRIDE + ac0_q*4)*4,
              Msb + (size_t)(oBase + ac0_r)*CC + k0 + ac0_q*4);
        cpa16(sAb[buf] + (uint32_t)(ac1_r*ASTRIDE + ac1_q*4)*4,
              Msb + (size_t)(oBase + ac1_r)*CC + k0 + ac1_q*4);
        cpa16(sBb[buf] + (uint32_t)(bc0_r*BSTRIDE + bc0_q*4)*4,
              V + (size_t)(k0 + bc0_r)*HWP + pBase + bc0_q*4);
        cpa16(sBb[buf] + (uint32_t)(bc1_r*BSTRIDE + bc1_q*4)*4,
              V + (size_t)(k0 + bc1_r)*HWP + pBase + bc1_q*4);
    };

    stage(0, 0);
    CPA_COMMIT();

    const int NIT = CC / 16;
    for (int it = 0; it < NIT; it++) {
        int buf = it & 1;
        if (it + 1 < NIT) { stage((it+1)*16, buf ^ 1); CPA_COMMIT(); CPA_WAIT1(); }
        else CPA_WAIT0();
        __syncthreads();

        const float* A = sA[buf];
        const float* Bm = sB[buf];
        #pragma unroll
        for (int kk = 0; kk < 2; kk++) {
            uint32_t af[2][4];
            #pragma unroll
            for (int mt = 0; mt < 2; mt++) {
                int m = mbw + mt*16 + g;
                int k = kk*8 + q;
                af[mt][0] = tf32r(A[m*ASTRIDE + k]);
                af[mt][1] = tf32r(A[(m+8)*ASTRIDE + k]);
                af[mt][2] = tf32r(A[m*ASTRIDE + k + 4]);
                af[mt][3] = tf32r(A[(m+8)*ASTRIDE + k + 4]);
            }
            #pragma unroll
            for (int nt = 0; nt < 8; nt++) {
                int n = nbw + nt*8 + g;
                int k = kk*8 + q;
                uint32_t b0 = tf32r(Bm[k*BSTRIDE + n]);
                uint32_t b1 = tf32r(Bm[(k+4)*BSTRIDE + n]);
                mma_tf32(acc[0][nt], af[0], b0, b1);
                mma_tf32(acc[1][nt], af[1], b0, b1);
            }
        }
        __syncthreads();
    }

    #pragma unroll
    for (int mt = 0; mt < 2; mt++) {
        int o0 = oBase + mbw + mt*16 + g;
        int o1 = o0 + 8;
        float bo0 = pb[o0], bo1 = pb[o1];
        float* y0 = Y + (size_t)o0*HWP + pBase + nbw + q*2;
        float* y1 = Y + (size_t)o1*HWP + pBase + nbw + q*2;
        const float* r0 = res + (size_t)o0*HWP + pBase + nbw + q*2;
        const float* r1 = res + (size_t)o1*HWP + pBase + nbw + q*2;
        #pragma unroll
        for (int nt = 0; nt < 8; nt++) {
            float2 rv0 = *(const float2*)(r0 + nt*8);
            float2 rv1 = *(const float2*)(r1 + nt*8);
            float2 v0, v1;
            v0.x = acc[mt][nt][0] + bo0 + rv0.x;
            v0.y = acc[mt][nt][1] + bo0 + rv0.y;
            v1.x = acc[mt][nt][2] + bo1 + rv1.x;
            v1.y = acc[mt][nt][3] + bo1 + rv1.y;
            *(float2*)(y0 + nt*8) = v0;
            *(float2*)(y1 + nt*8) = v1;
        }
    }
}

// ---------------------------------------------------------------------------
extern "C" void kernel_launch(void* const* d_in, const int* in_sizes, int n_in,
                              void* d_out, int out_size)
{
    const float* x1     = (const float*)d_in[0];
    const float* x2     = (const float*)d_in[1];
    const float* ms_w3  = (const float*)d_in[2];
    const float* ms_b3  = (const float*)d_in[3];
    const float* ms_w5  = (const float*)d_in[4];
    const float* ms_b5  = (const float*)d_in[5];
    const float* ms_w7  = (const float*)d_in[6];
    const float* ms_b7  = (const float*)d_in[7];
    const float* qkv1_w = (const float*)d_in[8];
    const float* qkv1_b = (const float*)d_in[9];
    const float* bn1_g  = (const float*)d_in[10];
    const float* bn1_b  = (const float*)d_in[11];
    const float* bn1_m  = (const float*)d_in[12];
    const float* bn1_v  = (const float*)d_in[13];
    const float* qkv2_w = (const float*)d_in[14];
    const float* qkv2_b = (const float*)d_in[15];
    const float* bn2_g  = (const float*)d_in[16];
    const float* bn2_b  = (const float*)d_in[17];
    const float* bn2_m  = (const float*)d_in[18];
    const float* bn2_v  = (const float*)d_in[19];
    const float* ca_w1  = (const float*)d_in[20];
    const float* ca_b1  = (const float*)d_in[21];
    const float* ca_w2  = (const float*)d_in[22];
    const float* ca_b2  = (const float*)d_in[23];
    const float* po1_w  = (const float*)d_in[24];
    const float* po1_b  = (const float*)d_in[25];
    const float* po2_w  = (const float*)d_in[26];
    const float* po2_b  = (const float*)d_in[27];
    float* out = (float*)d_out;

    msconv_kernel<<<dim3(CC, BB, 2), 256>>>(x1, x2, ms_w3, ms_b3, ms_w5, ms_b5, ms_w7, ms_b7);
    qkv_tc_kernel<<<dim3(NPT, C3/128, 16), 256>>>(
        qkv1_w, qkv1_b, bn1_g, bn1_b, bn1_m, bn1_v,
        qkv2_w, qkv2_b, bn2_g, bn2_b, bn2_m, bn2_v);
    finalize_kernel<<<16, 512>>>();
    attn_part_kernel<<<dim3(4, NHH*BB, 2), 256>>>();
    attn_soft_kernel<<<dim3(NHH*BB, 2), 64>>>();
    se_kernel<<<dim3(BB, 2), 256>>>(ca_w1, ca_b1, ca_w2, ca_b2);
    mproj_kernel<<<dim3(NHH, BB, 2), 256>>>(po1_w, po2_w);
    mv_tc_kernel<<<dim3(HWP/128, CC/128, 16), 256>>>(x1, x2, po1_b, po2_b, out);
}

// round 6
// speedup vs baseline: 4.7137x; 1.2194x over previous
#include <cuda_runtime.h>
#include <cuda_bf16.h>
#include <math.h>
#include <cstdint>

#define BB  8
#define CC  256
#define HH  64
#define WW  64
#define HWP 4096
#define NHH 4
#define HDD 64
#define C3  768
#define NPT 32            // qkv pTile count (4096/128)

// ---- scratch (static device globals; no allocation at runtime) ----
__device__ __nv_bfloat16  g_xfh[2ULL*BB*CC*HWP];   //  33 MB  msconv out, [c][n] bf16
__device__ __nv_bfloat16  g_xfT[2ULL*BB*CC*HWP];   //  33 MB  transposed  [n][c] bf16
__device__ __nv_bfloat16  g_wqkv[2ULL*C3*CC];      //  qkv weights bf16
__device__ __nv_bfloat16  g_qk [2ULL*BB*512*HWP];  //  67 MB  gelu(bn(q,k)) bf16
__device__ float          g_v  [2ULL*BB*CC*HWP];   //  67 MB  gelu(bn(v)) fp32
__device__ float g_ss_part[NPT*16*512];            //  per-pTile sum-of-squares partials
__device__ float g_vs_part[NPT*16*256];            //  per-pTile V row-sum partials
__device__ float g_rnorm[16*512];
__device__ float g_vmean[16*256];
__device__ float g_lpart[4ULL*2*BB*NHH*HDD*HDD];   //  attn logit partials (4 chunks)
__device__ float g_attn [2*BB*NHH*HDD*HDD];
__device__ float g_pool [2*BB*CC];
__device__ float g_gate [2*BB*CC];
__device__ float g_M    [16ULL*CC*CC];             //  M = PO*diag(gate)*A_blk

// ======================= helpers =======================
__device__ __forceinline__ uint32_t smem_u32(const void* p) {
    uint32_t a;
    asm("{ .reg .u64 t; cvta.to.shared.u64 t, %1; cvt.u32.u64 %0, t; }" : "=r"(a) : "l"(p));
    return a;
}
__device__ __forceinline__ uint32_t tf32r(float x) {
    uint32_t y; asm("cvt.rna.tf32.f32 %0, %1;" : "=r"(y) : "f"(x)); return y;
}
__device__ __forceinline__ void cpa16(uint32_t dst, const void* src) {
    asm volatile("cp.async.cg.shared.global [%0], [%1], 16;" :: "r"(dst), "l"(src));
}
#define CPA_COMMIT() asm volatile("cp.async.commit_group;" ::: "memory")
#define CPA_WAIT1()  asm volatile("cp.async.wait_group 1;" ::: "memory")
#define CPA_WAIT0()  asm volatile("cp.async.wait_group 0;" ::: "memory")

__device__ __forceinline__ void mma_tf32(float* d, const uint32_t* a, uint32_t b0, uint32_t b1) {
    asm volatile(
        "mma.sync.aligned.m16n8k8.row.col.f32.tf32.tf32.f32 "
        "{%0,%1,%2,%3}, {%4,%5,%6,%7}, {%8,%9}, {%0,%1,%2,%3};"
        : "+f"(d[0]), "+f"(d[1]), "+f"(d[2]), "+f"(d[3])
        : "r"(a[0]), "r"(a[1]), "r"(a[2]), "r"(a[3]), "r"(b0), "r"(b1));
}
__device__ __forceinline__ void mma_bf16(float* d, const uint32_t* a, uint32_t b0, uint32_t b1) {
    asm volatile(
        "mma.sync.aligned.m16n8k16.row.col.f32.bf16.bf16.f32 "
        "{%0,%1,%2,%3}, {%4,%5,%6,%7}, {%8,%9}, {%0,%1,%2,%3};"
        : "+f"(d[0]), "+f"(d[1]), "+f"(d[2]), "+f"(d[3])
        : "r"(a[0]), "r"(a[1]), "r"(a[2]), "r"(a[3]), "r"(b0), "r"(b1));
}

#define ASTRIDE 20    // fp32 GEMM (mv) A stride
#define BSTRIDE 136   // fp32 GEMM (mv) B stride
#define QST 40        // bf16 qkv GEMM smem row stride (elems): 80B, conflict-free

// ---------------------------------------------------------------------------
// K0a: convert qkv weights to bf16 (tiny)
// ---------------------------------------------------------------------------
__global__ void convert_w_kernel(const float* __restrict__ w1, const float* __restrict__ w2) {
    int i = blockIdx.x * 256 + threadIdx.x;
    g_wqkv[i]         = __float2bfloat16(w1[i]);
    g_wqkv[C3*CC + i] = __float2bfloat16(w2[i]);
}

// ---------------------------------------------------------------------------
// K1: fused multiscale depthwise conv; writes bf16 [c][n]
// ---------------------------------------------------------------------------
__global__ void msconv_kernel(const float* __restrict__ x1, const float* __restrict__ x2,
                              const float* __restrict__ w3, const float* __restrict__ b3,
                              const float* __restrict__ w5, const float* __restrict__ b5,
                              const float* __restrict__ w7, const float* __restrict__ b7)
{
    int c = blockIdx.x, b = blockIdx.y, s = blockIdx.z;
    const float* xin = (s ? x2 : x1) + ((size_t)b*CC + c)*HWP;

    __shared__ float tile[70*70];
    __shared__ float wc[49];
    int t = threadIdx.x;

    if (t < 49) {
        int ky = t / 7, kx = t % 7;
        float w = w7[c*49 + t];
        if (ky >= 1 && ky <= 5 && kx >= 1 && kx <= 5) w += w5[c*25 + (ky-1)*5 + (kx-1)];
        if (ky >= 2 && ky <= 4 && kx >= 2 && kx <= 4) w += w3[c*9  + (ky-2)*3 + (kx-2)];
        wc[t] = w * (1.0f/3.0f);
    }
    for (int i = t; i < 70*70; i += 256) {
        int ty = i / 70, tx = i % 70;
        int gy = ty - 3, gx = tx - 3;
        tile[i] = (gy >= 0 && gy < HH && gx >= 0 && gx < WW) ? xin[gy*WW + gx] : 0.0f;
    }
    __syncthreads();

    int tx = t & 63;
    int ty0 = (t >> 6) * 16;
    float bias = (b3[c] + b5[c] + b7[c]) * (1.0f/3.0f);

    float acc[16];
    #pragma unroll
    for (int i = 0; i < 16; i++) acc[i] = bias;

    #pragma unroll
    for (int r = 0; r < 22; r++) {
        float v[7];
        #pragma unroll
        for (int kx = 0; kx < 7; kx++) v[kx] = tile[(ty0 + r)*70 + tx + kx];
        #pragma unroll
        for (int ky = 0; ky < 7; ky++) {
            int ro = r - ky;
            if (ro >= 0 && ro < 16) {
                #pragma unroll
                for (int kx = 0; kx < 7; kx++)
                    acc[ro] += wc[ky*7+kx] * v[kx];
            }
        }
    }

    __nv_bfloat16* outp = g_xfh + ((size_t)(s*BB+b)*CC + c)*HWP;
    #pragma unroll
    for (int i = 0; i < 16; i++)
        outp[(ty0 + i)*WW + tx] = __float2bfloat16(acc[i]);
}

// ---------------------------------------------------------------------------
// K1b: transpose xf [c][n] -> xfT [n][c]  (bf16, 64x64 tiles)
// ---------------------------------------------------------------------------
__global__ void transpose_kernel() {
    int nT = blockIdx.x * 64, cT = blockIdx.y * 64, sb = blockIdx.z;
    __shared__ __nv_bfloat16 ts[64][65];
    const __nv_bfloat16* src = g_xfh + ((size_t)sb*CC + cT)*HWP + nT;
    __nv_bfloat16*       dst = g_xfT + ((size_t)sb*HWP + nT)*CC + cT;
    int t = threadIdx.x;
    #pragma unroll
    for (int e = 0; e < 16; e++) {
        int idx = t + e*256;
        int r = idx >> 6, col = idx & 63;       // r = c-local, col = n-local
        ts[r][col] = src[(size_t)r*HWP + col];
    }
    __syncthreads();
    #pragma unroll
    for (int e = 0; e < 16; e++) {
        int idx = t + e*256;
        int r = idx >> 6, col = idx & 63;       // r = n-local, col = c-local
        dst[(size_t)r*CC + col] = ts[col][r];
    }
}

// ---------------------------------------------------------------------------
// K2: qkv GEMM on bf16 mma (m16n8k16).  M=128(o), N=128(n), K=256(c), BK=32.
//     A = W bf16 (c contig), B = xfT bf16 (c contig).  Epilogue: BN + GELU,
//     q/k out bf16, v out fp32, plus per-pTile row statistics.
// ---------------------------------------------------------------------------
__global__ void __launch_bounds__(256, 2) qkv_tc_kernel(
    const float* __restrict__ bq1,
    const float* __restrict__ g1, const float* __restrict__ be1,
    const float* __restrict__ m1, const float* __restrict__ v1,
    const float* __restrict__ bq2,
    const float* __restrict__ g2, const float* __restrict__ be2,
    const float* __restrict__ m2, const float* __restrict__ v2)
{
    __shared__ __align__(16) __nv_bfloat16 sA[2][128*QST];
    __shared__ __align__(16) __nv_bfloat16 sB[2][128*QST];
    __shared__ float sred[128][2];

    int pTile = blockIdx.x;
    int pBase = pTile * 128;
    int oBase = blockIdx.y * 128;
    int s = blockIdx.z >> 3, b = blockIdx.z & 7;
    int sb = s*BB + b;

    const __nv_bfloat16* W = g_wqkv + (size_t)s*C3*CC;
    const float* bq  = s ? bq2 : bq1;
    const float* bg  = s ? g2  : g1;
    const float* bbv = s ? be2 : be1;
    const float* bm  = s ? m2  : m1;
    const float* bv  = s ? v2  : v1;
    const __nv_bfloat16* XT = g_xfT + (size_t)sb*HWP*CC;

    int t = threadIdx.x;
    int wid = t >> 5, lane = t & 31;
    int warpM = wid >> 1, warpN = wid & 1;
    int mbw = warpM*32, nbw = warpN*64;
    int g = lane >> 2, q = lane & 3;

    uint32_t sAb[2] = { smem_u32(sA[0]), smem_u32(sA[1]) };
    uint32_t sBb[2] = { smem_u32(sB[0]), smem_u32(sB[1]) };

    // staging: 128 rows x 32 bf16 = 512 chunks of 16B each; 2/thread per matrix
    int c0_r = t >> 2, c0_g = t & 3;
    int c1_r = (t + 256) >> 2, c1_g = (t + 256) & 3;

    float acc[2][8][4] = {};

    auto stage = [&](int k0, int buf) {
        cpa16(sAb[buf] + (uint32_t)(c0_r*QST + c0_g*8)*2,
              W + (size_t)(oBase + c0_r)*CC + k0 + c0_g*8);
        cpa16(sAb[buf] + (uint32_t)(c1_r*QST + c1_g*8)*2,
              W + (size_t)(oBase + c1_r)*CC + k0 + c1_g*8);
        cpa16(sBb[buf] + (uint32_t)(c0_r*QST + c0_g*8)*2,
              XT + (size_t)(pBase + c0_r)*CC + k0 + c0_g*8);
        cpa16(sBb[buf] + (uint32_t)(c1_r*QST + c1_g*8)*2,
              XT + (size_t)(pBase + c1_r)*CC + k0 + c1_g*8);
    };

    stage(0, 0);
    CPA_COMMIT();

    const int NIT = CC / 32;
    for (int it = 0; it < NIT; it++) {
        int buf = it & 1;
        if (it + 1 < NIT) { stage((it+1)*32, buf ^ 1); CPA_COMMIT(); CPA_WAIT1(); }
        else CPA_WAIT0();
        __syncthreads();

        const __nv_bfloat16* A = sA[buf];
        const __nv_bfloat16* Bm = sB[buf];
        #pragma unroll
        for (int ks = 0; ks < 2; ks++) {
            uint32_t af[2][4];
            #pragma unroll
            for (int mt = 0; mt < 2; mt++) {
                const __nv_bfloat16* r0 = A + (mbw + mt*16 + g)*QST + ks*16 + 2*q;
                const __nv_bfloat16* r1 = r0 + 8*QST;
                af[mt][0] = *(const uint32_t*)(r0);
                af[mt][1] = *(const uint32_t*)(r1);
                af[mt][2] = *(const uint32_t*)(r0 + 8);
                af[mt][3] = *(const uint32_t*)(r1 + 8);
            }
            #pragma unroll
            for (int nt = 0; nt < 8; nt++) {
                const __nv_bfloat16* br = Bm + (nbw + nt*8 + g)*QST + ks*16 + 2*q;
                uint32_t b0 = *(const uint32_t*)(br);
                uint32_t b1 = *(const uint32_t*)(br + 8);
                mma_bf16(acc[0][nt], af[0], b0, b1);
                mma_bf16(acc[1][nt], af[1], b0, b1);
            }
        }
        __syncthreads();
    }

    bool isV = (oBase >= 512);
    float rs[2][2] = {};

    #pragma unroll
    for (int mt = 0; mt < 2; mt++) {
        int o0 = oBase + mbw + mt*16 + g;
        int o1 = o0 + 8;
        float scl0 = bg[o0] * rsqrtf(bv[o0] + 1e-5f);
        float sft0 = bbv[o0] - bm[o0]*scl0 + bq[o0]*scl0;
        float scl1 = bg[o1] * rsqrtf(bv[o1] + 1e-5f);
        float sft1 = bbv[o1] - bm[o1]*scl1 + bq[o1]*scl1;

        float* yv0 = g_v + ((size_t)sb*CC + (o0 - 512))*HWP + pBase + nbw + q*2;
        float* yv1 = g_v + ((size_t)sb*CC + (o1 - 512))*HWP + pBase + nbw + q*2;
        __nv_bfloat16* yq0 = g_qk + ((size_t)sb*512 + o0)*HWP + pBase + nbw + q*2;
        __nv_bfloat16* yq1 = g_qk + ((size_t)sb*512 + o1)*HWP + pBase + nbw + q*2;

        #pragma unroll
        for (int nt = 0; nt < 8; nt++) {
            float2 v0, v1;
            v0.x = acc[mt][nt][0]*scl0 + sft0;
            v0.y = acc[mt][nt][1]*scl0 + sft0;
            v1.x = acc[mt][nt][2]*scl1 + sft1;
            v1.y = acc[mt][nt][3]*scl1 + sft1;
            v0.x = 0.5f*v0.x*(1.0f + erff(v0.x*0.70710678118654752f));
            v0.y = 0.5f*v0.y*(1.0f + erff(v0.y*0.70710678118654752f));
            v1.x = 0.5f*v1.x*(1.0f + erff(v1.x*0.70710678118654752f));
            v1.y = 0.5f*v1.y*(1.0f + erff(v1.y*0.70710678118654752f));
            if (isV) {
                *(float2*)(yv0 + nt*8) = v0;
                *(float2*)(yv1 + nt*8) = v1;
                rs[mt][0] += v0.x + v0.y;
                rs[mt][1] += v1.x + v1.y;
            } else {
                *(__nv_bfloat162*)(yq0 + nt*8) = __float22bfloat162_rn(v0);
                *(__nv_bfloat162*)(yq1 + nt*8) = __float22bfloat162_rn(v1);
                rs[mt][0] += v0.x*v0.x + v0.y*v0.y;
                rs[mt][1] += v1.x*v1.x + v1.y*v1.y;
            }
        }
    }

    #pragma unroll
    for (int mt = 0; mt < 2; mt++)
        #pragma unroll
        for (int rr = 0; rr < 2; rr++) {
            float v = rs[mt][rr];
            v += __shfl_xor_sync(0xffffffffu, v, 1);
            v += __shfl_xor_sync(0xffffffffu, v, 2);
            if (q == 0) sred[mbw + mt*16 + g + rr*8][warpN] = v;
        }
    __syncthreads();
    if (t < 128) {
        float tot = sred[t][0] + sred[t][1];
        if (isV) g_vs_part[((size_t)pTile*16 + sb)*256 + (oBase - 512 + t)] = tot;
        else     g_ss_part[((size_t)pTile*16 + sb)*512 + (oBase + t)] = tot;
    }
}

// ---------------------------------------------------------------------------
// K3: finalize rnorm and vmean from partials
// ---------------------------------------------------------------------------
__global__ void finalize_kernel() {
    int sb = blockIdx.x;
    int t = threadIdx.x;
    float ss = 0.0f;
    for (int p = 0; p < NPT; p++) ss += g_ss_part[((size_t)p*16 + sb)*512 + t];
    g_rnorm[sb*512 + t] = 1.0f / fmaxf(sqrtf(ss), 1e-12f);
    if (t < 256) {
        float vs = 0.0f;
        for (int p = 0; p < NPT; p++) vs += g_vs_part[((size_t)p*16 + sb)*256 + t];
        g_vmean[sb*256 + t] = vs * (1.0f/HWP);
    }
}

// ---------------------------------------------------------------------------
// K4: attention logit partials via bf16 mma
// ---------------------------------------------------------------------------
#define ANC 128
#define AST (ANC + 8)

__global__ void __launch_bounds__(256) attn_part_kernel() {
    int cx = blockIdx.x;
    int hb = blockIdx.y;
    int which = blockIdx.z;
    int h = hb & 3, b = hb >> 2;
    const __nv_bfloat16* Q = g_qk + ((size_t)(which*BB+b)*512 +       h*HDD)*HWP;
    const __nv_bfloat16* K = g_qk + ((size_t)((1-which)*BB+b)*512 + 256 + h*HDD)*HWP;

    __shared__ __align__(16) __nv_bfloat16 sQ[2][64*AST];
    __shared__ __align__(16) __nv_bfloat16 sK[2][64*AST];

    int t = threadIdx.x;
    int wid = t >> 5, lane = t & 31;
    int g = lane >> 2, q = lane & 3;
    int dBase = wid * 8;

    uint32_t sQb[2] = { smem_u32(sQ[0]), smem_u32(sQ[1]) };
    uint32_t sKb[2] = { smem_u32(sK[0]), smem_u32(sK[1]) };

    auto stage = [&](int n0, int buf) {
        #pragma unroll
        for (int e = 0; e < 4; e++) {
            int c = t + e*256;
            int row = c >> 4, grp = c & 15;
            cpa16(sQb[buf] + (uint32_t)(row*AST + grp*8)*2, Q + (size_t)row*HWP + n0 + grp*8);
            cpa16(sKb[buf] + (uint32_t)(row*AST + grp*8)*2, K + (size_t)row*HWP + n0 + grp*8);
        }
    };

    float acc[4][4] = {};
    int n0base = cx * 1024;

    stage(n0base, 0);
    CPA_COMMIT();

    for (int st = 0; st < 8; st++) {
        int buf = st & 1;
        if (st + 1 < 8) { stage(n0base + (st+1)*ANC, buf ^ 1); CPA_COMMIT(); CPA_WAIT1(); }
        else CPA_WAIT0();
        __syncthreads();

        const __nv_bfloat16* Qs = sQ[buf];
        const __nv_bfloat16* Ks = sK[buf];
        #pragma unroll
        for (int ks = 0; ks < 8; ks++) {
            uint32_t b0 = *(const uint32_t*)(Ks + (dBase + g)*AST + ks*16 + 2*q);
            uint32_t b1 = *(const uint32_t*)(Ks + (dBase + g)*AST + ks*16 + 2*q + 8);
            #pragma unroll
            for (int mt = 0; mt < 4; mt++) {
                uint32_t a[4];
                const __nv_bfloat16* r0 = Qs + (mt*16 + g)*AST + ks*16 + 2*q;
                const __nv_bfloat16* r1 = r0 + 8*AST;
                a[0] = *(const uint32_t*)(r0);
                a[1] = *(const uint32_t*)(r1);
                a[2] = *(const uint32_t*)(r0 + 8);
                a[3] = *(const uint32_t*)(r1 + 8);
                mma_bf16(acc[mt], a, b0, b1);
            }
        }
        __syncthreads();
    }

    float* P = g_lpart + (size_t)(((cx*2 + which)*BB + b)*NHH + h)*HDD*HDD;
    #pragma unroll
    for (int mt = 0; mt < 4; mt++) {
        float2 lo = { acc[mt][0], acc[mt][1] };
        float2 hi = { acc[mt][2], acc[mt][3] };
        *(float2*)(P + (mt*16 + g)*64 + dBase + 2*q) = lo;
        *(float2*)(P + (mt*16 + g + 8)*64 + dBase + 2*q) = hi;
    }
}

// ---------------------------------------------------------------------------
// K5: softmax over summed partials + SE-pool via A @ vmean
// ---------------------------------------------------------------------------
__global__ void attn_soft_kernel() {
    int hb = blockIdx.x;
    int which = blockIdx.y;
    int h = hb & 3, b = hb >> 2;
    int t = threadIdx.x;

    __shared__ float S[64][65];
    __shared__ float rq[64], rk[64], vm[64];

    rq[t] = g_rnorm[(which*BB+b)*512 +       h*64 + t];
    rk[t] = g_rnorm[((1-which)*BB+b)*512 + 256 + h*64 + t];
    vm[t] = g_vmean[(which*BB+b)*256 + h*64 + t];

    #pragma unroll
    for (int cx = 0; cx < 4; cx++) {
        const float* P = g_lpart + (size_t)(((cx*2 + which)*BB + b)*NHH + h)*HDD*HDD;
        for (int idx = t; idx < 4096; idx += 64) {
            float v = P[idx];
            if (cx == 0) S[idx >> 6][idx & 63] = v;
            else         S[idx >> 6][idx & 63] += v;
        }
        __syncthreads();
    }

    float sc = 0.125f * rq[t];
    float m = -1e30f;
    #pragma unroll
    for (int d = 0; d < 64; d++) {
        float v = S[t][d] * sc * rk[d];
        S[t][d] = v;
        m = fmaxf(m, v);
    }
    float sum = 0.0f;
    #pragma unroll
    for (int d = 0; d < 64; d++) { float ev = expf(S[t][d] - m); S[t][d] = ev; sum += ev; }
    float inv = 1.0f / sum;

    float* ap = g_attn + (size_t)(((which*BB+b)*NHH + h)*HDD + t)*HDD;
    float pool = 0.0f;
    #pragma unroll
    for (int d = 0; d < 64; d++) {
        float a = S[t][d] * inv;
        ap[d] = a;
        pool += a * vm[d];
    }
    g_pool[(which*BB+b)*CC + h*64 + t] = pool;
}

// ---------------------------------------------------------------------------
// K6: SE gate
// ---------------------------------------------------------------------------
__global__ void se_kernel(const float* __restrict__ w1, const float* __restrict__ b1_,
                          const float* __restrict__ w2, const float* __restrict__ b2_)
{
    int b = blockIdx.x, s = blockIdx.y;
    __shared__ float pm[256], ys[32];
    int t = threadIdx.x;
    pm[t] = g_pool[(s*BB+b)*CC + t];
    __syncthreads();
    if (t < 32) {
        float a = b1_[t];
        #pragma unroll 8
        for (int c = 0; c < 256; c++) a += w1[t*256 + c]*pm[c];
        ys[t] = fmaxf(a, 0.0f);
    }
    __syncthreads();
    float a = b2_[t];
    #pragma unroll
    for (int r = 0; r < 32; r++) a += w2[t*32 + r]*ys[r];
    g_gate[(s*BB+b)*CC + t] = 1.0f/(1.0f + expf(-a));
}

// ---------------------------------------------------------------------------
// K7: M = PO * diag(gate) * A_blk
// ---------------------------------------------------------------------------
__global__ void __launch_bounds__(256) mproj_kernel(
    const float* __restrict__ pw1, const float* __restrict__ pw2)
{
    int h = blockIdx.x, b = blockIdx.y, s = blockIdx.z;
    int sb = s*BB + b;
    const float* PO = s ? pw2 : pw1;
    const float* A  = g_attn + (size_t)((sb)*NHH + h)*HDD*HDD;
    int t = threadIdx.x;

    __shared__ float Ag[64][65];
    __shared__ float gsl[64];

    if (t < 64) gsl[t] = g_gate[sb*CC + h*64 + t];
    for (int idx = t; idx < 4096; idx += 256)
        Ag[idx >> 6][idx & 63] = A[idx];
    __syncthreads();

    float m[64];
    #pragma unroll
    for (int d = 0; d < 64; d++) m[d] = 0.0f;

    const float* po = PO + (size_t)t*CC + h*64;
    for (int c = 0; c < 64; c++) {
        float poc = po[c] * gsl[c];
        #pragma unroll
        for (int d = 0; d < 64; d++) m[d] += poc * Ag[c][d];
    }

    float* Mp = g_M + (size_t)sb*CC*CC + (size_t)t*CC + h*64;
    #pragma unroll
    for (int d = 0; d < 64; d++) Mp[d] = m[d];
}

// ---------------------------------------------------------------------------
// K8: out = M @ V + bias + residual  (mma.sync tf32)
// ---------------------------------------------------------------------------
__global__ void __launch_bounds__(256, 2) mv_tc_kernel(
    const float* __restrict__ x1, const float* __restrict__ x2,
    const float* __restrict__ pb1, const float* __restrict__ pb2,
    float* __restrict__ out)
{
    __shared__ __align__(16) float sA[2][128*ASTRIDE];
    __shared__ __align__(16) float sB[2][16*BSTRIDE];

    int pBase = blockIdx.x * 128;
    int oBase = blockIdx.y * 128;
    int s = blockIdx.z >> 3, b = blockIdx.z & 7;
    int sb = s*BB + b;

    const float* Msb  = g_M + (size_t)sb*CC*CC;
    const float* pb   = s ? pb2 : pb1;
    const float* V    = g_v + (size_t)sb*CC*HWP;
    const float* res  = (s ? x2 : x1) + (size_t)b*CC*HWP;
    float*       Y    = out + ((size_t)sb)*CC*HWP;

    int t = threadIdx.x;
    int wid = t >> 5, lane = t & 31;
    int warpM = wid >> 1, warpN = wid & 1;
    int mbw = warpM*32, nbw = warpN*64;
    int g = lane >> 2, q = lane & 3;

    uint32_t sAb[2] = { smem_u32(sA[0]), smem_u32(sA[1]) };
    uint32_t sBb[2] = { smem_u32(sB[0]), smem_u32(sB[1]) };

    int ac0_r = t >> 2, ac0_q = t & 3;
    int ac1_r = (t + 256) >> 2, ac1_q = (t + 256) & 3;
    int bc0_r = t >> 5, bc0_q = t & 31;
    int bc1_r = (t + 256) >> 5, bc1_q = (t + 256) & 31;

    float acc[2][8][4] = {};

    auto stage = [&](int k0, int buf) {
        cpa16(sAb[buf] + (uint32_t)(ac0_r*ASTRIDE + ac0_q*4)*4,
              Msb + (size_t)(oBase + ac0_r)*CC + k0 + ac0_q*4);
        cpa16(sAb[buf] + (uint32_t)(ac1_r*ASTRIDE + ac1_q*4)*4,
              Msb + (size_t)(oBase + ac1_r)*CC + k0 + ac1_q*4);
        cpa16(sBb[buf] + (uint32_t)(bc0_r*BSTRIDE + bc0_q*4)*4,
              V + (size_t)(k0 + bc0_r)*HWP + pBase + bc0_q*4);
        cpa16(sBb[buf] + (uint32_t)(bc1_r*BSTRIDE + bc1_q*4)*4,
              V + (size_t)(k0 + bc1_r)*HWP + pBase + bc1_q*4);
    };

    stage(0, 0);
    CPA_COMMIT();

    const int NIT = CC / 16;
    for (int it = 0; it < NIT; it++) {
        int buf = it & 1;
        if (it + 1 < NIT) { stage((it+1)*16, buf ^ 1); CPA_COMMIT(); CPA_WAIT1(); }
        else CPA_WAIT0();
        __syncthreads();

        const float* A = sA[buf];
        const float* Bm = sB[buf];
        #pragma unroll
        for (int kk = 0; kk < 2; kk++) {
            uint32_t af[2][4];
            #pragma unroll
            for (int mt = 0; mt < 2; mt++) {
                int m = mbw + mt*16 + g;
                int k = kk*8 + q;
                af[mt][0] = tf32r(A[m*ASTRIDE + k]);
                af[mt][1] = tf32r(A[(m+8)*ASTRIDE + k]);
                af[mt][2] = tf32r(A[m*ASTRIDE + k + 4]);
                af[mt][3] = tf32r(A[(m+8)*ASTRIDE + k + 4]);
            }
            #pragma unroll
            for (int nt = 0; nt < 8; nt++) {
                int n = nbw + nt*8 + g;
                int k = kk*8 + q;
                uint32_t b0 = tf32r(Bm[k*BSTRIDE + n]);
                uint32_t b1 = tf32r(Bm[(k+4)*BSTRIDE + n]);
                mma_tf32(acc[0][nt], af[0], b0, b1);
                mma_tf32(acc[1][nt], af[1], b0, b1);
            }
        }
        __syncthreads();
    }

    #pragma unroll
    for (int mt = 0; mt < 2; mt++) {
        int o0 = oBase + mbw + mt*16 + g;
        int o1 = o0 + 8;
        float bo0 = pb[o0], bo1 = pb[o1];
        float* y0 = Y + (size_t)o0*HWP + pBase + nbw + q*2;
        float* y1 = Y + (size_t)o1*HWP + pBase + nbw + q*2;
        const float* r0 = res + (size_t)o0*HWP + pBase + nbw + q*2;
        const float* r1 = res + (size_t)o1*HWP + pBase + nbw + q*2;
        #pragma unroll
        for (int nt = 0; nt < 8; nt++) {
            float2 rv0 = *(const float2*)(r0 + nt*8);
            float2 rv1 = *(const float2*)(r1 + nt*8);
            float2 v0, v1;
            v0.x = acc[mt][nt][0] + bo0 + rv0.x;
            v0.y = acc[mt][nt][1] + bo0 + rv0.y;
            v1.x = acc[mt][nt][2] + bo1 + rv1.x;
            v1.y = acc[mt][nt][3] + bo1 + rv1.y;
            *(float2*)(y0 + nt*8) = v0;
            *(float2*)(y1 + nt*8) = v1;
        }
    }
}

// ---------------------------------------------------------------------------
extern "C" void kernel_launch(void* const* d_in, const int* in_sizes, int n_in,
                              void* d_out, int out_size)
{
    const float* x1     = (const float*)d_in[0];
    const float* x2     = (const float*)d_in[1];
    const float* ms_w3  = (const float*)d_in[2];
    const float* ms_b3  = (const float*)d_in[3];
    const float* ms_w5  = (const float*)d_in[4];
    const float* ms_b5  = (const float*)d_in[5];
    const float* ms_w7  = (const float*)d_in[6];
    const float* ms_b7  = (const float*)d_in[7];
    const float* qkv1_w = (const float*)d_in[8];
    const float* qkv1_b = (const float*)d_in[9];
    const float* bn1_g  = (const float*)d_in[10];
    const float* bn1_b  = (const float*)d_in[11];
    const float* bn1_m  = (const float*)d_in[12];
    const float* bn1_v  = (const float*)d_in[13];
    const float* qkv2_w = (const float*)d_in[14];
    const float* qkv2_b = (const float*)d_in[15];
    const float* bn2_g  = (const float*)d_in[16];
    const float* bn2_b  = (const float*)d_in[17];
    const float* bn2_m  = (const float*)d_in[18];
    const float* bn2_v  = (const float*)d_in[19];
    const float* ca_w1  = (const float*)d_in[20];
    const float* ca_b1  = (const float*)d_in[21];
    const float* ca_w2  = (const float*)d_in[22];
    const float* ca_b2  = (const float*)d_in[23];
    const float* po1_w  = (const float*)d_in[24];
    const float* po1_b  = (const float*)d_in[25];
    const float* po2_w  = (const float*)d_in[26];
    const float* po2_b  = (const float*)d_in[27];
    float* out = (float*)d_out;

    convert_w_kernel<<<C3*CC/256, 256>>>(qkv1_w, qkv2_w);
    msconv_kernel<<<dim3(CC, BB, 2), 256>>>(x1, x2, ms_w3, ms_b3, ms_w5, ms_b5, ms_w7, ms_b7);
    transpose_kernel<<<dim3(HWP/64, CC/64, 16), 256>>>();
    qkv_tc_kernel<<<dim3(NPT, C3/128, 16), 256>>>(
        qkv1_b, bn1_g, bn1_b, bn1_m, bn1_v,
        qkv2_b, bn2_g, bn2_b, bn2_m, bn2_v);
    finalize_kernel<<<16, 512>>>();
    attn_part_kernel<<<dim3(4, NHH*BB, 2), 256>>>();
    attn_soft_kernel<<<dim3(NHH*BB, 2), 64>>>();
    se_kernel<<<dim3(BB, 2), 256>>>(ca_w1, ca_b1, ca_w2, ca_b2);
    mproj_kernel<<<dim3(NHH, BB, 2), 256>>>(po1_w, po2_w);
    mv_tc_kernel<<<dim3(HWP/128, CC/128, 16), 256>>>(x1, x2, po1_b, po2_b, out);
}

// round 7
// speedup vs baseline: 4.8016x; 1.0186x over previous
#include <cuda_runtime.h>
#include <cuda_bf16.h>
#include <math.h>
#include <cstdint>

#define BB  8
#define CC  256
#define HH  64
#define WW  64
#define HWP 4096
#define NHH 4
#define HDD 64
#define C3  768
#define NPT 32            // qkv pTile count (4096/128)

// ---- scratch (static device globals; no allocation at runtime) ----
__device__ __nv_bfloat16  g_xfh[2ULL*BB*CC*HWP];   //  33 MB  msconv out, [c][n] bf16
__device__ __nv_bfloat16  g_xfT[2ULL*BB*CC*HWP];   //  33 MB  transposed  [n][c] bf16
__device__ __nv_bfloat16  g_wqkv[2ULL*C3*CC];      //  qkv weights bf16
__device__ __nv_bfloat16  g_qk [2ULL*BB*512*HWP];  //  67 MB  gelu(bn(q,k)) bf16
__device__ float          g_v  [2ULL*BB*CC*HWP];   //  67 MB  gelu(bn(v)) fp32
__device__ float g_ss_part[NPT*16*512];            //  per-pTile sum-of-squares partials
__device__ float g_vs_part[NPT*16*256];            //  per-pTile V row-sum partials
__device__ float g_rnorm[16*512];
__device__ float g_vmean[16*256];
__device__ float g_lpart[4ULL*2*BB*NHH*HDD*HDD];   //  attn logit partials (4 chunks)
__device__ float g_attn [2*BB*NHH*HDD*HDD];
__device__ float g_pool [2*BB*CC];
__device__ float g_gate [2*BB*CC];
__device__ float g_M    [16ULL*CC*CC];             //  M = PO*diag(gate)*A_blk

// ======================= helpers =======================
__device__ __forceinline__ uint32_t smem_u32(const void* p) {
    uint32_t a;
    asm("{ .reg .u64 t; cvta.to.shared.u64 t, %1; cvt.u32.u64 %0, t; }" : "=r"(a) : "l"(p));
    return a;
}
__device__ __forceinline__ uint32_t tf32r(float x) {
    uint32_t y; asm("cvt.rna.tf32.f32 %0, %1;" : "=r"(y) : "f"(x)); return y;
}
__device__ __forceinline__ void cpa16(uint32_t dst, const void* src) {
    asm volatile("cp.async.cg.shared.global [%0], [%1], 16;" :: "r"(dst), "l"(src));
}
#define CPA_COMMIT() asm volatile("cp.async.commit_group;" ::: "memory")
#define CPA_WAIT1()  asm volatile("cp.async.wait_group 1;" ::: "memory")
#define CPA_WAIT0()  asm volatile("cp.async.wait_group 0;" ::: "memory")

__device__ __forceinline__ void mma_tf32(float* d, const uint32_t* a, uint32_t b0, uint32_t b1) {
    asm volatile(
        "mma.sync.aligned.m16n8k8.row.col.f32.tf32.tf32.f32 "
        "{%0,%1,%2,%3}, {%4,%5,%6,%7}, {%8,%9}, {%0,%1,%2,%3};"
        : "+f"(d[0]), "+f"(d[1]), "+f"(d[2]), "+f"(d[3])
        : "r"(a[0]), "r"(a[1]), "r"(a[2]), "r"(a[3]), "r"(b0), "r"(b1));
}
__device__ __forceinline__ void mma_bf16(float* d, const uint32_t* a, uint32_t b0, uint32_t b1) {
    asm volatile(
        "mma.sync.aligned.m16n8k16.row.col.f32.bf16.bf16.f32 "
        "{%0,%1,%2,%3}, {%4,%5,%6,%7}, {%8,%9}, {%0,%1,%2,%3};"
        : "+f"(d[0]), "+f"(d[1]), "+f"(d[2]), "+f"(d[3])
        : "r"(a[0]), "r"(a[1]), "r"(a[2]), "r"(a[3]), "r"(b0), "r"(b1));
}
__device__ __forceinline__ void ldsm_x4(uint32_t addr, uint32_t& r0, uint32_t& r1,
                                        uint32_t& r2, uint32_t& r3) {
    asm volatile("ldmatrix.sync.aligned.m8n8.x4.shared.b16 {%0,%1,%2,%3}, [%4];"
                 : "=r"(r0), "=r"(r1), "=r"(r2), "=r"(r3) : "r"(addr));
}

#define ASTRIDE 20    // fp32 GEMM (mv) A stride
#define BSTRIDE 136   // fp32 GEMM (mv) B stride
#define QST 40        // bf16 qkv GEMM smem row stride (elems): 80B, ldmatrix conflict-free

// ---------------------------------------------------------------------------
// K0a: convert qkv weights to bf16 (tiny)
// ---------------------------------------------------------------------------
__global__ void convert_w_kernel(const float* __restrict__ w1, const float* __restrict__ w2) {
    int i = blockIdx.x * 256 + threadIdx.x;
    g_wqkv[i]         = __float2bfloat16(w1[i]);
    g_wqkv[C3*CC + i] = __float2bfloat16(w2[i]);
}

// ---------------------------------------------------------------------------
// K1: fused multiscale depthwise conv; writes bf16 [c][n]
// ---------------------------------------------------------------------------
__global__ void msconv_kernel(const float* __restrict__ x1, const float* __restrict__ x2,
                              const float* __restrict__ w3, const float* __restrict__ b3,
                              const float* __restrict__ w5, const float* __restrict__ b5,
                              const float* __restrict__ w7, const float* __restrict__ b7)
{
    int c = blockIdx.x, b = blockIdx.y, s = blockIdx.z;
    const float* xin = (s ? x2 : x1) + ((size_t)b*CC + c)*HWP;

    __shared__ float tile[70*70];
    __shared__ float wc[49];
    int t = threadIdx.x;

    if (t < 49) {
        int ky = t / 7, kx = t % 7;
        float w = w7[c*49 + t];
        if (ky >= 1 && ky <= 5 && kx >= 1 && kx <= 5) w += w5[c*25 + (ky-1)*5 + (kx-1)];
        if (ky >= 2 && ky <= 4 && kx >= 2 && kx <= 4) w += w3[c*9  + (ky-2)*3 + (kx-2)];
        wc[t] = w * (1.0f/3.0f);
    }
    for (int i = t; i < 70*70; i += 256) {
        int ty = i / 70, tx = i % 70;
        int gy = ty - 3, gx = tx - 3;
        tile[i] = (gy >= 0 && gy < HH && gx >= 0 && gx < WW) ? xin[gy*WW + gx] : 0.0f;
    }
    __syncthreads();

    int tx = t & 63;
    int ty0 = (t >> 6) * 16;
    float bias = (b3[c] + b5[c] + b7[c]) * (1.0f/3.0f);

    float acc[16];
    #pragma unroll
    for (int i = 0; i < 16; i++) acc[i] = bias;

    #pragma unroll
    for (int r = 0; r < 22; r++) {
        float v[7];
        #pragma unroll
        for (int kx = 0; kx < 7; kx++) v[kx] = tile[(ty0 + r)*70 + tx + kx];
        #pragma unroll
        for (int ky = 0; ky < 7; ky++) {
            int ro = r - ky;
            if (ro >= 0 && ro < 16) {
                #pragma unroll
                for (int kx = 0; kx < 7; kx++)
                    acc[ro] += wc[ky*7+kx] * v[kx];
            }
        }
    }

    __nv_bfloat16* outp = g_xfh + ((size_t)(s*BB+b)*CC + c)*HWP;
    #pragma unroll
    for (int i = 0; i < 16; i++)
        outp[(ty0 + i)*WW + tx] = __float2bfloat16(acc[i]);
}

// ---------------------------------------------------------------------------
// K1b: transpose xf [c][n] -> xfT [n][c]  (bf16, 64x64 tiles)
// ---------------------------------------------------------------------------
__global__ void transpose_kernel() {
    int nT = blockIdx.x * 64, cT = blockIdx.y * 64, sb = blockIdx.z;
    __shared__ __nv_bfloat16 ts[64][65];
    const __nv_bfloat16* src = g_xfh + ((size_t)sb*CC + cT)*HWP + nT;
    __nv_bfloat16*       dst = g_xfT + ((size_t)sb*HWP + nT)*CC + cT;
    int t = threadIdx.x;
    #pragma unroll
    for (int e = 0; e < 16; e++) {
        int idx = t + e*256;
        int r = idx >> 6, col = idx & 63;
        ts[r][col] = src[(size_t)r*HWP + col];
    }
    __syncthreads();
    #pragma unroll
    for (int e = 0; e < 16; e++) {
        int idx = t + e*256;
        int r = idx >> 6, col = idx & 63;
        dst[(size_t)r*CC + col] = ts[col][r];
    }
}

// ---------------------------------------------------------------------------
// K2: qkv GEMM on bf16 mma (m16n8k16) with ldmatrix fragment loads.
//     M=128(o), N=128(n), K=256(c), BK=32.  Epilogue: BN + GELU,
//     q/k out bf16, v out fp32, plus per-pTile row statistics.
// ---------------------------------------------------------------------------
__global__ void __launch_bounds__(256, 2) qkv_tc_kernel(
    const float* __restrict__ bq1,
    const float* __restrict__ g1, const float* __restrict__ be1,
    const float* __restrict__ m1, const float* __restrict__ v1,
    const float* __restrict__ bq2,
    const float* __restrict__ g2, const float* __restrict__ be2,
    const float* __restrict__ m2, const float* __restrict__ v2)
{
    __shared__ __align__(16) __nv_bfloat16 sA[2][128*QST];
    __shared__ __align__(16) __nv_bfloat16 sB[2][128*QST];
    __shared__ float sred[128][2];

    int pTile = blockIdx.x;
    int pBase = pTile * 128;
    int oBase = blockIdx.y * 128;
    int s = blockIdx.z >> 3, b = blockIdx.z & 7;
    int sb = s*BB + b;

    const __nv_bfloat16* W = g_wqkv + (size_t)s*C3*CC;
    const float* bq  = s ? bq2 : bq1;
    const float* bg  = s ? g2  : g1;
    const float* bbv = s ? be2 : be1;
    const float* bm  = s ? m2  : m1;
    const float* bv  = s ? v2  : v1;
    const __nv_bfloat16* XT = g_xfT + (size_t)sb*HWP*CC;

    int t = threadIdx.x;
    int wid = t >> 5, lane = t & 31;
    int warpM = wid >> 1, warpN = wid & 1;
    int mbw = warpM*32, nbw = warpN*64;
    int g = lane >> 2, q = lane & 3;

    uint32_t sAb[2] = { smem_u32(sA[0]), smem_u32(sA[1]) };
    uint32_t sBb[2] = { smem_u32(sB[0]), smem_u32(sB[1]) };

    // ldmatrix per-thread address offsets (bytes)
    int lrow = lane & 7, lmat = lane >> 3;
    // A x4: mat0 m+0..7@k, mat1 m+8..15@k, mat2 m@k+8, mat3 m+8@k+8
    uint32_t aoff = (uint32_t)((mbw + (lmat & 1)*8 + lrow)*QST + (lmat >> 1)*8) * 2;
    // B x4 (per 16-row n pair): mat0 n@k, mat1 n@k+8, mat2 n+8@k, mat3 n+8@k+8
    uint32_t boff = (uint32_t)((nbw + (lmat >> 1)*8 + lrow)*QST + (lmat & 1)*8) * 2;

    // staging: 128 rows x 32 bf16 = 512 chunks of 16B each; 2/thread per matrix
    int c0_r = t >> 2, c0_g = t & 3;
    int c1_r = (t + 256) >> 2, c1_g = (t + 256) & 3;

    float acc[2][8][4] = {};

    auto stage = [&](int k0, int buf) {
        cpa16(sAb[buf] + (uint32_t)(c0_r*QST + c0_g*8)*2,
              W + (size_t)(oBase + c0_r)*CC + k0 + c0_g*8);
        cpa16(sAb[buf] + (uint32_t)(c1_r*QST + c1_g*8)*2,
              W + (size_t)(oBase + c1_r)*CC + k0 + c1_g*8);
        cpa16(sBb[buf] + (uint32_t)(c0_r*QST + c0_g*8)*2,
              XT + (size_t)(pBase + c0_r)*CC + k0 + c0_g*8);
        cpa16(sBb[buf] + (uint32_t)(c1_r*QST + c1_g*8)*2,
              XT + (size_t)(pBase + c1_r)*CC + k0 + c1_g*8);
    };

    stage(0, 0);
    CPA_COMMIT();

    const int NIT = CC / 32;
    for (int it = 0; it < NIT; it++) {
        int buf = it & 1;
        if (it + 1 < NIT) { stage((it+1)*32, buf ^ 1); CPA_COMMIT(); CPA_WAIT1(); }
        else CPA_WAIT0();
        __syncthreads();

        uint32_t Ab = sAb[buf], Bb = sBb[buf];
        #pragma unroll
        for (int ks = 0; ks < 2; ks++) {
            uint32_t af[2][4];
            ldsm_x4(Ab + aoff + ks*32,        af[0][0], af[0][1], af[0][2], af[0][3]);
            ldsm_x4(Ab + aoff + 1280 + ks*32, af[1][0], af[1][1], af[1][2], af[1][3]);
            #pragma unroll
            for (int p = 0; p < 4; p++) {
                uint32_t r0, r1, r2, r3;
                ldsm_x4(Bb + boff + p*1280 + ks*32, r0, r1, r2, r3);
                mma_bf16(acc[0][2*p],   af[0], r0, r1);
                mma_bf16(acc[0][2*p+1], af[0], r2, r3);
                mma_bf16(acc[1][2*p],   af[1], r0, r1);
                mma_bf16(acc[1][2*p+1], af[1], r2, r3);
            }
        }
        __syncthreads();
    }

    bool isV = (oBase >= 512);
    float rs[2][2] = {};

    #pragma unroll
    for (int mt = 0; mt < 2; mt++) {
        int o0 = oBase + mbw + mt*16 + g;
        int o1 = o0 + 8;
        float scl0 = bg[o0] * rsqrtf(bv[o0] + 1e-5f);
        float sft0 = bbv[o0] - bm[o0]*scl0 + bq[o0]*scl0;
        float scl1 = bg[o1] * rsqrtf(bv[o1] + 1e-5f);
        float sft1 = bbv[o1] - bm[o1]*scl1 + bq[o1]*scl1;

        float* yv0 = g_v + ((size_t)sb*CC + (o0 - 512))*HWP + pBase + nbw + q*2;
        float* yv1 = g_v + ((size_t)sb*CC + (o1 - 512))*HWP + pBase + nbw + q*2;
        __nv_bfloat16* yq0 = g_qk + ((size_t)sb*512 + o0)*HWP + pBase + nbw + q*2;
        __nv_bfloat16* yq1 = g_qk + ((size_t)sb*512 + o1)*HWP + pBase + nbw + q*2;

        #pragma unroll
        for (int nt = 0; nt < 8; nt++) {
            float2 v0, v1;
            v0.x = acc[mt][nt][0]*scl0 + sft0;
            v0.y = acc[mt][nt][1]*scl0 + sft0;
            v1.x = acc[mt][nt][2]*scl1 + sft1;
            v1.y = acc[mt][nt][3]*scl1 + sft1;
            v0.x = 0.5f*v0.x*(1.0f + erff(v0.x*0.70710678118654752f));
            v0.y = 0.5f*v0.y*(1.0f + erff(v0.y*0.70710678118654752f));
            v1.x = 0.5f*v1.x*(1.0f + erff(v1.x*0.70710678118654752f));
            v1.y = 0.5f*v1.y*(1.0f + erff(v1.y*0.70710678118654752f));
            if (isV) {
                *(float2*)(yv0 + nt*8) = v0;
                *(float2*)(yv1 + nt*8) = v1;
                rs[mt][0] += v0.x + v0.y;
                rs[mt][1] += v1.x + v1.y;
            } else {
                *(__nv_bfloat162*)(yq0 + nt*8) = __float22bfloat162_rn(v0);
                *(__nv_bfloat162*)(yq1 + nt*8) = __float22bfloat162_rn(v1);
                rs[mt][0] += v0.x*v0.x + v0.y*v0.y;
                rs[mt][1] += v1.x*v1.x + v1.y*v1.y;
            }
        }
    }

    #pragma unroll
    for (int mt = 0; mt < 2; mt++)
        #pragma unroll
        for (int rr = 0; rr < 2; rr++) {
            float v = rs[mt][rr];
            v += __shfl_xor_sync(0xffffffffu, v, 1);
            v += __shfl_xor_sync(0xffffffffu, v, 2);
            if (q == 0) sred[mbw + mt*16 + g + rr*8][warpN] = v;
        }
    __syncthreads();
    if (t < 128) {
        float tot = sred[t][0] + sred[t][1];
        if (isV) g_vs_part[((size_t)pTile*16 + sb)*256 + (oBase - 512 + t)] = tot;
        else     g_ss_part[((size_t)pTile*16 + sb)*512 + (oBase + t)] = tot;
    }
}

// ---------------------------------------------------------------------------
// K3: finalize rnorm and vmean from partials
// ---------------------------------------------------------------------------
__global__ void finalize_kernel() {
    int sb = blockIdx.x;
    int t = threadIdx.x;
    float ss = 0.0f;
    for (int p = 0; p < NPT; p++) ss += g_ss_part[((size_t)p*16 + sb)*512 + t];
    g_rnorm[sb*512 + t] = 1.0f / fmaxf(sqrtf(ss), 1e-12f);
    if (t < 256) {
        float vs = 0.0f;
        for (int p = 0; p < NPT; p++) vs += g_vs_part[((size_t)p*16 + sb)*256 + t];
        g_vmean[sb*256 + t] = vs * (1.0f/HWP);
    }
}

// ---------------------------------------------------------------------------
// K4: attention logit partials via bf16 mma + ldmatrix
// ---------------------------------------------------------------------------
#define ANC 128
#define AST (ANC + 8)

__global__ void __launch_bounds__(256) attn_part_kernel() {
    int cx = blockIdx.x;
    int hb = blockIdx.y;
    int which = blockIdx.z;
    int h = hb & 3, b = hb >> 2;
    const __nv_bfloat16* Q = g_qk + ((size_t)(which*BB+b)*512 +       h*HDD)*HWP;
    const __nv_bfloat16* K = g_qk + ((size_t)((1-which)*BB+b)*512 + 256 + h*HDD)*HWP;

    __shared__ __align__(16) __nv_bfloat16 sQ[2][64*AST];
    __shared__ __align__(16) __nv_bfloat16 sK[2][64*AST];

    int t = threadIdx.x;
    int wid = t >> 5, lane = t & 31;
    int g = lane >> 2, q = lane & 3;
    int dBase = wid * 8;

    uint32_t sQb[2] = { smem_u32(sQ[0]), smem_u32(sQ[1]) };
    uint32_t sKb[2] = { smem_u32(sK[0]), smem_u32(sK[1]) };

    int lrow = lane & 7, lmat = lane >> 3;
    // Q x4 (A operand): mat0 m@k, mat1 m+8@k, mat2 m@k+8, mat3 m+8@k+8
    uint32_t qoff = (uint32_t)(((lmat & 1)*8 + lrow)*AST + (lmat >> 1)*8) * 2;
    // K x4 (B operand, single 8-wide tile, 4 consecutive k8 groups)
    uint32_t koff = (uint32_t)((dBase + lrow)*AST + lmat*8) * 2;

    auto stage = [&](int n0, int buf) {
        #pragma unroll
        for (int e = 0; e < 4; e++) {
            int c = t + e*256;
            int row = c >> 4, grp = c & 15;
            cpa16(sQb[buf] + (uint32_t)(row*AST + grp*8)*2, Q + (size_t)row*HWP + n0 + grp*8);
            cpa16(sKb[buf] + (uint32_t)(row*AST + grp*8)*2, K + (size_t)row*HWP + n0 + grp*8);
        }
    };

    float acc[4][4] = {};
    int n0base = cx * 1024;

    stage(n0base, 0);
    CPA_COMMIT();

    for (int st = 0; st < 8; st++) {
        int buf = st & 1;
        if (st + 1 < 8) { stage(n0base + (st+1)*ANC, buf ^ 1); CPA_COMMIT(); CPA_WAIT1(); }
        else CPA_WAIT0();
        __syncthreads();

        uint32_t Qb = sQb[buf], Kb = sKb[buf];
        #pragma unroll
        for (int ks2 = 0; ks2 < 4; ks2++) {
            uint32_t kb0, kb1, kb2, kb3;
            ldsm_x4(Kb + koff + ks2*64, kb0, kb1, kb2, kb3);
            #pragma unroll
            for (int half = 0; half < 2; half++) {
                uint32_t b0 = half ? kb2 : kb0;
                uint32_t b1 = half ? kb3 : kb1;
                #pragma unroll
                for (int mt = 0; mt < 4; mt++) {
                    uint32_t a[4];
                    ldsm_x4(Qb + qoff + mt*(16*AST*2) + ks2*64 + half*32,
                            a[0], a[1], a[2], a[3]);
                    mma_bf16(acc[mt], a, b0, b1);
                }
            }
        }
        __syncthreads();
    }

    float* P = g_lpart + (size_t)(((cx*2 + which)*BB + b)*NHH + h)*HDD*HDD;
    #pragma unroll
    for (int mt = 0; mt < 4; mt++) {
        float2 lo = { acc[mt][0], acc[mt][1] };
        float2 hi = { acc[mt][2], acc[mt][3] };
        *(float2*)(P + (mt*16 + g)*64 + dBase + 2*q) = lo;
        *(float2*)(P + (mt*16 + g + 8)*64 + dBase + 2*q) = hi;
    }
}

// ---------------------------------------------------------------------------
// K5: softmax over summed partials + SE-pool via A @ vmean
// ---------------------------------------------------------------------------
__global__ void attn_soft_kernel() {
    int hb = blockIdx.x;
    int which = blockIdx.y;
    int h = hb & 3, b = hb >> 2;
    int t = threadIdx.x;

    __shared__ float S[64][65];
    __shared__ float rq[64], rk[64], vm[64];

    rq[t] = g_rnorm[(which*BB+b)*512 +       h*64 + t];
    rk[t] = g_rnorm[((1-which)*BB+b)*512 + 256 + h*64 + t];
    vm[t] = g_vmean[(which*BB+b)*256 + h*64 + t];

    #pragma unroll
    for (int cx = 0; cx < 4; cx++) {
        const float* P = g_lpart + (size_t)(((cx*2 + which)*BB + b)*NHH + h)*HDD*HDD;
        for (int idx = t; idx < 4096; idx += 64) {
            float v = P[idx];
            if (cx == 0) S[idx >> 6][idx & 63] = v;
            else         S[idx >> 6][idx & 63] += v;
        }
        __syncthreads();
    }

    float sc = 0.125f * rq[t];
    float m = -1e30f;
    #pragma unroll
    for (int d = 0; d < 64; d++) {
        float v = S[t][d] * sc * rk[d];
        S[t][d] = v;
        m = fmaxf(m, v);
    }
    float sum = 0.0f;
    #pragma unroll
    for (int d = 0; d < 64; d++) { float ev = expf(S[t][d] - m); S[t][d] = ev; sum += ev; }
    float inv = 1.0f / sum;

    float* ap = g_attn + (size_t)(((which*BB+b)*NHH + h)*HDD + t)*HDD;
    float pool = 0.0f;
    #pragma unroll
    for (int d = 0; d < 64; d++) {
        float a = S[t][d] * inv;
        ap[d] = a;
        pool += a * vm[d];
    }
    g_pool[(which*BB+b)*CC + h*64 + t] = pool;
}

// ---------------------------------------------------------------------------
// K6: SE gate
// ---------------------------------------------------------------------------
__global__ void se_kernel(const float* __restrict__ w1, const float* __restrict__ b1_,
                          const float* __restrict__ w2, const float* __restrict__ b2_)
{
    int b = blockIdx.x, s = blockIdx.y;
    __shared__ float pm[256], ys[32];
    int t = threadIdx.x;
    pm[t] = g_pool[(s*BB+b)*CC + t];
    __syncthreads();
    if (t < 32) {
        float a = b1_[t];
        #pragma unroll 8
        for (int c = 0; c < 256; c++) a += w1[t*256 + c]*pm[c];
        ys[t] = fmaxf(a, 0.0f);
    }
    __syncthreads();
    float a = b2_[t];
    #pragma unroll
    for (int r = 0; r < 32; r++) a += w2[t*32 + r]*ys[r];
    g_gate[(s*BB+b)*CC + t] = 1.0f/(1.0f + expf(-a));
}

// ---------------------------------------------------------------------------
// K7: M = PO * diag(gate) * A_blk
// ---------------------------------------------------------------------------
__global__ void __launch_bounds__(256) mproj_kernel(
    const float* __restrict__ pw1, const float* __restrict__ pw2)
{
    int h = blockIdx.x, b = blockIdx.y, s = blockIdx.z;
    int sb = s*BB + b;
    const float* PO = s ? pw2 : pw1;
    const float* A  = g_attn + (size_t)((sb)*NHH + h)*HDD*HDD;
    int t = threadIdx.x;

    __shared__ float Ag[64][65];
    __shared__ float gsl[64];

    if (t < 64) gsl[t] = g_gate[sb*CC + h*64 + t];
    for (int idx = t; idx < 4096; idx += 256)
        Ag[idx >> 6][idx & 63] = A[idx];
    __syncthreads();

    float m[64];
    #pragma unroll
    for (int d = 0; d < 64; d++) m[d] = 0.0f;

    const float* po = PO + (size_t)t*CC + h*64;
    for (int c = 0; c < 64; c++) {
        float poc = po[c] * gsl[c];
        #pragma unroll
        for (int d = 0; d < 64; d++) m[d] += poc * Ag[c][d];
    }

    float* Mp = g_M + (size_t)sb*CC*CC + (size_t)t*CC + h*64;
    #pragma unroll
    for (int d = 0; d < 64; d++) Mp[d] = m[d];
}

// ---------------------------------------------------------------------------
// K8: out = M @ V + bias + residual  (mma.sync tf32)
// ---------------------------------------------------------------------------
__global__ void __launch_bounds__(256, 2) mv_tc_kernel(
    const float* __restrict__ x1, const float* __restrict__ x2,
    const float* __restrict__ pb1, const float* __restrict__ pb2,
    float* __restrict__ out)
{
    __shared__ __align__(16) float sA[2][128*ASTRIDE];
    __shared__ __align__(16) float sB[2][16*BSTRIDE];

    int pBase = blockIdx.x * 128;
    int oBase = blockIdx.y * 128;
    int s = blockIdx.z >> 3, b = blockIdx.z & 7;
    int sb = s*BB + b;

    const float* Msb  = g_M + (size_t)sb*CC*CC;
    const float* pb   = s ? pb2 : pb1;
    const float* V    = g_v + (size_t)sb*CC*HWP;
    const float* res  = (s ? x2 : x1) + (size_t)b*CC*HWP;
    float*       Y    = out + ((size_t)sb)*CC*HWP;

    int t = threadIdx.x;
    int wid = t >> 5, lane = t & 31;
    int warpM = wid >> 1, warpN = wid & 1;
    int mbw = warpM*32, nbw = warpN*64;
    int g = lane >> 2, q = lane & 3;

    uint32_t sAb[2] = { smem_u32(sA[0]), smem_u32(sA[1]) };
    uint32_t sBb[2] = { smem_u32(sB[0]), smem_u32(sB[1]) };

    int ac0_r = t >> 2, ac0_q = t & 3;
    int ac1_r = (t + 256) >> 2, ac1_q = (t + 256) & 3;
    int bc0_r = t >> 5, bc0_q = t & 31;
    int bc1_r = (t + 256) >> 5, bc1_q = (t + 256) & 31;

    float acc[2][8][4] = {};

    auto stage = [&](int k0, int buf) {
        cpa16(sAb[buf] + (uint32_t)(ac0_r*ASTRIDE + ac0_q*4)*4,
              Msb + (size_t)(oBase + ac0_r)*CC + k0 + ac0_q*4);
        cpa16(sAb[buf] + (uint32_t)(ac1_r*ASTRIDE + ac1_q*4)*4,
              Msb + (size_t)(oBase + ac1_r)*CC + k0 + ac1_q*4);
        cpa16(sBb[buf] + (uint32_t)(bc0_r*BSTRIDE + bc0_q*4)*4,
              V + (size_t)(k0 + bc0_r)*HWP + pBase + bc0_q*4);
        cpa16(sBb[buf] + (uint32_t)(bc1_r*BSTRIDE + bc1_q*4)*4,
              V + (size_t)(k0 + bc1_r)*HWP + pBase + bc1_q*4);
    };

    stage(0, 0);
    CPA_COMMIT();

    const int NIT = CC / 16;
    for (int it = 0; it < NIT; it++) {
        int buf = it & 1;
        if (it + 1 < NIT) { stage((it+1)*16, buf ^ 1); CPA_COMMIT(); CPA_WAIT1(); }
        else CPA_WAIT0();
        __syncthreads();

        const float* A = sA[buf];
        const float* Bm = sB[buf];
        #pragma unroll
        for (int kk = 0; kk < 2; kk++) {
            uint32_t af[2][4];
            #pragma unroll
            for (int mt = 0; mt < 2; mt++) {
                int m = mbw + mt*16 + g;
                int k = kk*8 + q;
                af[mt][0] = tf32r(A[m*ASTRIDE + k]);
                af[mt][1] = tf32r(A[(m+8)*ASTRIDE + k]);
                af[mt][2] = tf32r(A[m*ASTRIDE + k + 4]);
                af[mt][3] = tf32r(A[(m+8)*ASTRIDE + k + 4]);
            }
            #pragma unroll
            for (int nt = 0; nt < 8; nt++) {
                int n = nbw + nt*8 + g;
                int k = kk*8 + q;
                uint32_t b0 = tf32r(Bm[k*BSTRIDE + n]);
                uint32_t b1 = tf32r(Bm[(k+4)*BSTRIDE + n]);
                mma_tf32(acc[0][nt], af[0], b0, b1);
                mma_tf32(acc[1][nt], af[1], b0, b1);
            }
        }
        __syncthreads();
    }

    #pragma unroll
    for (int mt = 0; mt < 2; mt++) {
        int o0 = oBase + mbw + mt*16 + g;
        int o1 = o0 + 8;
        float bo0 = pb[o0], bo1 = pb[o1];
        float* y0 = Y + (size_t)o0*HWP + pBase + nbw + q*2;
        float* y1 = Y + (size_t)o1*HWP + pBase + nbw + q*2;
        const float* r0 = res + (size_t)o0*HWP + pBase + nbw + q*2;
        const float* r1 = res + (size_t)o1*HWP + pBase + nbw + q*2;
        #pragma unroll
        for (int nt = 0; nt < 8; nt++) {
            float2 rv0 = *(const float2*)(r0 + nt*8);
            float2 rv1 = *(const float2*)(r1 + nt*8);
            float2 v0, v1;
            v0.x = acc[mt][nt][0] + bo0 + rv0.x;
            v0.y = acc[mt][nt][1] + bo0 + rv0.y;
            v1.x = acc[mt][nt][2] + bo1 + rv1.x;
            v1.y = acc[mt][nt][3] + bo1 + rv1.y;
            *(float2*)(y0 + nt*8) = v0;
            *(float2*)(y1 + nt*8) = v1;
        }
    }
}

// ---------------------------------------------------------------------------
extern "C" void kernel_launch(void* const* d_in, const int* in_sizes, int n_in,
                              void* d_out, int out_size)
{
    const float* x1     = (const float*)d_in[0];
    const float* x2     = (const float*)d_in[1];
    const float* ms_w3  = (const float*)d_in[2];
    const float* ms_b3  = (const float*)d_in[3];
    const float* ms_w5  = (const float*)d_in[4];
    const float* ms_b5  = (const float*)d_in[5];
    const float* ms_w7  = (const float*)d_in[6];
    const float* ms_b7  = (const float*)d_in[7];
    const float* qkv1_w = (const float*)d_in[8];
    const float* qkv1_b = (const float*)d_in[9];
    const float* bn1_g  = (const float*)d_in[10];
    const float* bn1_b  = (const float*)d_in[11];
    const float* bn1_m  = (const float*)d_in[12];
    const float* bn1_v  = (const float*)d_in[13];
    const float* qkv2_w = (const float*)d_in[14];
    const float* qkv2_b = (const float*)d_in[15];
    const float* bn2_g  = (const float*)d_in[16];
    const float* bn2_b  = (const float*)d_in[17];
    const float* bn2_m  = (const float*)d_in[18];
    const float* bn2_v  = (const float*)d_in[19];
    const float* ca_w1  = (const float*)d_in[20];
    const float* ca_b1  = (const float*)d_in[21];
    const float* ca_w2  = (const float*)d_in[22];
    const float* ca_b2  = (const float*)d_in[23];
    const float* po1_w  = (const float*)d_in[24];
    const float* po1_b  = (const float*)d_in[25];
    const float* po2_w  = (const float*)d_in[26];
    const float* po2_b  = (const float*)d_in[27];
    float* out = (float*)d_out;

    convert_w_kernel<<<C3*CC/256, 256>>>(qkv1_w, qkv2_w);
    msconv_kernel<<<dim3(CC, BB, 2), 256>>>(x1, x2, ms_w3, ms_b3, ms_w5, ms_b5, ms_w7, ms_b7);
    transpose_kernel<<<dim3(HWP/64, CC/64, 16), 256>>>();
    qkv_tc_kernel<<<dim3(NPT, C3/128, 16), 256>>>(
        qkv1_b, bn1_g, bn1_b, bn1_m, bn1_v,
        qkv2_b, bn2_g, bn2_b, bn2_m, bn2_v);
    finalize_kernel<<<16, 512>>>();
    attn_part_kernel<<<dim3(4, NHH*BB, 2), 256>>>();
    attn_soft_kernel<<<dim3(NHH*BB, 2), 64>>>();
    se_kernel<<<dim3(BB, 2), 256>>>(ca_w1, ca_b1, ca_w2, ca_b2);
    mproj_kernel<<<dim3(NHH, BB, 2), 256>>>(po1_w, po2_w);
    mv_tc_kernel<<<dim3(HWP/128, CC/128, 16), 256>>>(x1, x2, po1_b, po2_b, out);
}

// round 8
// speedup vs baseline: 5.6884x; 1.1847x over previous
#include <cuda_runtime.h>
#include <cuda_bf16.h>
#include <cuda_fp16.h>
#include <math.h>
#include <cstdint>

#define BB  8
#define CC  256
#define HH  64
#define WW  64
#define HWP 4096
#define NHH 4
#define HDD 64
#define C3  768
#define NPT 32            // qkv pTile count (4096/128)

// ---- scratch (static device globals; no allocation at runtime) ----
__device__ __nv_bfloat16  g_xfh[2ULL*BB*CC*HWP];   //  33 MB  msconv out, [c][n] bf16
__device__ __nv_bfloat16  g_xfT[2ULL*BB*CC*HWP];   //  33 MB  transposed  [n][c] bf16
__device__ __nv_bfloat16  g_wqkv[2ULL*C3*CC];      //  qkv weights bf16
__device__ __nv_bfloat16  g_qk [2ULL*BB*512*HWP];  //  67 MB  gelu(bn(q,k)) bf16
__device__ __half         g_vh [2ULL*BB*CC*HWP];   //  33 MB  gelu(bn(v)) fp16 [c][n]
__device__ float g_ss_part[NPT*16*512];            //  per-pTile sum-of-squares partials
__device__ float g_vs_part[NPT*16*256];            //  per-pTile V row-sum partials
__device__ float g_rnorm[16*512];
__device__ float g_vmean[16*256];
__device__ float g_lpart[4ULL*2*BB*NHH*HDD*HDD];   //  attn logit partials (4 chunks)
__device__ float g_attn [2*BB*NHH*HDD*HDD];
__device__ float g_pool [2*BB*CC];
__device__ float g_gate [2*BB*CC];
__device__ __half g_Mh  [16ULL*CC*CC];             //  M = PO*diag(gate)*A_blk, fp16

// ======================= helpers =======================
__device__ __forceinline__ uint32_t smem_u32(const void* p) {
    uint32_t a;
    asm("{ .reg .u64 t; cvta.to.shared.u64 t, %1; cvt.u32.u64 %0, t; }" : "=r"(a) : "l"(p));
    return a;
}
__device__ __forceinline__ void cpa16(uint32_t dst, const void* src) {
    asm volatile("cp.async.cg.shared.global [%0], [%1], 16;" :: "r"(dst), "l"(src));
}
#define CPA_COMMIT() asm volatile("cp.async.commit_group;" ::: "memory")
#define CPA_WAIT1()  asm volatile("cp.async.wait_group 1;" ::: "memory")
#define CPA_WAIT0()  asm volatile("cp.async.wait_group 0;" ::: "memory")

__device__ __forceinline__ void mma_bf16(float* d, const uint32_t* a, uint32_t b0, uint32_t b1) {
    asm volatile(
        "mma.sync.aligned.m16n8k16.row.col.f32.bf16.bf16.f32 "
        "{%0,%1,%2,%3}, {%4,%5,%6,%7}, {%8,%9}, {%0,%1,%2,%3};"
        : "+f"(d[0]), "+f"(d[1]), "+f"(d[2]), "+f"(d[3])
        : "r"(a[0]), "r"(a[1]), "r"(a[2]), "r"(a[3]), "r"(b0), "r"(b1));
}
__device__ __forceinline__ void mma_f16(float* d, const uint32_t* a, uint32_t b0, uint32_t b1) {
    asm volatile(
        "mma.sync.aligned.m16n8k16.row.col.f32.f16.f16.f32 "
        "{%0,%1,%2,%3}, {%4,%5,%6,%7}, {%8,%9}, {%0,%1,%2,%3};"
        : "+f"(d[0]), "+f"(d[1]), "+f"(d[2]), "+f"(d[3])
        : "r"(a[0]), "r"(a[1]), "r"(a[2]), "r"(a[3]), "r"(b0), "r"(b1));
}
__device__ __forceinline__ void ldsm_x4(uint32_t addr, uint32_t& r0, uint32_t& r1,
                                        uint32_t& r2, uint32_t& r3) {
    asm volatile("ldmatrix.sync.aligned.m8n8.x4.shared.b16 {%0,%1,%2,%3}, [%4];"
                 : "=r"(r0), "=r"(r1), "=r"(r2), "=r"(r3) : "r"(addr));
}
__device__ __forceinline__ void ldsm_x4_t(uint32_t addr, uint32_t& r0, uint32_t& r1,
                                          uint32_t& r2, uint32_t& r3) {
    asm volatile("ldmatrix.sync.aligned.m8n8.x4.trans.shared.b16 {%0,%1,%2,%3}, [%4];"
                 : "=r"(r0), "=r"(r1), "=r"(r2), "=r"(r3) : "r"(addr));
}

#define QST 40        // bf16/fp16 GEMM smem A/B row stride (elems): 80B, conflict-free
#define VST 136       // mv V smem row stride (elems): 272B, conflict-free for trans

// ---------------------------------------------------------------------------
// K0a: convert qkv weights to bf16 (tiny)
// ---------------------------------------------------------------------------
__global__ void convert_w_kernel(const float* __restrict__ w1, const float* __restrict__ w2) {
    int i = blockIdx.x * 256 + threadIdx.x;
    g_wqkv[i]         = __float2bfloat16(w1[i]);
    g_wqkv[C3*CC + i] = __float2bfloat16(w2[i]);
}

// ---------------------------------------------------------------------------
// K1: fused multiscale depthwise conv; writes bf16 [c][n]
// ---------------------------------------------------------------------------
__global__ void msconv_kernel(const float* __restrict__ x1, const float* __restrict__ x2,
                              const float* __restrict__ w3, const float* __restrict__ b3,
                              const float* __restrict__ w5, const float* __restrict__ b5,
                              const float* __restrict__ w7, const float* __restrict__ b7)
{
    int c = blockIdx.x, b = blockIdx.y, s = blockIdx.z;
    const float* xin = (s ? x2 : x1) + ((size_t)b*CC + c)*HWP;

    __shared__ float tile[70*70];
    __shared__ float wc[49];
    int t = threadIdx.x;

    if (t < 49) {
        int ky = t / 7, kx = t % 7;
        float w = w7[c*49 + t];
        if (ky >= 1 && ky <= 5 && kx >= 1 && kx <= 5) w += w5[c*25 + (ky-1)*5 + (kx-1)];
        if (ky >= 2 && ky <= 4 && kx >= 2 && kx <= 4) w += w3[c*9  + (ky-2)*3 + (kx-2)];
        wc[t] = w * (1.0f/3.0f);
    }
    for (int i = t; i < 70*70; i += 256) {
        int ty = i / 70, tx = i % 70;
        int gy = ty - 3, gx = tx - 3;
        tile[i] = (gy >= 0 && gy < HH && gx >= 0 && gx < WW) ? xin[gy*WW + gx] : 0.0f;
    }
    __syncthreads();

    int tx = t & 63;
    int ty0 = (t >> 6) * 16;
    float bias = (b3[c] + b5[c] + b7[c]) * (1.0f/3.0f);

    float acc[16];
    #pragma unroll
    for (int i = 0; i < 16; i++) acc[i] = bias;

    #pragma unroll
    for (int r = 0; r < 22; r++) {
        float v[7];
        #pragma unroll
        for (int kx = 0; kx < 7; kx++) v[kx] = tile[(ty0 + r)*70 + tx + kx];
        #pragma unroll
        for (int ky = 0; ky < 7; ky++) {
            int ro = r - ky;
            if (ro >= 0 && ro < 16) {
                #pragma unroll
                for (int kx = 0; kx < 7; kx++)
                    acc[ro] += wc[ky*7+kx] * v[kx];
            }
        }
    }

    __nv_bfloat16* outp = g_xfh + ((size_t)(s*BB+b)*CC + c)*HWP;
    #pragma unroll
    for (int i = 0; i < 16; i++)
        outp[(ty0 + i)*WW + tx] = __float2bfloat16(acc[i]);
}

// ---------------------------------------------------------------------------
// K1b: transpose xf [c][n] -> xfT [n][c]  (bf16, 64x64 tiles)
// ---------------------------------------------------------------------------
__global__ void transpose_kernel() {
    int nT = blockIdx.x * 64, cT = blockIdx.y * 64, sb = blockIdx.z;
    __shared__ __nv_bfloat16 ts[64][65];
    const __nv_bfloat16* src = g_xfh + ((size_t)sb*CC + cT)*HWP + nT;
    __nv_bfloat16*       dst = g_xfT + ((size_t)sb*HWP + nT)*CC + cT;
    int t = threadIdx.x;
    #pragma unroll
    for (int e = 0; e < 16; e++) {
        int idx = t + e*256;
        int r = idx >> 6, col = idx & 63;
        ts[r][col] = src[(size_t)r*HWP + col];
    }
    __syncthreads();
    #pragma unroll
    for (int e = 0; e < 16; e++) {
        int idx = t + e*256;
        int r = idx >> 6, col = idx & 63;
        dst[(size_t)r*CC + col] = ts[col][r];
    }
}

// ---------------------------------------------------------------------------
// K2: qkv GEMM bf16 mma + ldmatrix, 3-stage cp.async ring (1 sync/iter).
//     Epilogue: BN + GELU; q/k out bf16, v out fp16; row statistics.
// ---------------------------------------------------------------------------
__global__ void __launch_bounds__(256, 2) qkv_tc_kernel(
    const float* __restrict__ bq1,
    const float* __restrict__ g1, const float* __restrict__ be1,
    const float* __restrict__ m1, const float* __restrict__ v1,
    const float* __restrict__ bq2,
    const float* __restrict__ g2, const float* __restrict__ be2,
    const float* __restrict__ m2, const float* __restrict__ v2)
{
    __shared__ __align__(16) __nv_bfloat16 sA[3][128*QST];
    __shared__ __align__(16) __nv_bfloat16 sB[3][128*QST];
    __shared__ float sred[128][2];

    int pTile = blockIdx.x;
    int pBase = pTile * 128;
    int oBase = blockIdx.y * 128;
    int s = blockIdx.z >> 3, b = blockIdx.z & 7;
    int sb = s*BB + b;

    const __nv_bfloat16* W = g_wqkv + (size_t)s*C3*CC;
    const float* bq  = s ? bq2 : bq1;
    const float* bg  = s ? g2  : g1;
    const float* bbv = s ? be2 : be1;
    const float* bm  = s ? m2  : m1;
    const float* bv  = s ? v2  : v1;
    const __nv_bfloat16* XT = g_xfT + (size_t)sb*HWP*CC;

    int t = threadIdx.x;
    int wid = t >> 5, lane = t & 31;
    int warpM = wid >> 1, warpN = wid & 1;
    int mbw = warpM*32, nbw = warpN*64;
    int g = lane >> 2, q = lane & 3;

    uint32_t sA0 = smem_u32(sA[0]);
    uint32_t sB0 = smem_u32(sB[0]);
    const uint32_t BUFB = 128*QST*2;   // 10240 bytes per stage

    int lrow = lane & 7, lmat = lane >> 3;
    uint32_t aoff = (uint32_t)((mbw + (lmat & 1)*8 + lrow)*QST + (lmat >> 1)*8) * 2;
    uint32_t boff = (uint32_t)((nbw + (lmat >> 1)*8 + lrow)*QST + (lmat & 1)*8) * 2;

    int c0_r = t >> 2, c0_g = t & 3;
    int c1_r = (t + 256) >> 2, c1_g = (t + 256) & 3;

    float acc[2][8][4] = {};

    auto stage = [&](int k0, int st) {
        uint32_t ab = sA0 + st*BUFB, bb = sB0 + st*BUFB;
        cpa16(ab + (uint32_t)(c0_r*QST + c0_g*8)*2,
              W + (size_t)(oBase + c0_r)*CC + k0 + c0_g*8);
        cpa16(ab + (uint32_t)(c1_r*QST + c1_g*8)*2,
              W + (size_t)(oBase + c1_r)*CC + k0 + c1_g*8);
        cpa16(bb + (uint32_t)(c0_r*QST + c0_g*8)*2,
              XT + (size_t)(pBase + c0_r)*CC + k0 + c0_g*8);
        cpa16(bb + (uint32_t)(c1_r*QST + c1_g*8)*2,
              XT + (size_t)(pBase + c1_r)*CC + k0 + c1_g*8);
    };

    stage(0, 0);  CPA_COMMIT();
    stage(32, 1); CPA_COMMIT();

    const int NIT = CC / 32;   // 8
    for (int it = 0; it < NIT; it++) {
        if (it < NIT-1) CPA_WAIT1(); else CPA_WAIT0();
        __syncthreads();
        if (it + 2 < NIT) { stage((it+2)*32, (it+2)%3); CPA_COMMIT(); }

        int st = it % 3;
        uint32_t Ab = sA0 + st*BUFB, Bb = sB0 + st*BUFB;
        #pragma unroll
        for (int ks = 0; ks < 2; ks++) {
            uint32_t af[2][4];
            ldsm_x4(Ab + aoff + ks*32,        af[0][0], af[0][1], af[0][2], af[0][3]);
            ldsm_x4(Ab + aoff + 1280 + ks*32, af[1][0], af[1][1], af[1][2], af[1][3]);
            #pragma unroll
            for (int p = 0; p < 4; p++) {
                uint32_t r0, r1, r2, r3;
                ldsm_x4(Bb + boff + p*1280 + ks*32, r0, r1, r2, r3);
                mma_bf16(acc[0][2*p],   af[0], r0, r1);
                mma_bf16(acc[0][2*p+1], af[0], r2, r3);
                mma_bf16(acc[1][2*p],   af[1], r0, r1);
                mma_bf16(acc[1][2*p+1], af[1], r2, r3);
            }
        }
    }

    bool isV = (oBase >= 512);
    float rs[2][2] = {};

    #pragma unroll
    for (int mt = 0; mt < 2; mt++) {
        int o0 = oBase + mbw + mt*16 + g;
        int o1 = o0 + 8;
        float scl0 = bg[o0] * rsqrtf(bv[o0] + 1e-5f);
        float sft0 = bbv[o0] - bm[o0]*scl0 + bq[o0]*scl0;
        float scl1 = bg[o1] * rsqrtf(bv[o1] + 1e-5f);
        float sft1 = bbv[o1] - bm[o1]*scl1 + bq[o1]*scl1;

        __half* yv0 = g_vh + ((size_t)sb*CC + (o0 - 512))*HWP + pBase + nbw + q*2;
        __half* yv1 = g_vh + ((size_t)sb*CC + (o1 - 512))*HWP + pBase + nbw + q*2;
        __nv_bfloat16* yq0 = g_qk + ((size_t)sb*512 + o0)*HWP + pBase + nbw + q*2;
        __nv_bfloat16* yq1 = g_qk + ((size_t)sb*512 + o1)*HWP + pBase + nbw + q*2;

        #pragma unroll
        for (int nt = 0; nt < 8; nt++) {
            float2 v0, v1;
            v0.x = acc[mt][nt][0]*scl0 + sft0;
            v0.y = acc[mt][nt][1]*scl0 + sft0;
            v1.x = acc[mt][nt][2]*scl1 + sft1;
            v1.y = acc[mt][nt][3]*scl1 + sft1;
            v0.x = 0.5f*v0.x*(1.0f + erff(v0.x*0.70710678118654752f));
            v0.y = 0.5f*v0.y*(1.0f + erff(v0.y*0.70710678118654752f));
            v1.x = 0.5f*v1.x*(1.0f + erff(v1.x*0.70710678118654752f));
            v1.y = 0.5f*v1.y*(1.0f + erff(v1.y*0.70710678118654752f));
            if (isV) {
                *(__half2*)(yv0 + nt*8) = __float22half2_rn(v0);
                *(__half2*)(yv1 + nt*8) = __float22half2_rn(v1);
                rs[mt][0] += v0.x + v0.y;
                rs[mt][1] += v1.x + v1.y;
            } else {
                *(__nv_bfloat162*)(yq0 + nt*8) = __float22bfloat162_rn(v0);
                *(__nv_bfloat162*)(yq1 + nt*8) = __float22bfloat162_rn(v1);
                rs[mt][0] += v0.x*v0.x + v0.y*v0.y;
                rs[mt][1] += v1.x*v1.x + v1.y*v1.y;
            }
        }
    }

    #pragma unroll
    for (int mt = 0; mt < 2; mt++)
        #pragma unroll
        for (int rr = 0; rr < 2; rr++) {
            float v = rs[mt][rr];
            v += __shfl_xor_sync(0xffffffffu, v, 1);
            v += __shfl_xor_sync(0xffffffffu, v, 2);
            if (q == 0) sred[mbw + mt*16 + g + rr*8][warpN] = v;
        }
    __syncthreads();
    if (t < 128) {
        float tot = sred[t][0] + sred[t][1];
        if (isV) g_vs_part[((size_t)pTile*16 + sb)*256 + (oBase - 512 + t)] = tot;
        else     g_ss_part[((size_t)pTile*16 + sb)*512 + (oBase + t)] = tot;
    }
}

// ---------------------------------------------------------------------------
// K3: finalize rnorm and vmean from partials
// ---------------------------------------------------------------------------
__global__ void finalize_kernel() {
    int sb = blockIdx.x;
    int t = threadIdx.x;
    float ss = 0.0f;
    for (int p = 0; p < NPT; p++) ss += g_ss_part[((size_t)p*16 + sb)*512 + t];
    g_rnorm[sb*512 + t] = 1.0f / fmaxf(sqrtf(ss), 1e-12f);
    if (t < 256) {
        float vs = 0.0f;
        for (int p = 0; p < NPT; p++) vs += g_vs_part[((size_t)p*16 + sb)*256 + t];
        g_vmean[sb*256 + t] = vs * (1.0f/HWP);
    }
}

// ---------------------------------------------------------------------------
// K4: attention logit partials via bf16 mma + ldmatrix
// ---------------------------------------------------------------------------
#define ANC 128
#define AST (ANC + 8)

__global__ void __launch_bounds__(256) attn_part_kernel() {
    int cx = blockIdx.x;
    int hb = blockIdx.y;
    int which = blockIdx.z;
    int h = hb & 3, b = hb >> 2;
    const __nv_bfloat16* Q = g_qk + ((size_t)(which*BB+b)*512 +       h*HDD)*HWP;
    const __nv_bfloat16* K = g_qk + ((size_t)((1-which)*BB+b)*512 + 256 + h*HDD)*HWP;

    __shared__ __align__(16) __nv_bfloat16 sQ[2][64*AST];
    __shared__ __align__(16) __nv_bfloat16 sK[2][64*AST];

    int t = threadIdx.x;
    int wid = t >> 5, lane = t & 31;
    int g = lane >> 2, q = lane & 3;
    int dBase = wid * 8;

    uint32_t sQb[2] = { smem_u32(sQ[0]), smem_u32(sQ[1]) };
    uint32_t sKb[2] = { smem_u32(sK[0]), smem_u32(sK[1]) };

    int lrow = lane & 7, lmat = lane >> 3;
    uint32_t qoff = (uint32_t)(((lmat & 1)*8 + lrow)*AST + (lmat >> 1)*8) * 2;
    uint32_t koff = (uint32_t)((dBase + lrow)*AST + lmat*8) * 2;

    auto stage = [&](int n0, int buf) {
        #pragma unroll
        for (int e = 0; e < 4; e++) {
            int c = t + e*256;
            int row = c >> 4, grp = c & 15;
            cpa16(sQb[buf] + (uint32_t)(row*AST + grp*8)*2, Q + (size_t)row*HWP + n0 + grp*8);
            cpa16(sKb[buf] + (uint32_t)(row*AST + grp*8)*2, K + (size_t)row*HWP + n0 + grp*8);
        }
    };

    float acc[4][4] = {};
    int n0base = cx * 1024;

    stage(n0base, 0);
    CPA_COMMIT();

    for (int st = 0; st < 8; st++) {
        int buf = st & 1;
        if (st + 1 < 8) { stage(n0base + (st+1)*ANC, buf ^ 1); CPA_COMMIT(); CPA_WAIT1(); }
        else CPA_WAIT0();
        __syncthreads();

        uint32_t Qb = sQb[buf], Kb = sKb[buf];
        #pragma unroll
        for (int ks2 = 0; ks2 < 4; ks2++) {
            uint32_t kb0, kb1, kb2, kb3;
            ldsm_x4(Kb + koff + ks2*64, kb0, kb1, kb2, kb3);
            #pragma unroll
            for (int half = 0; half < 2; half++) {
                uint32_t b0 = half ? kb2 : kb0;
                uint32_t b1 = half ? kb3 : kb1;
                #pragma unroll
                for (int mt = 0; mt < 4; mt++) {
                    uint32_t a[4];
                    ldsm_x4(Qb + qoff + mt*(16*AST*2) + ks2*64 + half*32,
                            a[0], a[1], a[2], a[3]);
                    mma_bf16(acc[mt], a, b0, b1);
                }
            }
        }
        __syncthreads();
    }

    float* P = g_lpart + (size_t)(((cx*2 + which)*BB + b)*NHH + h)*HDD*HDD;
    #pragma unroll
    for (int mt = 0; mt < 4; mt++) {
        float2 lo = { acc[mt][0], acc[mt][1] };
        float2 hi = { acc[mt][2], acc[mt][3] };
        *(float2*)(P + (mt*16 + g)*64 + dBase + 2*q) = lo;
        *(float2*)(P + (mt*16 + g + 8)*64 + dBase + 2*q) = hi;
    }
}

// ---------------------------------------------------------------------------
// K5: softmax over summed partials + SE-pool via A @ vmean (256 threads)
// ---------------------------------------------------------------------------
__global__ void __launch_bounds__(256) attn_soft_kernel() {
    int hb = blockIdx.x;
    int which = blockIdx.y;
    int h = hb & 3, b = hb >> 2;
    int t = threadIdx.x;

    __shared__ float S[64][65];
    __shared__ float rq[64], rk[64], vm[64];

    if (t < 64) {
        rq[t] = g_rnorm[(which*BB+b)*512 +       h*64 + t];
        rk[t] = g_rnorm[((1-which)*BB+b)*512 + 256 + h*64 + t];
        vm[t] = g_vmean[(which*BB+b)*256 + h*64 + t];
    }

    // each thread accumulates its 16 cells of the 4 chunk partials in regs
    float vacc[16];
    {
        const float* P0 = g_lpart + (size_t)(((0*2 + which)*BB + b)*NHH + h)*HDD*HDD;
        #pragma unroll
        for (int j = 0; j < 16; j++) vacc[j] = P0[t + j*256];
    }
    #pragma unroll
    for (int cx = 1; cx < 4; cx++) {
        const float* P = g_lpart + (size_t)(((cx*2 + which)*BB + b)*NHH + h)*HDD*HDD;
        #pragma unroll
        for (int j = 0; j < 16; j++) vacc[j] += P[t + j*256];
    }
    #pragma unroll
    for (int j = 0; j < 16; j++) {
        int idx = t + j*256;
        S[idx >> 6][idx & 63] = vacc[j];
    }
    __syncthreads();

    if (t < 64) {
        float sc = 0.125f * rq[t];
        float m = -1e30f;
        #pragma unroll
        for (int d = 0; d < 64; d++) {
            float v = S[t][d] * sc * rk[d];
            S[t][d] = v;
            m = fmaxf(m, v);
        }
        float sum = 0.0f;
        #pragma unroll
        for (int d = 0; d < 64; d++) { float ev = expf(S[t][d] - m); S[t][d] = ev; sum += ev; }
        float inv = 1.0f / sum;

        float* ap = g_attn + (size_t)(((which*BB+b)*NHH + h)*HDD + t)*HDD;
        float pool = 0.0f;
        #pragma unroll
        for (int d = 0; d < 64; d++) {
            float a = S[t][d] * inv;
            ap[d] = a;
            pool += a * vm[d];
        }
        g_pool[(which*BB+b)*CC + h*64 + t] = pool;
    }
}

// ---------------------------------------------------------------------------
// K6: SE gate
// ---------------------------------------------------------------------------
__global__ void se_kernel(const float* __restrict__ w1, const float* __restrict__ b1_,
                          const float* __restrict__ w2, const float* __restrict__ b2_)
{
    int b = blockIdx.x, s = blockIdx.y;
    __shared__ float pm[256], ys[32];
    int t = threadIdx.x;
    pm[t] = g_pool[(s*BB+b)*CC + t];
    __syncthreads();
    if (t < 32) {
        float a = b1_[t];
        #pragma unroll 8
        for (int c = 0; c < 256; c++) a += w1[t*256 + c]*pm[c];
        ys[t] = fmaxf(a, 0.0f);
    }
    __syncthreads();
    float a = b2_[t];
    #pragma unroll
    for (int r = 0; r < 32; r++) a += w2[t*32 + r]*ys[r];
    g_gate[(s*BB+b)*CC + t] = 1.0f/(1.0f + expf(-a));
}

// ---------------------------------------------------------------------------
// K7: M = PO * diag(gate) * A_blk  -> fp16
// ---------------------------------------------------------------------------
__global__ void __launch_bounds__(256) mproj_kernel(
    const float* __restrict__ pw1, const float* __restrict__ pw2)
{
    int h = blockIdx.x, b = blockIdx.y, s = blockIdx.z;
    int sb = s*BB + b;
    const float* PO = s ? pw2 : pw1;
    const float* A  = g_attn + (size_t)((sb)*NHH + h)*HDD*HDD;
    int t = threadIdx.x;

    __shared__ float Ag[64][65];
    __shared__ float gsl[64];

    if (t < 64) gsl[t] = g_gate[sb*CC + h*64 + t];
    for (int idx = t; idx < 4096; idx += 256)
        Ag[idx >> 6][idx & 63] = A[idx];
    __syncthreads();

    float m[64];
    #pragma unroll
    for (int d = 0; d < 64; d++) m[d] = 0.0f;

    const float* po = PO + (size_t)t*CC + h*64;
    for (int c = 0; c < 64; c++) {
        float poc = po[c] * gsl[c];
        #pragma unroll
        for (int d = 0; d < 64; d++) m[d] += poc * Ag[c][d];
    }

    __half* Mp = g_Mh + (size_t)sb*CC*CC + (size_t)t*CC + h*64;
    #pragma unroll
    for (int d = 0; d < 64; d += 2)
        *(__half2*)(Mp + d) = __floats2half2_rn(m[d], m[d+1]);
}

// ---------------------------------------------------------------------------
// K8: out = M @ V + bias + residual  (fp16 mma; V via ldmatrix.trans)
// ---------------------------------------------------------------------------
__global__ void __launch_bounds__(256, 2) mv_tc_kernel(
    const float* __restrict__ x1, const float* __restrict__ x2,
    const float* __restrict__ pb1, const float* __restrict__ pb2,
    float* __restrict__ out)
{
    __shared__ __align__(16) __half sM[3][128*QST];   // 128 o-rows x 32 c
    __shared__ __align__(16) __half sV[3][32*VST];    // 32 c-rows x 128 n

    int pBase = blockIdx.x * 128;
    int oBase = blockIdx.y * 128;
    int s = blockIdx.z >> 3, b = blockIdx.z & 7;
    int sb = s*BB + b;

    const __half* Mh = g_Mh + (size_t)sb*CC*CC;
    const __half* Vh = g_vh + (size_t)sb*CC*HWP;
    const float* pb  = s ? pb2 : pb1;
    const float* res = (s ? x2 : x1) + (size_t)b*CC*HWP;
    float*       Y   = out + ((size_t)sb)*CC*HWP;

    int t = threadIdx.x;
    int wid = t >> 5, lane = t & 31;
    int warpM = wid >> 1, warpN = wid & 1;
    int mbw = warpM*32, nbw = warpN*64;
    int g = lane >> 2, q = lane & 3;
    int lrow = lane & 7, lmat = lane >> 3;

    uint32_t sM0 = smem_u32(sM[0]);
    uint32_t sV0 = smem_u32(sV[0]);
    const uint32_t MBUF = 128*QST*2;  // 10240
    const uint32_t VBUF = 32*VST*2;   // 8704

    // A fragment offsets (same pattern as qkv A)
    uint32_t aoff = (uint32_t)((mbw + (lmat & 1)*8 + lrow)*QST + (lmat >> 1)*8) * 2;
    // B via trans: lanes 0-7:(k0-7,n0-7) 8-15:(k8-15,n0-7) 16-23:(k0-7,n8-15) 24-31:(k8-15,n8-15)
    uint32_t boff = (uint32_t)(((lmat & 1)*8 + lrow)*VST + nbw + (lmat >> 1)*8) * 2;

    int a0_r = t >> 2, a0_g = t & 3;
    int a1_r = (t + 256) >> 2, a1_g = (t + 256) & 3;
    int v0_r = t >> 4, v0_g = t & 15;
    int v1_r = (t + 256) >> 4, v1_g = (t + 256) & 15;

    float acc[2][8][4] = {};

    auto stage = [&](int k0, int st) {
        uint32_t ab = sM0 + st*MBUF, vb = sV0 + st*VBUF;
        cpa16(ab + (uint32_t)(a0_r*QST + a0_g*8)*2,
              Mh + (size_t)(oBase + a0_r)*CC + k0 + a0_g*8);
        cpa16(ab + (uint32_t)(a1_r*QST + a1_g*8)*2,
              Mh + (size_t)(oBase + a1_r)*CC + k0 + a1_g*8);
        cpa16(vb + (uint32_t)(v0_r*VST + v0_g*8)*2,
              Vh + (size_t)(k0 + v0_r)*HWP + pBase + v0_g*8);
        cpa16(vb + (uint32_t)(v1_r*VST + v1_g*8)*2,
              Vh + (size_t)(k0 + v1_r)*HWP + pBase + v1_g*8);
    };

    stage(0, 0);  CPA_COMMIT();
    stage(32, 1); CPA_COMMIT();

    const int NIT = CC / 32;   // 8
    for (int it = 0; it < NIT; it++) {
        if (it < NIT-1) CPA_WAIT1(); else CPA_WAIT0();
        __syncthreads();
        if (it + 2 < NIT) { stage((it+2)*32, (it+2)%3); CPA_COMMIT(); }

        int st = it % 3;
        uint32_t Ab = sM0 + st*MBUF, Vb = sV0 + st*VBUF;
        #pragma unroll
        for (int ks = 0; ks < 2; ks++) {
            uint32_t af[2][4];
            ldsm_x4(Ab + aoff + ks*32,        af[0][0], af[0][1], af[0][2], af[0][3]);
            ldsm_x4(Ab + aoff + 1280 + ks*32, af[1][0], af[1][1], af[1][2], af[1][3]);
            #pragma unroll
            for (int p = 0; p < 4; p++) {
                uint32_t r0, r1, r2, r3;
                ldsm_x4_t(Vb + boff + ks*(16*VST*2) + p*32, r0, r1, r2, r3);
                mma_f16(acc[0][2*p],   af[0], r0, r1);
                mma_f16(acc[0][2*p+1], af[0], r2, r3);
                mma_f16(acc[1][2*p],   af[1], r0, r1);
                mma_f16(acc[1][2*p+1], af[1], r2, r3);
            }
        }
    }

    #pragma unroll
    for (int mt = 0; mt < 2; mt++) {
        int o0 = oBase + mbw + mt*16 + g;
        int o1 = o0 + 8;
        float bo0 = pb[o0], bo1 = pb[o1];
        float* y0 = Y + (size_t)o0*HWP + pBase + nbw + q*2;
        float* y1 = Y + (size_t)o1*HWP + pBase + nbw + q*2;
        const float* r0 = res + (size_t)o0*HWP + pBase + nbw + q*2;
        const float* r1 = res + (size_t)o1*HWP + pBase + nbw + q*2;
        #pragma unroll
        for (int nt = 0; nt < 8; nt++) {
            float2 rv0 = *(const float2*)(r0 + nt*8);
            float2 rv1 = *(const float2*)(r1 + nt*8);
            float2 v0, v1;
            v0.x = acc[mt][nt][0] + bo0 + rv0.x;
            v0.y = acc[mt][nt][1] + bo0 + rv0.y;
            v1.x = acc[mt][nt][2] + bo1 + rv1.x;
            v1.y = acc[mt][nt][3] + bo1 + rv1.y;
            *(float2*)(y0 + nt*8) = v0;
            *(float2*)(y1 + nt*8) = v1;
        }
    }
}

// ---------------------------------------------------------------------------
extern "C" void kernel_launch(void* const* d_in, const int* in_sizes, int n_in,
                              void* d_out, int out_size)
{
    const float* x1     = (const float*)d_in[0];
    const float* x2     = (const float*)d_in[1];
    const float* ms_w3  = (const float*)d_in[2];
    const float* ms_b3  = (const float*)d_in[3];
    const float* ms_w5  = (const float*)d_in[4];
    const float* ms_b5  = (const float*)d_in[5];
    const float* ms_w7  = (const float*)d_in[6];
    const float* ms_b7  = (const float*)d_in[7];
    const float* qkv1_w = (const float*)d_in[8];
    const float* qkv1_b = (const float*)d_in[9];
    const float* bn1_g  = (const float*)d_in[10];
    const float* bn1_b  = (const float*)d_in[11];
    const float* bn1_m  = (const float*)d_in[12];
    const float* bn1_v  = (const float*)d_in[13];
    const float* qkv2_w = (const float*)d_in[14];
    const float* qkv2_b = (const float*)d_in[15];
    const float* bn2_g  = (const float*)d_in[16];
    const float* bn2_b  = (const float*)d_in[17];
    const float* bn2_m  = (const float*)d_in[18];
    const float* bn2_v  = (const float*)d_in[19];
    const float* ca_w1  = (const float*)d_in[20];
    const float* ca_b1  = (const float*)d_in[21];
    const float* ca_w2  = (const float*)d_in[22];
    const float* ca_b2  = (const float*)d_in[23];
    const float* po1_w  = (const float*)d_in[24];
    const float* po1_b  = (const float*)d_in[25];
    const float* po2_w  = (const float*)d_in[26];
    const float* po2_b  = (const float*)d_in[27];
    float* out = (float*)d_out;

    convert_w_kernel<<<C3*CC/256, 256>>>(qkv1_w, qkv2_w);
    msconv_kernel<<<dim3(CC, BB, 2), 256>>>(x1, x2, ms_w3, ms_b3, ms_w5, ms_b5, ms_w7, ms_b7);
    transpose_kernel<<<dim3(HWP/64, CC/64, 16), 256>>>();
    qkv_tc_kernel<<<dim3(NPT, C3/128, 16), 256>>>(
        qkv1_b, bn1_g, bn1_b, bn1_m, bn1_v,
        qkv2_b, bn2_g, bn2_b, bn2_m, bn2_v);
    finalize_kernel<<<16, 512>>>();
    attn_part_kernel<<<dim3(4, NHH*BB, 2), 256>>>();
    attn_soft_kernel<<<dim3(NHH*BB, 2), 256>>>();
    se_kernel<<<dim3(BB, 2), 256>>>(ca_w1, ca_b1, ca_w2, ca_b2);
    mproj_kernel<<<dim3(NHH, BB, 2), 256>>>(po1_w, po2_w);
    mv_tc_kernel<<<dim3(HWP/128, CC/128, 16), 256>>>(x1, x2, po1_b, po2_b, out);
}